// round 3
// baseline (speedup 1.0000x reference)
#include <cuda_runtime.h>
#include <cuda_bf16.h>
#include <math.h>
#include <math_constants.h>

// Problem constants
#define TT   2048
#define HID  2048
#define NH   16
#define NKV  8
#define DH   128
#define QKVW ((NH + 2 * NKV) * DH)   // 4096
#define EPS  1e-6f

// Scratch (allocation-free rule: __device__ globals)
__device__ float g_qkv[(size_t)TT * QKVW];      // 32 MB: [T][4096] = q(2048) | k(1024) | v(1024)
__device__ float g_attn[(size_t)TT * NH * DH];  // 16 MB: [T][2048]

// ---------------------------------------------------------------------------
// SGEMM: C[M,N] = A[M,K] @ B[K,N], all row-major, fp32.
// 128x128 block tile, BK=8, 256 threads, 8x8 per-thread register tile.
// Requires M%128==0, N%128==0, K%8==0 (holds: 2048/4096).
// ---------------------------------------------------------------------------
#define GBM 128
#define GBN 128
#define GBK 8

__global__ __launch_bounds__(256) void sgemm_kernel(
    int M, int N, int K,
    const float* __restrict__ A, const float* __restrict__ B,
    float* __restrict__ C)
{
    __shared__ float As[GBK][GBM];   // transposed A tile
    __shared__ float Bs[GBK][GBN];

    const int tid = threadIdx.x;
    const int tx  = tid & 15;        // 0..15 -> cols tx*8
    const int ty  = tid >> 4;        // 0..15 -> rows ty*8
    const int bm  = blockIdx.y * GBM;
    const int bn  = blockIdx.x * GBN;

    // A load map: 128x8 tile = 256 float4; 1 per thread
    const int aRow = tid >> 1;           // 0..127
    const int aCol = (tid & 1) << 2;     // 0 or 4
    // B load map: 8x128 tile = 256 float4
    const int bRow = tid >> 5;           // 0..7
    const int bCol = (tid & 31) << 2;    // 0..124

    float acc[8][8];
#pragma unroll
    for (int i = 0; i < 8; i++)
#pragma unroll
        for (int j = 0; j < 8; j++) acc[i][j] = 0.f;

    for (int k0 = 0; k0 < K; k0 += GBK) {
        float4 a4 = *(const float4*)(A + (size_t)(bm + aRow) * K + k0 + aCol);
        As[aCol + 0][aRow] = a4.x;
        As[aCol + 1][aRow] = a4.y;
        As[aCol + 2][aRow] = a4.z;
        As[aCol + 3][aRow] = a4.w;
        *(float4*)&Bs[bRow][bCol] =
            *(const float4*)(B + (size_t)(k0 + bRow) * N + bn + bCol);
        __syncthreads();

#pragma unroll
        for (int kk = 0; kk < GBK; kk++) {
            float ra[8], rb[8];
            *(float4*)&ra[0] = *(float4*)&As[kk][ty * 8];
            *(float4*)&ra[4] = *(float4*)&As[kk][ty * 8 + 4];
            *(float4*)&rb[0] = *(float4*)&Bs[kk][tx * 8];
            *(float4*)&rb[4] = *(float4*)&Bs[kk][tx * 8 + 4];
#pragma unroll
            for (int i = 0; i < 8; i++)
#pragma unroll
                for (int j = 0; j < 8; j++)
                    acc[i][j] += ra[i] * rb[j];
        }
        __syncthreads();
    }

#pragma unroll
    for (int i = 0; i < 8; i++)
#pragma unroll
        for (int j = 0; j < 8; j += 4) {
            float4 v = make_float4(acc[i][j], acc[i][j + 1], acc[i][j + 2], acc[i][j + 3]);
            *(float4*)(C + (size_t)(bm + ty * 8 + i) * N + bn + tx * 8 + j) = v;
        }
}

// ---------------------------------------------------------------------------
// Per-head RMSNorm + neox RoPE, in-place on q and k slices of g_qkv.
// grid = (NH+NKV, T), block = 128 threads (one per dim element).
// ---------------------------------------------------------------------------
__global__ __launch_bounds__(128) void norm_rope_kernel(
    const int* __restrict__ positions,
    const float* __restrict__ qw, const float* __restrict__ kw,
    float* __restrict__ qkv)
{
    const int t = blockIdx.y;
    const int h = blockIdx.x;    // 0..15 = q heads, 16..23 = k heads (contiguous layout)
    const int d = threadIdx.x;

    float* ptr = qkv + (size_t)t * QKVW + h * DH;
    const float* w = (h < NH) ? qw : kw;

    float x = ptr[d];
    float ss = x * x;
#pragma unroll
    for (int o = 16; o > 0; o >>= 1) ss += __shfl_xor_sync(0xffffffffu, ss, o);

    __shared__ float wsum[4];
    __shared__ float xs[DH];
    if ((d & 31) == 0) wsum[d >> 5] = ss;
    __syncthreads();
    float tot = wsum[0] + wsum[1] + wsum[2] + wsum[3];
    float xn = x * rsqrtf(tot * (1.f / DH) + EPS) * w[d];
    xs[d] = xn;
    __syncthreads();

    if (d < 64) {
        float x1 = xs[d], x2 = xs[d + 64];
        float pos = (float)positions[t];
        float inv_freq = powf(10000.f, -(float)d * (1.f / 64.f));  // accurate path
        float ang = pos * inv_freq;
        float sv, cv;
        sincosf(ang, &sv, &cv);
        ptr[d]      = x1 * cv - x2 * sv;
        ptr[d + 64] = x2 * cv + x1 * sv;
    }
}

// ---------------------------------------------------------------------------
// Flash-style causal GQA attention, fp32.
// One block per (head, q-tile of 128 rows). 256 threads.
// Streams 64-key tiles with online softmax. O accumulated in registers.
// ---------------------------------------------------------------------------
#define AT_BM 128
#define AT_BN 64

struct AttnSmem {
    float Qs[DH][AT_BM + 4];     // [d][row], Q pre-scaled
    float Ks[DH][AT_BN + 4];     // [d][key]
    float Vs[AT_BN][DH];         // [key][d]
    float Ps[AT_BN][AT_BM + 4];  // [key][row] scores -> probs
    float row_m[AT_BM];
    float row_l[AT_BM];
    float row_c[AT_BM];
};

__global__ __launch_bounds__(256, 1) void attn_kernel(
    const float* __restrict__ qkv, float* __restrict__ out)
{
    extern __shared__ float smem_raw[];
    AttnSmem& s = *(AttnSmem*)smem_raw;

    const int h   = blockIdx.x;                          // 0..15
    const int m0  = (gridDim.y - 1 - blockIdx.y) * AT_BM; // heavy diagonal blocks first
    const int kvh = h >> 1;                               // G = NH/NKV = 2
    const int tid = threadIdx.x;
    const float scale = 0.08838834764831845f;             // 1/sqrt(128)

    const float* qbase = qkv + h * DH;
    const float* kbase = qkv + NH * DH + kvh * DH;              // +2048
    const float* vbase = qkv + (NH + NKV) * DH + kvh * DH;      // +3072

    // Load Q tile (scaled), transposed to [d][row]
    for (int u = tid; u < AT_BM * 32; u += 256) {
        int row = u >> 5;
        int d   = (u & 31) << 2;
        float4 q4 = *(const float4*)(qbase + (size_t)(m0 + row) * QKVW + d);
        s.Qs[d + 0][row] = q4.x * scale;
        s.Qs[d + 1][row] = q4.y * scale;
        s.Qs[d + 2][row] = q4.z * scale;
        s.Qs[d + 3][row] = q4.w * scale;
    }
    if (tid < AT_BM) { s.row_m[tid] = -CUDART_INF_F; s.row_l[tid] = 0.f; }

    float accO[8][8];
#pragma unroll
    for (int i = 0; i < 8; i++)
#pragma unroll
        for (int j = 0; j < 8; j++) accO[i][j] = 0.f;

    const int tx = tid & 15;   // S cols tx*4 ; O cols tx*8
    const int ty = tid >> 4;   // rows ty*8
    const int n_tiles = (m0 + AT_BM) / AT_BN;  // m0/64 + 2

    for (int tile = 0; tile < n_tiles; tile++) {
        const int n0 = tile * AT_BN;
        __syncthreads();  // previous iteration consumers done (also covers Q load)

        // Load K (transposed) + V tile
        for (int u = tid; u < AT_BN * 32; u += 256) {
            int key = u >> 5;
            int d   = (u & 31) << 2;
            float4 k4 = *(const float4*)(kbase + (size_t)(n0 + key) * QKVW + d);
            s.Ks[d + 0][key] = k4.x;
            s.Ks[d + 1][key] = k4.y;
            s.Ks[d + 2][key] = k4.z;
            s.Ks[d + 3][key] = k4.w;
            *(float4*)&s.Vs[key][d] =
                *(const float4*)(vbase + (size_t)(n0 + key) * QKVW + d);
        }
        __syncthreads();

        // S = Q @ K^T  (each thread: rows ty*8..+7, cols tx*4..+3)
        float accS[8][4];
#pragma unroll
        for (int i = 0; i < 8; i++)
#pragma unroll
            for (int j = 0; j < 4; j++) accS[i][j] = 0.f;

#pragma unroll 4
        for (int kk = 0; kk < DH; kk++) {
            float ra[8], rb[4];
            *(float4*)&ra[0] = *(float4*)&s.Qs[kk][ty * 8];
            *(float4*)&ra[4] = *(float4*)&s.Qs[kk][ty * 8 + 4];
            *(float4*)&rb[0] = *(float4*)&s.Ks[kk][tx * 4];
#pragma unroll
            for (int i = 0; i < 8; i++)
#pragma unroll
                for (int j = 0; j < 4; j++)
                    accS[i][j] += ra[i] * rb[j];
        }

        // Causal mask + store transposed [key][row]
        const bool need_mask = (n0 + AT_BN - 1 > m0);
#pragma unroll
        for (int i = 0; i < 8; i++) {
            int row = ty * 8 + i;
#pragma unroll
            for (int j = 0; j < 4; j++) {
                int col = tx * 4 + j;
                float v = accS[i][j];
                if (need_mask && (n0 + col > m0 + row)) v = -CUDART_INF_F;
                s.Ps[col][row] = v;
            }
        }
        __syncthreads();

        // Online softmax per row (128 threads)
        if (tid < AT_BM) {
            const int r = tid;
            float m_old = s.row_m[r];
            float m_new = m_old;
#pragma unroll 8
            for (int j = 0; j < AT_BN; j++) m_new = fmaxf(m_new, s.Ps[j][r]);
            float corr = __expf(m_old - m_new);   // exp(-inf)=0 on first tile
            float sum = 0.f;
#pragma unroll 8
            for (int j = 0; j < AT_BN; j++) {
                float p = __expf(s.Ps[j][r] - m_new);
                s.Ps[j][r] = p;
                sum += p;
            }
            s.row_m[r] = m_new;
            s.row_l[r] = s.row_l[r] * corr + sum;
            s.row_c[r] = corr;
        }
        __syncthreads();

        // O = O * corr + P @ V   (each thread: rows ty*8..+7, cols tx*8..+7)
        float c[8];
#pragma unroll
        for (int i = 0; i < 8; i++) c[i] = s.row_c[ty * 8 + i];
#pragma unroll
        for (int i = 0; i < 8; i++)
#pragma unroll
            for (int j = 0; j < 8; j++) accO[i][j] *= c[i];

#pragma unroll 2
        for (int kk = 0; kk < AT_BN; kk++) {
            float pa[8], vb[8];
            *(float4*)&pa[0] = *(float4*)&s.Ps[kk][ty * 8];
            *(float4*)&pa[4] = *(float4*)&s.Ps[kk][ty * 8 + 4];
            *(float4*)&vb[0] = *(float4*)&s.Vs[kk][tx * 8];
            *(float4*)&vb[4] = *(float4*)&s.Vs[kk][tx * 8 + 4];
#pragma unroll
            for (int i = 0; i < 8; i++)
#pragma unroll
                for (int j = 0; j < 8; j++)
                    accO[i][j] += pa[i] * vb[j];
        }
    }

    // Normalize and write out: out[t][h*128 + d]
    float invl[8];
#pragma unroll
    for (int i = 0; i < 8; i++) invl[i] = 1.f / s.row_l[ty * 8 + i];
#pragma unroll
    for (int i = 0; i < 8; i++) {
        float4 o0 = make_float4(accO[i][0] * invl[i], accO[i][1] * invl[i],
                                accO[i][2] * invl[i], accO[i][3] * invl[i]);
        float4 o1 = make_float4(accO[i][4] * invl[i], accO[i][5] * invl[i],
                                accO[i][6] * invl[i], accO[i][7] * invl[i]);
        size_t off = (size_t)(m0 + ty * 8 + i) * (NH * DH) + h * DH + tx * 8;
        *(float4*)(out + off)     = o0;
        *(float4*)(out + off + 4) = o1;
    }
}

// ---------------------------------------------------------------------------
// Launch
// ---------------------------------------------------------------------------
extern "C" void kernel_launch(void* const* d_in, const int* in_sizes, int n_in,
                              void* d_out, int out_size)
{
    const int*   positions = (const int*)d_in[0];
    const float* hidden    = (const float*)d_in[1];
    const float* w_qkv     = (const float*)d_in[2];
    const float* w_o       = (const float*)d_in[3];
    const float* q_norm_w  = (const float*)d_in[4];
    const float* k_norm_w  = (const float*)d_in[5];
    float*       out       = (float*)d_out;

    float* qkv_ptr = nullptr;
    float* attn_ptr = nullptr;
    cudaGetSymbolAddress((void**)&qkv_ptr, g_qkv);
    cudaGetSymbolAddress((void**)&attn_ptr, g_attn);

    // 1. QKV projection: [T,HID] @ [HID,4096]
    {
        dim3 grid(QKVW / GBN, TT / GBM);
        sgemm_kernel<<<grid, 256>>>(TT, QKVW, HID, hidden, w_qkv, qkv_ptr);
    }

    // 2. RMSNorm + RoPE on q,k (in-place)
    {
        dim3 grid(NH + NKV, TT);
        norm_rope_kernel<<<grid, 128>>>(positions, q_norm_w, k_norm_w, qkv_ptr);
    }

    // 3. Causal GQA flash attention
    {
        static_assert(sizeof(AttnSmem) <= 224 * 1024, "smem");
        cudaFuncSetAttribute(attn_kernel,
                             cudaFuncAttributeMaxDynamicSharedMemorySize,
                             (int)sizeof(AttnSmem));
        dim3 grid(NH, TT / AT_BM);
        attn_kernel<<<grid, 256, sizeof(AttnSmem)>>>(qkv_ptr, attn_ptr);
    }

    // 4. Output projection: [T,2048] @ [2048,HID]
    {
        dim3 grid(HID / GBN, TT / GBM);
        sgemm_kernel<<<grid, 256>>>(TT, HID, NH * DH, attn_ptr, w_o, out);
    }
}

// round 5
// speedup vs baseline: 1.9805x; 1.9805x over previous
#include <cuda_runtime.h>
#include <cuda_bf16.h>
#include <math.h>
#include <math_constants.h>
#include <stdint.h>

// Problem constants
#define TT   2048
#define HID  2048
#define NH   16
#define NKV  8
#define DH   128
#define QKVW ((NH + 2 * NKV) * DH)   // 4096
#define EPS  1e-6f

// Scratch (allocation-free rule: __device__ globals)
__device__ float g_qkv[(size_t)TT * QKVW];          // fp32 qkv
__device__ float g_attn[(size_t)TT * NH * DH];      // fp32 attn out
__device__ __nv_bfloat16 g_ah[(size_t)TT * HID];    // A hi (split bf16)
__device__ __nv_bfloat16 g_al[(size_t)TT * HID];    // A lo
__device__ __nv_bfloat16 g_bh[(size_t)QKVW * HID];  // B^T hi ([N,K])
__device__ __nv_bfloat16 g_bl[(size_t)QKVW * HID];  // B^T lo

// ---------------------------------------------------------------------------
// Warp-level bf16 MMA (sm_80+ HMMA path; NOT tcgen05 — base sm_103 target)
// D(16x8,f32) += A(16x16,bf16,row) * B(16x8,bf16,col)
// ---------------------------------------------------------------------------
__device__ __forceinline__ void mma16816(float d[4],
                                         uint32_t a0, uint32_t a1, uint32_t a2, uint32_t a3,
                                         uint32_t b0, uint32_t b1)
{
    asm volatile(
        "mma.sync.aligned.m16n8k16.row.col.f32.bf16.bf16.f32 "
        "{%0,%1,%2,%3}, {%4,%5,%6,%7}, {%8,%9}, {%0,%1,%2,%3};\n"
        : "+f"(d[0]), "+f"(d[1]), "+f"(d[2]), "+f"(d[3])
        : "r"(a0), "r"(a1), "r"(a2), "r"(a3), "r"(b0), "r"(b1));
}

__device__ __forceinline__ void ldsm_x4_t(uint32_t& r0, uint32_t& r1,
                                          uint32_t& r2, uint32_t& r3, uint32_t addr)
{
    asm volatile("ldmatrix.sync.aligned.m8n8.x4.trans.shared.b16 {%0,%1,%2,%3}, [%4];"
                 : "=r"(r0), "=r"(r1), "=r"(r2), "=r"(r3) : "r"(addr));
}

__device__ __forceinline__ uint32_t su32(const void* p) {
    return (uint32_t)__cvta_generic_to_shared(p);
}

// ---------------------------------------------------------------------------
// Split conversion: fp32 -> (hi, lo) bf16, same layout. n % 4 == 0.
// ---------------------------------------------------------------------------
__global__ __launch_bounds__(256) void split_kernel(
    const float* __restrict__ x,
    __nv_bfloat16* __restrict__ hi, __nv_bfloat16* __restrict__ lo, int n)
{
    int i = (blockIdx.x * blockDim.x + threadIdx.x) * 4;
    if (i >= n) return;
    float4 v = *(const float4*)(x + i);
    __nv_bfloat16 h0 = __float2bfloat16(v.x);
    __nv_bfloat16 h1 = __float2bfloat16(v.y);
    __nv_bfloat16 h2 = __float2bfloat16(v.z);
    __nv_bfloat16 h3 = __float2bfloat16(v.w);
    __nv_bfloat16 l0 = __float2bfloat16(v.x - __bfloat162float(h0));
    __nv_bfloat16 l1 = __float2bfloat16(v.y - __bfloat162float(h1));
    __nv_bfloat16 l2 = __float2bfloat16(v.z - __bfloat162float(h2));
    __nv_bfloat16 l3 = __float2bfloat16(v.w - __bfloat162float(h3));
    __nv_bfloat162 hA; hA.x = h0; hA.y = h1;
    __nv_bfloat162 hB; hB.x = h2; hB.y = h3;
    __nv_bfloat162 lA; lA.x = l0; lA.y = l1;
    __nv_bfloat162 lB; lB.x = l2; lB.y = l3;
    *(__nv_bfloat162*)(hi + i)     = hA;
    *(__nv_bfloat162*)(hi + i + 2) = hB;
    *(__nv_bfloat162*)(lo + i)     = lA;
    *(__nv_bfloat162*)(lo + i + 2) = lB;
}

// ---------------------------------------------------------------------------
// Transpose + split: W[K,N] fp32 -> Th/Tl [N,K] bf16. K,N % 32 == 0.
// ---------------------------------------------------------------------------
__global__ __launch_bounds__(256) void transpose_split_kernel(
    const float* __restrict__ W,
    __nv_bfloat16* __restrict__ Th, __nv_bfloat16* __restrict__ Tl,
    int K, int N)
{
    __shared__ float tile[32][33];
    const int bn = blockIdx.x * 32;
    const int bk = blockIdx.y * 32;
    const int tx = threadIdx.x;
    const int ty = threadIdx.y;
#pragma unroll
    for (int j = 0; j < 32; j += 8)
        tile[ty + j][tx] = W[(size_t)(bk + ty + j) * N + bn + tx];
    __syncthreads();
#pragma unroll
    for (int j = 0; j < 32; j += 8) {
        float v = tile[tx][ty + j];
        __nv_bfloat16 h = __float2bfloat16(v);
        __nv_bfloat16 l = __float2bfloat16(v - __bfloat162float(h));
        size_t o = (size_t)(bn + ty + j) * K + bk + tx;
        Th[o] = h;
        Tl[o] = l;
    }
}

// ---------------------------------------------------------------------------
// mma.sync bf16x3 GEMM: C[M,N] = A[M,K] @ B[K,N].
// A [M,K] hi/lo row-major; B passed transposed [N,K] hi/lo.
// CTA 128x128, 256 threads (8 warps, 2x4), warp tile 64x32, BK=32.
// ---------------------------------------------------------------------------
#define GPITCH 40   // smem row pitch in bf16 (32 + 8 pad -> 80B, conflict-free frags)

__global__ __launch_bounds__(256) void gemm_mma_kernel(
    int M, int N, int K,
    const __nv_bfloat16* __restrict__ Ah, const __nv_bfloat16* __restrict__ Al,
    const __nv_bfloat16* __restrict__ Bh, const __nv_bfloat16* __restrict__ Bl,
    float* __restrict__ C)
{
    __shared__ __nv_bfloat16 sAh[128 * GPITCH], sAl[128 * GPITCH];
    __shared__ __nv_bfloat16 sBh[128 * GPITCH], sBl[128 * GPITCH];

    const int tid  = threadIdx.x;
    const int lane = tid & 31;
    const int wid  = tid >> 5;
    const int wm   = wid >> 2;      // 0..1 -> rows wm*64
    const int wn   = wid & 3;       // 0..3 -> cols wn*32
    const int gq   = lane >> 2;     // groupID
    const int tg   = lane & 3;      // thread-in-group
    const int bm = blockIdx.y * 128;
    const int bn = blockIdx.x * 128;

    // global load map: idx 0..511 per array: row = idx>>2, quad = idx&3 (8 bf16 = 16B)
    const int r0g = tid >> 2, q0 = tid & 3;
    const int r1g = (tid + 256) >> 2, q1 = (tid + 256) & 3;

    float acc[4][4][4];
#pragma unroll
    for (int a = 0; a < 4; a++)
#pragma unroll
        for (int b = 0; b < 4; b++)
#pragma unroll
            for (int c = 0; c < 4; c++) acc[a][b][c] = 0.f;

    const int nch = K / 32;
    uint4 pA0, pA1, pAl0, pAl1, pB0, pB1, pBl0, pBl1;

    // prefetch chunk 0
    {
        const int k0 = 0;
        pA0  = *(const uint4*)(Ah + (size_t)(bm + r0g) * K + k0 + q0 * 8);
        pA1  = *(const uint4*)(Ah + (size_t)(bm + r1g) * K + k0 + q1 * 8);
        pAl0 = *(const uint4*)(Al + (size_t)(bm + r0g) * K + k0 + q0 * 8);
        pAl1 = *(const uint4*)(Al + (size_t)(bm + r1g) * K + k0 + q1 * 8);
        pB0  = *(const uint4*)(Bh + (size_t)(bn + r0g) * K + k0 + q0 * 8);
        pB1  = *(const uint4*)(Bh + (size_t)(bn + r1g) * K + k0 + q1 * 8);
        pBl0 = *(const uint4*)(Bl + (size_t)(bn + r0g) * K + k0 + q0 * 8);
        pBl1 = *(const uint4*)(Bl + (size_t)(bn + r1g) * K + k0 + q1 * 8);
    }

    for (int c = 0; c < nch; c++) {
        __syncthreads();
        *(uint4*)&sAh[r0g * GPITCH + q0 * 8] = pA0;
        *(uint4*)&sAh[r1g * GPITCH + q1 * 8] = pA1;
        *(uint4*)&sAl[r0g * GPITCH + q0 * 8] = pAl0;
        *(uint4*)&sAl[r1g * GPITCH + q1 * 8] = pAl1;
        *(uint4*)&sBh[r0g * GPITCH + q0 * 8] = pB0;
        *(uint4*)&sBh[r1g * GPITCH + q1 * 8] = pB1;
        *(uint4*)&sBl[r0g * GPITCH + q0 * 8] = pBl0;
        *(uint4*)&sBl[r1g * GPITCH + q1 * 8] = pBl1;
        __syncthreads();

        if (c + 1 < nch) {
            const int k0 = (c + 1) * 32;
            pA0  = *(const uint4*)(Ah + (size_t)(bm + r0g) * K + k0 + q0 * 8);
            pA1  = *(const uint4*)(Ah + (size_t)(bm + r1g) * K + k0 + q1 * 8);
            pAl0 = *(const uint4*)(Al + (size_t)(bm + r0g) * K + k0 + q0 * 8);
            pAl1 = *(const uint4*)(Al + (size_t)(bm + r1g) * K + k0 + q1 * 8);
            pB0  = *(const uint4*)(Bh + (size_t)(bn + r0g) * K + k0 + q0 * 8);
            pB1  = *(const uint4*)(Bh + (size_t)(bn + r1g) * K + k0 + q1 * 8);
            pBl0 = *(const uint4*)(Bl + (size_t)(bn + r0g) * K + k0 + q0 * 8);
            pBl1 = *(const uint4*)(Bl + (size_t)(bn + r1g) * K + k0 + q1 * 8);
        }

#pragma unroll
        for (int ks = 0; ks < 2; ks++) {
            const int kk = ks * 16;
            uint32_t ah[4][4], al[4][4], bh[4][2], bl[4][2];
#pragma unroll
            for (int mt = 0; mt < 4; mt++) {
                int row = wm * 64 + mt * 16 + gq;
                ah[mt][0] = *(const uint32_t*)&sAh[row * GPITCH + kk + 2 * tg];
                ah[mt][1] = *(const uint32_t*)&sAh[(row + 8) * GPITCH + kk + 2 * tg];
                ah[mt][2] = *(const uint32_t*)&sAh[row * GPITCH + kk + 2 * tg + 8];
                ah[mt][3] = *(const uint32_t*)&sAh[(row + 8) * GPITCH + kk + 2 * tg + 8];
                al[mt][0] = *(const uint32_t*)&sAl[row * GPITCH + kk + 2 * tg];
                al[mt][1] = *(const uint32_t*)&sAl[(row + 8) * GPITCH + kk + 2 * tg];
                al[mt][2] = *(const uint32_t*)&sAl[row * GPITCH + kk + 2 * tg + 8];
                al[mt][3] = *(const uint32_t*)&sAl[(row + 8) * GPITCH + kk + 2 * tg + 8];
            }
#pragma unroll
            for (int nt = 0; nt < 4; nt++) {
                int n = wn * 32 + nt * 8 + gq;
                bh[nt][0] = *(const uint32_t*)&sBh[n * GPITCH + kk + 2 * tg];
                bh[nt][1] = *(const uint32_t*)&sBh[n * GPITCH + kk + 2 * tg + 8];
                bl[nt][0] = *(const uint32_t*)&sBl[n * GPITCH + kk + 2 * tg];
                bl[nt][1] = *(const uint32_t*)&sBl[n * GPITCH + kk + 2 * tg + 8];
            }
#pragma unroll
            for (int mt = 0; mt < 4; mt++)
#pragma unroll
                for (int nt = 0; nt < 4; nt++) {
                    mma16816(acc[mt][nt], ah[mt][0], ah[mt][1], ah[mt][2], ah[mt][3],
                             bh[nt][0], bh[nt][1]);
                    mma16816(acc[mt][nt], ah[mt][0], ah[mt][1], ah[mt][2], ah[mt][3],
                             bl[nt][0], bl[nt][1]);
                    mma16816(acc[mt][nt], al[mt][0], al[mt][1], al[mt][2], al[mt][3],
                             bh[nt][0], bh[nt][1]);
                }
        }
    }

    // epilogue
#pragma unroll
    for (int mt = 0; mt < 4; mt++) {
        int row = bm + wm * 64 + mt * 16 + gq;
#pragma unroll
        for (int nt = 0; nt < 4; nt++) {
            int col = bn + wn * 32 + nt * 8 + 2 * tg;
            *(float2*)(C + (size_t)row * N + col) =
                make_float2(acc[mt][nt][0], acc[mt][nt][1]);
            *(float2*)(C + (size_t)(row + 8) * N + col) =
                make_float2(acc[mt][nt][2], acc[mt][nt][3]);
        }
    }
}

// ---------------------------------------------------------------------------
// Per-head RMSNorm + neox RoPE, in-place on q and k slices of g_qkv.
// ---------------------------------------------------------------------------
__global__ __launch_bounds__(128) void norm_rope_kernel(
    const int* __restrict__ positions,
    const float* __restrict__ qw, const float* __restrict__ kw,
    float* __restrict__ qkv)
{
    const int t = blockIdx.y;
    const int h = blockIdx.x;
    const int d = threadIdx.x;

    float* ptr = qkv + (size_t)t * QKVW + h * DH;
    const float* w = (h < NH) ? qw : kw;

    float x = ptr[d];
    float ss = x * x;
#pragma unroll
    for (int o = 16; o > 0; o >>= 1) ss += __shfl_xor_sync(0xffffffffu, ss, o);

    __shared__ float wsum[4];
    __shared__ float xs[DH];
    if ((d & 31) == 0) wsum[d >> 5] = ss;
    __syncthreads();
    float tot = wsum[0] + wsum[1] + wsum[2] + wsum[3];
    float xn = x * rsqrtf(tot * (1.f / DH) + EPS) * w[d];
    xs[d] = xn;
    __syncthreads();

    if (d < 64) {
        float x1 = xs[d], x2 = xs[d + 64];
        float pos = (float)positions[t];
        float inv_freq = powf(10000.f, -(float)d * (1.f / 64.f));
        float ang = pos * inv_freq;
        float sv, cv;
        sincosf(ang, &sv, &cv);
        ptr[d]      = x1 * cv - x2 * sv;
        ptr[d + 64] = x2 * cv + x1 * sv;
    }
}

// ---------------------------------------------------------------------------
// Flash-style causal GQA attention with bf16x3 mma.sync.
// Block: 256 threads (8 warps). Q-tile 128 rows, key-tile 64.
// QK warp grid 4x2 (warp tile 32x32); PV warp grid 4x2 (warp tile 32x64).
// ---------------------------------------------------------------------------
#define AT_BM 128
#define AT_BN 64
#define QP 136      // Q/K/V smem pitch (bf16): 272B rows, conflict-free
#define PP 72       // P smem pitch (bf16): 144B rows
#define SPP 132     // score smem pitch (fp32)

struct AttnSmem {
    __nv_bfloat16 Qh[AT_BM * QP], Ql[AT_BM * QP];
    __nv_bfloat16 Kh[AT_BN * QP], Kl[AT_BN * QP];
    __nv_bfloat16 Vh[AT_BN * QP], Vl[AT_BN * QP];
    __nv_bfloat16 Ph[AT_BM * PP], Pl[AT_BM * PP];
    float Ps[AT_BN * SPP];
    float row_m[AT_BM], row_l[AT_BM], row_c[AT_BM];
};

__global__ __launch_bounds__(256, 1) void attn_kernel(
    const float* __restrict__ qkv, float* __restrict__ out)
{
    extern __shared__ char smem_raw[];
    AttnSmem& s = *(AttnSmem*)smem_raw;

    const int h   = blockIdx.x;
    const int m0  = (gridDim.y - 1 - blockIdx.y) * AT_BM;  // heavy blocks first
    const int kvh = h >> 1;
    const int tid = threadIdx.x;
    const int lane = tid & 31;
    const int wid  = tid >> 5;
    const int wm   = wid >> 1;    // 0..3 -> rows wm*32
    const int wn   = wid & 1;     // 0..1
    const int gq   = lane >> 2;
    const int tg   = lane & 3;
    const float scale = 0.08838834764831845f;

    const float* qbase = qkv + h * DH;
    const float* kbase = qkv + NH * DH + kvh * DH;
    const float* vbase = qkv + (NH + NKV) * DH + kvh * DH;

    // Load + scale + split Q tile: [row][d], row-major
    for (int u = tid; u < AT_BM * 32; u += 256) {
        int row = u >> 5;
        int d   = (u & 31) << 2;
        float4 q4 = *(const float4*)(qbase + (size_t)(m0 + row) * QKVW + d);
        float q0 = q4.x * scale, q1 = q4.y * scale, q2 = q4.z * scale, q3 = q4.w * scale;
        __nv_bfloat16 h0 = __float2bfloat16(q0), h1 = __float2bfloat16(q1);
        __nv_bfloat16 h2 = __float2bfloat16(q2), h3 = __float2bfloat16(q3);
        s.Qh[row * QP + d + 0] = h0; s.Qh[row * QP + d + 1] = h1;
        s.Qh[row * QP + d + 2] = h2; s.Qh[row * QP + d + 3] = h3;
        s.Ql[row * QP + d + 0] = __float2bfloat16(q0 - __bfloat162float(h0));
        s.Ql[row * QP + d + 1] = __float2bfloat16(q1 - __bfloat162float(h1));
        s.Ql[row * QP + d + 2] = __float2bfloat16(q2 - __bfloat162float(h2));
        s.Ql[row * QP + d + 3] = __float2bfloat16(q3 - __bfloat162float(h3));
    }
    if (tid < AT_BM) { s.row_m[tid] = -CUDART_INF_F; s.row_l[tid] = 0.f; }

    float accO[2][8][4];
#pragma unroll
    for (int a = 0; a < 2; a++)
#pragma unroll
        for (int b = 0; b < 8; b++)
#pragma unroll
            for (int c = 0; c < 4; c++) accO[a][b][c] = 0.f;

    // ldmatrix lane-constant offset (bytes) into V tiles
    const uint32_t vlane_off = (uint32_t)((lane & 15) * (QP * 2) + ((lane >> 4) << 4));
    const uint32_t svh = su32(s.Vh);
    const uint32_t svl = su32(s.Vl);

    const int n_tiles = (m0 + AT_BM) / AT_BN;

    for (int tile = 0; tile < n_tiles; tile++) {
        const int n0 = tile * AT_BN;
        __syncthreads();  // prev PV done; Q visible on first iter

        // Load + split K and V tiles ([key][d] row-major)
        for (int u = tid; u < AT_BN * 32; u += 256) {
            int key = u >> 5;
            int d   = (u & 31) << 2;
            float4 k4 = *(const float4*)(kbase + (size_t)(n0 + key) * QKVW + d);
            float4 v4 = *(const float4*)(vbase + (size_t)(n0 + key) * QKVW + d);
            __nv_bfloat16 kh0 = __float2bfloat16(k4.x), kh1 = __float2bfloat16(k4.y);
            __nv_bfloat16 kh2 = __float2bfloat16(k4.z), kh3 = __float2bfloat16(k4.w);
            s.Kh[key * QP + d + 0] = kh0; s.Kh[key * QP + d + 1] = kh1;
            s.Kh[key * QP + d + 2] = kh2; s.Kh[key * QP + d + 3] = kh3;
            s.Kl[key * QP + d + 0] = __float2bfloat16(k4.x - __bfloat162float(kh0));
            s.Kl[key * QP + d + 1] = __float2bfloat16(k4.y - __bfloat162float(kh1));
            s.Kl[key * QP + d + 2] = __float2bfloat16(k4.z - __bfloat162float(kh2));
            s.Kl[key * QP + d + 3] = __float2bfloat16(k4.w - __bfloat162float(kh3));
            __nv_bfloat16 vh0 = __float2bfloat16(v4.x), vh1 = __float2bfloat16(v4.y);
            __nv_bfloat16 vh2 = __float2bfloat16(v4.z), vh3 = __float2bfloat16(v4.w);
            s.Vh[key * QP + d + 0] = vh0; s.Vh[key * QP + d + 1] = vh1;
            s.Vh[key * QP + d + 2] = vh2; s.Vh[key * QP + d + 3] = vh3;
            s.Vl[key * QP + d + 0] = __float2bfloat16(v4.x - __bfloat162float(vh0));
            s.Vl[key * QP + d + 1] = __float2bfloat16(v4.y - __bfloat162float(vh1));
            s.Vl[key * QP + d + 2] = __float2bfloat16(v4.z - __bfloat162float(vh2));
            s.Vl[key * QP + d + 3] = __float2bfloat16(v4.w - __bfloat162float(vh3));
        }
        __syncthreads();

        // ---- S = Q @ K^T (bf16x3) : warp tile 32x32 ----
        float accS[2][4][4];
#pragma unroll
        for (int a = 0; a < 2; a++)
#pragma unroll
            for (int b = 0; b < 4; b++)
#pragma unroll
                for (int c = 0; c < 4; c++) accS[a][b][c] = 0.f;

#pragma unroll
        for (int ks = 0; ks < 8; ks++) {
            const int kk = ks * 16;
            uint32_t ah[2][4], al[2][4], bh[4][2], bl[4][2];
#pragma unroll
            for (int mt = 0; mt < 2; mt++) {
                int row = wm * 32 + mt * 16 + gq;
                ah[mt][0] = *(const uint32_t*)&s.Qh[row * QP + kk + 2 * tg];
                ah[mt][1] = *(const uint32_t*)&s.Qh[(row + 8) * QP + kk + 2 * tg];
                ah[mt][2] = *(const uint32_t*)&s.Qh[row * QP + kk + 2 * tg + 8];
                ah[mt][3] = *(const uint32_t*)&s.Qh[(row + 8) * QP + kk + 2 * tg + 8];
                al[mt][0] = *(const uint32_t*)&s.Ql[row * QP + kk + 2 * tg];
                al[mt][1] = *(const uint32_t*)&s.Ql[(row + 8) * QP + kk + 2 * tg];
                al[mt][2] = *(const uint32_t*)&s.Ql[row * QP + kk + 2 * tg + 8];
                al[mt][3] = *(const uint32_t*)&s.Ql[(row + 8) * QP + kk + 2 * tg + 8];
            }
#pragma unroll
            for (int nt = 0; nt < 4; nt++) {
                int n = wn * 32 + nt * 8 + gq;
                bh[nt][0] = *(const uint32_t*)&s.Kh[n * QP + kk + 2 * tg];
                bh[nt][1] = *(const uint32_t*)&s.Kh[n * QP + kk + 2 * tg + 8];
                bl[nt][0] = *(const uint32_t*)&s.Kl[n * QP + kk + 2 * tg];
                bl[nt][1] = *(const uint32_t*)&s.Kl[n * QP + kk + 2 * tg + 8];
            }
#pragma unroll
            for (int mt = 0; mt < 2; mt++)
#pragma unroll
                for (int nt = 0; nt < 4; nt++) {
                    mma16816(accS[mt][nt], ah[mt][0], ah[mt][1], ah[mt][2], ah[mt][3],
                             bh[nt][0], bh[nt][1]);
                    mma16816(accS[mt][nt], ah[mt][0], ah[mt][1], ah[mt][2], ah[mt][3],
                             bl[nt][0], bl[nt][1]);
                    mma16816(accS[mt][nt], al[mt][0], al[mt][1], al[mt][2], al[mt][3],
                             bh[nt][0], bh[nt][1]);
                }
        }

        // mask + store transposed Ps[key][row]
        const bool need_mask = (n0 + AT_BN - 1 > m0);
#pragma unroll
        for (int mt = 0; mt < 2; mt++) {
            int r = wm * 32 + mt * 16 + gq;
#pragma unroll
            for (int nt = 0; nt < 4; nt++) {
                int c = wn * 32 + nt * 8 + 2 * tg;
                float v0 = accS[mt][nt][0], v1 = accS[mt][nt][1];
                float v2 = accS[mt][nt][2], v3 = accS[mt][nt][3];
                if (need_mask) {
                    if (n0 + c     > m0 + r)     v0 = -CUDART_INF_F;
                    if (n0 + c + 1 > m0 + r)     v1 = -CUDART_INF_F;
                    if (n0 + c     > m0 + r + 8) v2 = -CUDART_INF_F;
                    if (n0 + c + 1 > m0 + r + 8) v3 = -CUDART_INF_F;
                }
                s.Ps[c * SPP + r]           = v0;
                s.Ps[(c + 1) * SPP + r]     = v1;
                s.Ps[c * SPP + r + 8]       = v2;
                s.Ps[(c + 1) * SPP + r + 8] = v3;
            }
        }
        __syncthreads();

        // ---- online softmax per row; write P hi/lo ----
        if (tid < AT_BM) {
            const int r = tid;
            float m_old = s.row_m[r];
            float m_new = m_old;
#pragma unroll 8
            for (int j = 0; j < AT_BN; j++) m_new = fmaxf(m_new, s.Ps[j * SPP + r]);
            float corr = __expf(m_old - m_new);
            float sum = 0.f;
#pragma unroll 8
            for (int j = 0; j < AT_BN; j++) {
                float p = __expf(s.Ps[j * SPP + r] - m_new);
                __nv_bfloat16 ph = __float2bfloat16(p);
                s.Ph[r * PP + j] = ph;
                s.Pl[r * PP + j] = __float2bfloat16(p - __bfloat162float(ph));
                sum += p;
            }
            s.row_m[r] = m_new;
            s.row_l[r] = s.row_l[r] * corr + sum;
            s.row_c[r] = corr;
        }
        __syncthreads();

        // ---- rescale accO; O += P @ V (bf16x3) : warp tile 32x64 ----
        {
            float c0 = s.row_c[wm * 32 + gq];
            float c1 = s.row_c[wm * 32 + gq + 8];
            float c2 = s.row_c[wm * 32 + 16 + gq];
            float c3 = s.row_c[wm * 32 + 16 + gq + 8];
#pragma unroll
            for (int nt = 0; nt < 8; nt++) {
                accO[0][nt][0] *= c0; accO[0][nt][1] *= c0;
                accO[0][nt][2] *= c1; accO[0][nt][3] *= c1;
                accO[1][nt][0] *= c2; accO[1][nt][1] *= c2;
                accO[1][nt][2] *= c3; accO[1][nt][3] *= c3;
            }
        }

#pragma unroll
        for (int ks = 0; ks < 4; ks++) {
            const int kk = ks * 16;
            uint32_t ph[2][4], pl[2][4];
#pragma unroll
            for (int mt = 0; mt < 2; mt++) {
                int row = wm * 32 + mt * 16 + gq;
                ph[mt][0] = *(const uint32_t*)&s.Ph[row * PP + kk + 2 * tg];
                ph[mt][1] = *(const uint32_t*)&s.Ph[(row + 8) * PP + kk + 2 * tg];
                ph[mt][2] = *(const uint32_t*)&s.Ph[row * PP + kk + 2 * tg + 8];
                ph[mt][3] = *(const uint32_t*)&s.Ph[(row + 8) * PP + kk + 2 * tg + 8];
                pl[mt][0] = *(const uint32_t*)&s.Pl[row * PP + kk + 2 * tg];
                pl[mt][1] = *(const uint32_t*)&s.Pl[(row + 8) * PP + kk + 2 * tg];
                pl[mt][2] = *(const uint32_t*)&s.Pl[row * PP + kk + 2 * tg + 8];
                pl[mt][3] = *(const uint32_t*)&s.Pl[(row + 8) * PP + kk + 2 * tg + 8];
            }
            uint32_t bvh[8][2], bvl[8][2];
#pragma unroll
            for (int vb = 0; vb < 4; vb++) {
                int ncol = wn * 64 + vb * 16;
                uint32_t base_off = (uint32_t)(kk * (QP * 2) + ncol * 2) + vlane_off;
                uint32_t r0, r1, r2, r3;
                ldsm_x4_t(r0, r1, r2, r3, svh + base_off);
                bvh[vb * 2][0] = r0; bvh[vb * 2][1] = r1;
                bvh[vb * 2 + 1][0] = r2; bvh[vb * 2 + 1][1] = r3;
                ldsm_x4_t(r0, r1, r2, r3, svl + base_off);
                bvl[vb * 2][0] = r0; bvl[vb * 2][1] = r1;
                bvl[vb * 2 + 1][0] = r2; bvl[vb * 2 + 1][1] = r3;
            }
#pragma unroll
            for (int mt = 0; mt < 2; mt++)
#pragma unroll
                for (int nt = 0; nt < 8; nt++) {
                    mma16816(accO[mt][nt], ph[mt][0], ph[mt][1], ph[mt][2], ph[mt][3],
                             bvh[nt][0], bvh[nt][1]);
                    mma16816(accO[mt][nt], ph[mt][0], ph[mt][1], ph[mt][2], ph[mt][3],
                             bvl[nt][0], bvl[nt][1]);
                    mma16816(accO[mt][nt], pl[mt][0], pl[mt][1], pl[mt][2], pl[mt][3],
                             bvh[nt][0], bvh[nt][1]);
                }
        }
    }

    // normalize + write out[t][h*128 + d]
    float i0 = 1.f / s.row_l[wm * 32 + gq];
    float i1 = 1.f / s.row_l[wm * 32 + gq + 8];
    float i2 = 1.f / s.row_l[wm * 32 + 16 + gq];
    float i3 = 1.f / s.row_l[wm * 32 + 16 + gq + 8];
#pragma unroll
    for (int mt = 0; mt < 2; mt++) {
        int row = m0 + wm * 32 + mt * 16 + gq;
        float ia = mt ? i2 : i0;
        float ib = mt ? i3 : i1;
#pragma unroll
        for (int nt = 0; nt < 8; nt++) {
            int col = h * DH + wn * 64 + nt * 8 + 2 * tg;
            *(float2*)(out + (size_t)row * (NH * DH) + col) =
                make_float2(accO[mt][nt][0] * ia, accO[mt][nt][1] * ia);
            *(float2*)(out + (size_t)(row + 8) * (NH * DH) + col) =
                make_float2(accO[mt][nt][2] * ib, accO[mt][nt][3] * ib);
        }
    }
}

// ---------------------------------------------------------------------------
// Launch
// ---------------------------------------------------------------------------
extern "C" void kernel_launch(void* const* d_in, const int* in_sizes, int n_in,
                              void* d_out, int out_size)
{
    const int*   positions = (const int*)d_in[0];
    const float* hidden    = (const float*)d_in[1];
    const float* w_qkv     = (const float*)d_in[2];
    const float* w_o       = (const float*)d_in[3];
    const float* q_norm_w  = (const float*)d_in[4];
    const float* k_norm_w  = (const float*)d_in[5];
    float*       out       = (float*)d_out;

    float* qkv_ptr = nullptr;
    float* attn_ptr = nullptr;
    __nv_bfloat16 *ah, *al, *bh, *bl;
    cudaGetSymbolAddress((void**)&qkv_ptr, g_qkv);
    cudaGetSymbolAddress((void**)&attn_ptr, g_attn);
    cudaGetSymbolAddress((void**)&ah, g_ah);
    cudaGetSymbolAddress((void**)&al, g_al);
    cudaGetSymbolAddress((void**)&bh, g_bh);
    cudaGetSymbolAddress((void**)&bl, g_bl);

    // 1. Split hidden; transpose+split w_qkv.
    {
        int n = TT * HID;
        split_kernel<<<n / 4 / 256, 256>>>(hidden, ah, al, n);
        dim3 tg(QKVW / 32, HID / 32);
        transpose_split_kernel<<<tg, dim3(32, 8)>>>(w_qkv, bh, bl, HID, QKVW);
    }

    // 2. QKV projection via mma.sync bf16x3.
    {
        dim3 grid(QKVW / 128, TT / 128);
        gemm_mma_kernel<<<grid, 256>>>(TT, QKVW, HID, ah, al, bh, bl, qkv_ptr);
    }

    // 3. RMSNorm + RoPE on q,k (in-place, fp32)
    {
        dim3 grid(NH + NKV, TT);
        norm_rope_kernel<<<grid, 128>>>(positions, q_norm_w, k_norm_w, qkv_ptr);
    }

    // 4. Causal GQA flash attention (bf16x3 mma)
    {
        static_assert(sizeof(AttnSmem) <= 227 * 1024, "smem");
        cudaFuncSetAttribute(attn_kernel,
                             cudaFuncAttributeMaxDynamicSharedMemorySize,
                             (int)sizeof(AttnSmem));
        dim3 grid(NH, TT / AT_BM);
        attn_kernel<<<grid, 256, sizeof(AttnSmem)>>>(qkv_ptr, attn_ptr);
    }

    // 5. Split attention output; transpose+split w_o.
    {
        int n = TT * NH * DH;
        split_kernel<<<n / 4 / 256, 256>>>(attn_ptr, ah, al, n);
        dim3 tg(HID / 32, (NH * DH) / 32);
        transpose_split_kernel<<<tg, dim3(32, 8)>>>(w_o, bh, bl, NH * DH, HID);
    }

    // 6. Output projection via mma.sync bf16x3.
    {
        dim3 grid(HID / 128, TT / 128);
        gemm_mma_kernel<<<grid, 256>>>(TT, HID, NH * DH, ah, al, bh, bl, out);
    }
}

// round 6
// speedup vs baseline: 2.3125x; 1.1676x over previous
#include <cuda_runtime.h>
#include <cuda_bf16.h>
#include <math.h>
#include <math_constants.h>
#include <stdint.h>

// Problem constants
#define TT   2048
#define HID  2048
#define NH   16
#define NKV  8
#define DH   128
#define QKVW ((NH + 2 * NKV) * DH)   // 4096
#define EPS  1e-6f

// Scratch (allocation-free rule: __device__ globals)
__device__ float g_qkv[(size_t)TT * QKVW];          // fp32 qkv
__device__ __nv_bfloat16 g_ah[(size_t)TT * HID];    // A hi (split bf16)
__device__ __nv_bfloat16 g_al[(size_t)TT * HID];    // A lo
__device__ __nv_bfloat16 g_bh[(size_t)QKVW * HID];  // B^T hi ([N,K])
__device__ __nv_bfloat16 g_bl[(size_t)QKVW * HID];  // B^T lo

// ---------------------------------------------------------------------------
// Warp-level bf16 MMA (sm_80+ HMMA path; base sm_103 target)
// ---------------------------------------------------------------------------
__device__ __forceinline__ void mma16816(float d[4],
                                         uint32_t a0, uint32_t a1, uint32_t a2, uint32_t a3,
                                         uint32_t b0, uint32_t b1)
{
    asm volatile(
        "mma.sync.aligned.m16n8k16.row.col.f32.bf16.bf16.f32 "
        "{%0,%1,%2,%3}, {%4,%5,%6,%7}, {%8,%9}, {%0,%1,%2,%3};\n"
        : "+f"(d[0]), "+f"(d[1]), "+f"(d[2]), "+f"(d[3])
        : "r"(a0), "r"(a1), "r"(a2), "r"(a3), "r"(b0), "r"(b1));
}

__device__ __forceinline__ void ldsm_x4_t(uint32_t& r0, uint32_t& r1,
                                          uint32_t& r2, uint32_t& r3, uint32_t addr)
{
    asm volatile("ldmatrix.sync.aligned.m8n8.x4.trans.shared.b16 {%0,%1,%2,%3}, [%4];"
                 : "=r"(r0), "=r"(r1), "=r"(r2), "=r"(r3) : "r"(addr));
}

__device__ __forceinline__ uint32_t su32(const void* p) {
    return (uint32_t)__cvta_generic_to_shared(p);
}

__device__ __forceinline__ uint32_t pack_bf16x2(float a, float b) {
    __nv_bfloat162 t = __floats2bfloat162_rn(a, b);
    return *(uint32_t*)&t;
}

// ---------------------------------------------------------------------------
// Split conversion: fp32 -> (hi, lo) bf16, same layout. n % 4 == 0.
// ---------------------------------------------------------------------------
__global__ __launch_bounds__(256) void split_kernel(
    const float* __restrict__ x,
    __nv_bfloat16* __restrict__ hi, __nv_bfloat16* __restrict__ lo, int n)
{
    int i = (blockIdx.x * blockDim.x + threadIdx.x) * 4;
    if (i >= n) return;
    float4 v = *(const float4*)(x + i);
    __nv_bfloat16 h0 = __float2bfloat16(v.x);
    __nv_bfloat16 h1 = __float2bfloat16(v.y);
    __nv_bfloat16 h2 = __float2bfloat16(v.z);
    __nv_bfloat16 h3 = __float2bfloat16(v.w);
    __nv_bfloat162 hA; hA.x = h0; hA.y = h1;
    __nv_bfloat162 hB; hB.x = h2; hB.y = h3;
    __nv_bfloat162 lA;
    lA.x = __float2bfloat16(v.x - __bfloat162float(h0));
    lA.y = __float2bfloat16(v.y - __bfloat162float(h1));
    __nv_bfloat162 lB;
    lB.x = __float2bfloat16(v.z - __bfloat162float(h2));
    lB.y = __float2bfloat16(v.w - __bfloat162float(h3));
    *(__nv_bfloat162*)(hi + i)     = hA;
    *(__nv_bfloat162*)(hi + i + 2) = hB;
    *(__nv_bfloat162*)(lo + i)     = lA;
    *(__nv_bfloat162*)(lo + i + 2) = lB;
}

// ---------------------------------------------------------------------------
// Transpose + split: W[K,N] fp32 -> Th/Tl [N,K] bf16. K,N % 32 == 0.
// ---------------------------------------------------------------------------
__global__ __launch_bounds__(256) void transpose_split_kernel(
    const float* __restrict__ W,
    __nv_bfloat16* __restrict__ Th, __nv_bfloat16* __restrict__ Tl,
    int K, int N)
{
    __shared__ float tile[32][33];
    const int bn = blockIdx.x * 32;
    const int bk = blockIdx.y * 32;
    const int tx = threadIdx.x;
    const int ty = threadIdx.y;
#pragma unroll
    for (int j = 0; j < 32; j += 8)
        tile[ty + j][tx] = W[(size_t)(bk + ty + j) * N + bn + tx];
    __syncthreads();
#pragma unroll
    for (int j = 0; j < 32; j += 8) {
        float v = tile[tx][ty + j];
        __nv_bfloat16 h = __float2bfloat16(v);
        __nv_bfloat16 l = __float2bfloat16(v - __bfloat162float(h));
        size_t o = (size_t)(bn + ty + j) * K + bk + tx;
        Th[o] = h;
        Tl[o] = l;
    }
}

// ---------------------------------------------------------------------------
// mma.sync bf16x3 GEMM (unchanged from R5): C[M,N] = A[M,K] @ B[K,N].
// ---------------------------------------------------------------------------
#define GPITCH 40

__global__ __launch_bounds__(256) void gemm_mma_kernel(
    int M, int N, int K,
    const __nv_bfloat16* __restrict__ Ah, const __nv_bfloat16* __restrict__ Al,
    const __nv_bfloat16* __restrict__ Bh, const __nv_bfloat16* __restrict__ Bl,
    float* __restrict__ C)
{
    __shared__ __nv_bfloat16 sAh[128 * GPITCH], sAl[128 * GPITCH];
    __shared__ __nv_bfloat16 sBh[128 * GPITCH], sBl[128 * GPITCH];

    const int tid  = threadIdx.x;
    const int lane = tid & 31;
    const int wid  = tid >> 5;
    const int wm   = wid >> 2;
    const int wn   = wid & 3;
    const int gq   = lane >> 2;
    const int tg   = lane & 3;
    const int bm = blockIdx.y * 128;
    const int bn = blockIdx.x * 128;

    const int r0g = tid >> 2, q0 = tid & 3;
    const int r1g = (tid + 256) >> 2, q1 = (tid + 256) & 3;

    float acc[4][4][4];
#pragma unroll
    for (int a = 0; a < 4; a++)
#pragma unroll
        for (int b = 0; b < 4; b++)
#pragma unroll
            for (int c = 0; c < 4; c++) acc[a][b][c] = 0.f;

    const int nch = K / 32;
    uint4 pA0, pA1, pAl0, pAl1, pB0, pB1, pBl0, pBl1;
    {
        pA0  = *(const uint4*)(Ah + (size_t)(bm + r0g) * K + q0 * 8);
        pA1  = *(const uint4*)(Ah + (size_t)(bm + r1g) * K + q1 * 8);
        pAl0 = *(const uint4*)(Al + (size_t)(bm + r0g) * K + q0 * 8);
        pAl1 = *(const uint4*)(Al + (size_t)(bm + r1g) * K + q1 * 8);
        pB0  = *(const uint4*)(Bh + (size_t)(bn + r0g) * K + q0 * 8);
        pB1  = *(const uint4*)(Bh + (size_t)(bn + r1g) * K + q1 * 8);
        pBl0 = *(const uint4*)(Bl + (size_t)(bn + r0g) * K + q0 * 8);
        pBl1 = *(const uint4*)(Bl + (size_t)(bn + r1g) * K + q1 * 8);
    }

    for (int c = 0; c < nch; c++) {
        __syncthreads();
        *(uint4*)&sAh[r0g * GPITCH + q0 * 8] = pA0;
        *(uint4*)&sAh[r1g * GPITCH + q1 * 8] = pA1;
        *(uint4*)&sAl[r0g * GPITCH + q0 * 8] = pAl0;
        *(uint4*)&sAl[r1g * GPITCH + q1 * 8] = pAl1;
        *(uint4*)&sBh[r0g * GPITCH + q0 * 8] = pB0;
        *(uint4*)&sBh[r1g * GPITCH + q1 * 8] = pB1;
        *(uint4*)&sBl[r0g * GPITCH + q0 * 8] = pBl0;
        *(uint4*)&sBl[r1g * GPITCH + q1 * 8] = pBl1;
        __syncthreads();

        if (c + 1 < nch) {
            const int k0 = (c + 1) * 32;
            pA0  = *(const uint4*)(Ah + (size_t)(bm + r0g) * K + k0 + q0 * 8);
            pA1  = *(const uint4*)(Ah + (size_t)(bm + r1g) * K + k0 + q1 * 8);
            pAl0 = *(const uint4*)(Al + (size_t)(bm + r0g) * K + k0 + q0 * 8);
            pAl1 = *(const uint4*)(Al + (size_t)(bm + r1g) * K + k0 + q1 * 8);
            pB0  = *(const uint4*)(Bh + (size_t)(bn + r0g) * K + k0 + q0 * 8);
            pB1  = *(const uint4*)(Bh + (size_t)(bn + r1g) * K + k0 + q1 * 8);
            pBl0 = *(const uint4*)(Bl + (size_t)(bn + r0g) * K + k0 + q0 * 8);
            pBl1 = *(const uint4*)(Bl + (size_t)(bn + r1g) * K + k0 + q1 * 8);
        }

#pragma unroll
        for (int ks = 0; ks < 2; ks++) {
            const int kk = ks * 16;
            uint32_t ah[4][4], al[4][4], bh[4][2], bl[4][2];
#pragma unroll
            for (int mt = 0; mt < 4; mt++) {
                int row = wm * 64 + mt * 16 + gq;
                ah[mt][0] = *(const uint32_t*)&sAh[row * GPITCH + kk + 2 * tg];
                ah[mt][1] = *(const uint32_t*)&sAh[(row + 8) * GPITCH + kk + 2 * tg];
                ah[mt][2] = *(const uint32_t*)&sAh[row * GPITCH + kk + 2 * tg + 8];
                ah[mt][3] = *(const uint32_t*)&sAh[(row + 8) * GPITCH + kk + 2 * tg + 8];
                al[mt][0] = *(const uint32_t*)&sAl[row * GPITCH + kk + 2 * tg];
                al[mt][1] = *(const uint32_t*)&sAl[(row + 8) * GPITCH + kk + 2 * tg];
                al[mt][2] = *(const uint32_t*)&sAl[row * GPITCH + kk + 2 * tg + 8];
                al[mt][3] = *(const uint32_t*)&sAl[(row + 8) * GPITCH + kk + 2 * tg + 8];
            }
#pragma unroll
            for (int nt = 0; nt < 4; nt++) {
                int n = wn * 32 + nt * 8 + gq;
                bh[nt][0] = *(const uint32_t*)&sBh[n * GPITCH + kk + 2 * tg];
                bh[nt][1] = *(const uint32_t*)&sBh[n * GPITCH + kk + 2 * tg + 8];
                bl[nt][0] = *(const uint32_t*)&sBl[n * GPITCH + kk + 2 * tg];
                bl[nt][1] = *(const uint32_t*)&sBl[n * GPITCH + kk + 2 * tg + 8];
            }
#pragma unroll
            for (int mt = 0; mt < 4; mt++)
#pragma unroll
                for (int nt = 0; nt < 4; nt++) {
                    mma16816(acc[mt][nt], ah[mt][0], ah[mt][1], ah[mt][2], ah[mt][3],
                             bh[nt][0], bh[nt][1]);
                    mma16816(acc[mt][nt], ah[mt][0], ah[mt][1], ah[mt][2], ah[mt][3],
                             bl[nt][0], bl[nt][1]);
                    mma16816(acc[mt][nt], al[mt][0], al[mt][1], al[mt][2], al[mt][3],
                             bh[nt][0], bh[nt][1]);
                }
        }
    }

#pragma unroll
    for (int mt = 0; mt < 4; mt++) {
        int row = bm + wm * 64 + mt * 16 + gq;
#pragma unroll
        for (int nt = 0; nt < 4; nt++) {
            int col = bn + wn * 32 + nt * 8 + 2 * tg;
            *(float2*)(C + (size_t)row * N + col) =
                make_float2(acc[mt][nt][0], acc[mt][nt][1]);
            *(float2*)(C + (size_t)(row + 8) * N + col) =
                make_float2(acc[mt][nt][2], acc[mt][nt][3]);
        }
    }
}

// ---------------------------------------------------------------------------
// Per-head RMSNorm + neox RoPE: one warp per (t, head). No smem, no bar.
// grid = TT*24/8 blocks of 256 threads (8 warps).
// ---------------------------------------------------------------------------
__global__ __launch_bounds__(256) void norm_rope_kernel(
    const int* __restrict__ positions,
    const float* __restrict__ qw, const float* __restrict__ kw,
    float* __restrict__ qkv)
{
    const int gw   = blockIdx.x * 8 + (threadIdx.x >> 5);
    const int lane = threadIdx.x & 31;
    const int t = gw / (NH + NKV);
    const int h = gw % (NH + NKV);

    float* ptr = qkv + (size_t)t * QKVW + h * DH;
    const float* w = (h < NH) ? qw : kw;

    float4 x = ((const float4*)ptr)[lane];
    float ss = x.x * x.x + x.y * x.y + x.z * x.z + x.w * x.w;
#pragma unroll
    for (int o = 16; o > 0; o >>= 1) ss += __shfl_xor_sync(0xffffffffu, ss, o);
    float rinv = rsqrtf(ss * (1.f / DH) + EPS);

    float4 wv = ((const float4*)w)[lane];
    float4 xn = make_float4(x.x * rinv * wv.x, x.y * rinv * wv.y,
                            x.z * rinv * wv.z, x.w * rinv * wv.w);

    // exchange halves: lane l <-> lane l^16
    float4 other;
    other.x = __shfl_xor_sync(0xffffffffu, xn.x, 16);
    other.y = __shfl_xor_sync(0xffffffffu, xn.y, 16);
    other.z = __shfl_xor_sync(0xffffffffu, xn.z, 16);
    other.w = __shfl_xor_sync(0xffffffffu, xn.w, 16);

    const float pos = (float)positions[t];
    const int j = (lane & 15) * 4;
    float4 outv;
    float* xo = (float*)&outv;
    const float* x1 = (lane < 16) ? (const float*)&xn : (const float*)&other;
    const float* x2 = (lane < 16) ? (const float*)&other : (const float*)&xn;
#pragma unroll
    for (int c = 0; c < 4; c++) {
        float inv_freq = powf(10000.f, -(float)(j + c) * (1.f / 64.f));
        float sv, cv;
        sincosf(pos * inv_freq, &sv, &cv);
        xo[c] = (lane < 16) ? (x1[c] * cv - x2[c] * sv)
                            : (x2[c] * cv + x1[c] * sv);
    }
    ((float4*)ptr)[lane] = outv;
}

// ---------------------------------------------------------------------------
// FA2-style causal GQA attention, bf16x3 mma, in-register softmax.
// 256 threads = 8 warps; warp w owns rows w*16..w*16+15 of the 128-row q-tile.
// Per 64-key tile: QK (warp 16x64), reg softmax, PV (warp 16x128).
// Epilogue writes split bf16 hi/lo directly (feeds O-proj GEMM).
// ---------------------------------------------------------------------------
#define AT_BM 128
#define AT_BN 64
#define QP 136      // Q/K/V smem pitch (bf16): 272B rows, conflict-free frags

struct AttnSmem {
    __nv_bfloat16 Qh[AT_BM * QP], Ql[AT_BM * QP];
    __nv_bfloat16 Kh[AT_BN * QP], Kl[AT_BN * QP];
    __nv_bfloat16 Vh[AT_BN * QP], Vl[AT_BN * QP];
};

__global__ __launch_bounds__(256, 1) void attn_kernel(
    const float* __restrict__ qkv,
    __nv_bfloat16* __restrict__ oh, __nv_bfloat16* __restrict__ ol)
{
    extern __shared__ char smem_raw[];
    AttnSmem& s = *(AttnSmem*)smem_raw;

    const int h   = blockIdx.x;
    const int m0  = (gridDim.y - 1 - blockIdx.y) * AT_BM;  // heavy blocks first
    const int kvh = h >> 1;
    const int tid = threadIdx.x;
    const int lane = tid & 31;
    const int w    = tid >> 5;       // warp 0..7 -> rows w*16
    const int gq   = lane >> 2;
    const int tg   = lane & 3;
    const float scale = 0.08838834764831845f;

    const float* qbase = qkv + h * DH;
    const float* kbase = qkv + NH * DH + kvh * DH;
    const float* vbase = qkv + (NH + NKV) * DH + kvh * DH;

    // Load + scale + split Q tile [row][d]
    for (int u = tid; u < AT_BM * 32; u += 256) {
        int row = u >> 5;
        int d   = (u & 31) << 2;
        float4 q4 = *(const float4*)(qbase + (size_t)(m0 + row) * QKVW + d);
        float q0 = q4.x * scale, q1 = q4.y * scale, q2 = q4.z * scale, q3 = q4.w * scale;
        __nv_bfloat16 h0 = __float2bfloat16(q0), h1 = __float2bfloat16(q1);
        __nv_bfloat16 h2 = __float2bfloat16(q2), h3 = __float2bfloat16(q3);
        s.Qh[row * QP + d + 0] = h0; s.Qh[row * QP + d + 1] = h1;
        s.Qh[row * QP + d + 2] = h2; s.Qh[row * QP + d + 3] = h3;
        s.Ql[row * QP + d + 0] = __float2bfloat16(q0 - __bfloat162float(h0));
        s.Ql[row * QP + d + 1] = __float2bfloat16(q1 - __bfloat162float(h1));
        s.Ql[row * QP + d + 2] = __float2bfloat16(q2 - __bfloat162float(h2));
        s.Ql[row * QP + d + 3] = __float2bfloat16(q3 - __bfloat162float(h3));
    }

    // Per-thread softmax state: rows (gq) and (gq+8) of this warp's 16-row strip
    float m_[2] = { -CUDART_INF_F, -CUDART_INF_F };
    float l_[2] = { 0.f, 0.f };

    float accO[16][4];
#pragma unroll
    for (int a = 0; a < 16; a++)
#pragma unroll
        for (int c = 0; c < 4; c++) accO[a][c] = 0.f;

    const uint32_t vlane_off = (uint32_t)((lane & 15) * (QP * 2) + ((lane >> 4) << 4));
    const uint32_t svh = su32(s.Vh);
    const uint32_t svl = su32(s.Vl);

    const int row0 = m0 + w * 16 + gq;   // global q row (and row0+8)
    const int n_tiles = (m0 + AT_BM) / AT_BN;

    for (int tile = 0; tile < n_tiles; tile++) {
        const int n0 = tile * AT_BN;
        __syncthreads();  // prev tile consumers done; Q visible on iter 0

        // Load + split K,V tiles [key][d]
        for (int u = tid; u < AT_BN * 32; u += 256) {
            int key = u >> 5;
            int d   = (u & 31) << 2;
            float4 k4 = *(const float4*)(kbase + (size_t)(n0 + key) * QKVW + d);
            float4 v4 = *(const float4*)(vbase + (size_t)(n0 + key) * QKVW + d);
            __nv_bfloat16 kh0 = __float2bfloat16(k4.x), kh1 = __float2bfloat16(k4.y);
            __nv_bfloat16 kh2 = __float2bfloat16(k4.z), kh3 = __float2bfloat16(k4.w);
            s.Kh[key * QP + d + 0] = kh0; s.Kh[key * QP + d + 1] = kh1;
            s.Kh[key * QP + d + 2] = kh2; s.Kh[key * QP + d + 3] = kh3;
            s.Kl[key * QP + d + 0] = __float2bfloat16(k4.x - __bfloat162float(kh0));
            s.Kl[key * QP + d + 1] = __float2bfloat16(k4.y - __bfloat162float(kh1));
            s.Kl[key * QP + d + 2] = __float2bfloat16(k4.z - __bfloat162float(kh2));
            s.Kl[key * QP + d + 3] = __float2bfloat16(k4.w - __bfloat162float(kh3));
            __nv_bfloat16 vh0 = __float2bfloat16(v4.x), vh1 = __float2bfloat16(v4.y);
            __nv_bfloat16 vh2 = __float2bfloat16(v4.z), vh3 = __float2bfloat16(v4.w);
            s.Vh[key * QP + d + 0] = vh0; s.Vh[key * QP + d + 1] = vh1;
            s.Vh[key * QP + d + 2] = vh2; s.Vh[key * QP + d + 3] = vh3;
            s.Vl[key * QP + d + 0] = __float2bfloat16(v4.x - __bfloat162float(vh0));
            s.Vl[key * QP + d + 1] = __float2bfloat16(v4.y - __bfloat162float(vh1));
            s.Vl[key * QP + d + 2] = __float2bfloat16(v4.z - __bfloat162float(vh2));
            s.Vl[key * QP + d + 3] = __float2bfloat16(v4.w - __bfloat162float(vh3));
        }
        __syncthreads();

        // ---- S = Q @ K^T (bf16x3), warp tile 16x64 ----
        float accS[8][4];
#pragma unroll
        for (int b = 0; b < 8; b++)
#pragma unroll
            for (int c = 0; c < 4; c++) accS[b][c] = 0.f;

#pragma unroll
        for (int ks = 0; ks < 8; ks++) {
            const int kk = ks * 16;
            const int row = w * 16 + gq;
            uint32_t qh0 = *(const uint32_t*)&s.Qh[row * QP + kk + 2 * tg];
            uint32_t qh1 = *(const uint32_t*)&s.Qh[(row + 8) * QP + kk + 2 * tg];
            uint32_t qh2 = *(const uint32_t*)&s.Qh[row * QP + kk + 2 * tg + 8];
            uint32_t qh3 = *(const uint32_t*)&s.Qh[(row + 8) * QP + kk + 2 * tg + 8];
            uint32_t ql0 = *(const uint32_t*)&s.Ql[row * QP + kk + 2 * tg];
            uint32_t ql1 = *(const uint32_t*)&s.Ql[(row + 8) * QP + kk + 2 * tg];
            uint32_t ql2 = *(const uint32_t*)&s.Ql[row * QP + kk + 2 * tg + 8];
            uint32_t ql3 = *(const uint32_t*)&s.Ql[(row + 8) * QP + kk + 2 * tg + 8];
#pragma unroll
            for (int nt = 0; nt < 8; nt++) {
                int n = nt * 8 + gq;
                uint32_t bh0 = *(const uint32_t*)&s.Kh[n * QP + kk + 2 * tg];
                uint32_t bh1 = *(const uint32_t*)&s.Kh[n * QP + kk + 2 * tg + 8];
                uint32_t bl0 = *(const uint32_t*)&s.Kl[n * QP + kk + 2 * tg];
                uint32_t bl1 = *(const uint32_t*)&s.Kl[n * QP + kk + 2 * tg + 8];
                mma16816(accS[nt], qh0, qh1, qh2, qh3, bh0, bh1);
                mma16816(accS[nt], qh0, qh1, qh2, qh3, bl0, bl1);
                mma16816(accS[nt], ql0, ql1, ql2, ql3, bh0, bh1);
            }
        }

        // ---- causal mask (in registers) ----
        if (n0 + AT_BN - 1 > m0) {
#pragma unroll
            for (int nt = 0; nt < 8; nt++) {
                int c0 = n0 + nt * 8 + 2 * tg;
                if (c0     > row0)     accS[nt][0] = -CUDART_INF_F;
                if (c0 + 1 > row0)     accS[nt][1] = -CUDART_INF_F;
                if (c0     > row0 + 8) accS[nt][2] = -CUDART_INF_F;
                if (c0 + 1 > row0 + 8) accS[nt][3] = -CUDART_INF_F;
            }
        }

        // ---- in-register online softmax (rows gq, gq+8) ----
        float mx0 = accS[0][0], mx1 = accS[0][2];
#pragma unroll
        for (int nt = 0; nt < 8; nt++) {
            mx0 = fmaxf(mx0, fmaxf(accS[nt][0], accS[nt][1]));
            mx1 = fmaxf(mx1, fmaxf(accS[nt][2], accS[nt][3]));
        }
        mx0 = fmaxf(mx0, __shfl_xor_sync(0xffffffffu, mx0, 1));
        mx0 = fmaxf(mx0, __shfl_xor_sync(0xffffffffu, mx0, 2));
        mx1 = fmaxf(mx1, __shfl_xor_sync(0xffffffffu, mx1, 1));
        mx1 = fmaxf(mx1, __shfl_xor_sync(0xffffffffu, mx1, 2));

        float mn0 = fmaxf(m_[0], mx0);
        float mn1 = fmaxf(m_[1], mx1);
        float corr0 = __expf(m_[0] - mn0);
        float corr1 = __expf(m_[1] - mn1);
        float sum0 = 0.f, sum1 = 0.f;
#pragma unroll
        for (int nt = 0; nt < 8; nt++) {
            accS[nt][0] = __expf(accS[nt][0] - mn0);
            accS[nt][1] = __expf(accS[nt][1] - mn0);
            accS[nt][2] = __expf(accS[nt][2] - mn1);
            accS[nt][3] = __expf(accS[nt][3] - mn1);
            sum0 += accS[nt][0] + accS[nt][1];
            sum1 += accS[nt][2] + accS[nt][3];
        }
        sum0 += __shfl_xor_sync(0xffffffffu, sum0, 1);
        sum0 += __shfl_xor_sync(0xffffffffu, sum0, 2);
        sum1 += __shfl_xor_sync(0xffffffffu, sum1, 1);
        sum1 += __shfl_xor_sync(0xffffffffu, sum1, 2);
        l_[0] = l_[0] * corr0 + sum0;
        l_[1] = l_[1] * corr1 + sum1;
        m_[0] = mn0; m_[1] = mn1;

        // rescale accO
#pragma unroll
        for (int nt = 0; nt < 16; nt++) {
            accO[nt][0] *= corr0; accO[nt][1] *= corr0;
            accO[nt][2] *= corr1; accO[nt][3] *= corr1;
        }

        // ---- O += P @ V (bf16x3), warp tile 16x128, k=64 ----
#pragma unroll
        for (int kc = 0; kc < 4; kc++) {
            // P fragments (hi/lo) straight from accS: A-layout == C-layout pairing
            float p00 = accS[2 * kc][0],     p01 = accS[2 * kc][1];
            float p10 = accS[2 * kc][2],     p11 = accS[2 * kc][3];
            float p20 = accS[2 * kc + 1][0], p21 = accS[2 * kc + 1][1];
            float p30 = accS[2 * kc + 1][2], p31 = accS[2 * kc + 1][3];
            float h00 = __bfloat162float(__float2bfloat16(p00));
            float h01 = __bfloat162float(__float2bfloat16(p01));
            float h10 = __bfloat162float(__float2bfloat16(p10));
            float h11 = __bfloat162float(__float2bfloat16(p11));
            float h20 = __bfloat162float(__float2bfloat16(p20));
            float h21 = __bfloat162float(__float2bfloat16(p21));
            float h30 = __bfloat162float(__float2bfloat16(p30));
            float h31 = __bfloat162float(__float2bfloat16(p31));
            uint32_t ph0 = pack_bf16x2(h00, h01);
            uint32_t ph1 = pack_bf16x2(h10, h11);
            uint32_t ph2 = pack_bf16x2(h20, h21);
            uint32_t ph3 = pack_bf16x2(h30, h31);
            uint32_t pl0 = pack_bf16x2(p00 - h00, p01 - h01);
            uint32_t pl1 = pack_bf16x2(p10 - h10, p11 - h11);
            uint32_t pl2 = pack_bf16x2(p20 - h20, p21 - h21);
            uint32_t pl3 = pack_bf16x2(p30 - h30, p31 - h31);

#pragma unroll
            for (int ncg = 0; ncg < 8; ncg++) {
                uint32_t base_off = (uint32_t)(kc * 16 * (QP * 2) + ncg * 32) + vlane_off;
                uint32_t vh0, vh1, vh2, vh3, vl0, vl1, vl2, vl3;
                ldsm_x4_t(vh0, vh1, vh2, vh3, svh + base_off);
                ldsm_x4_t(vl0, vl1, vl2, vl3, svl + base_off);
                mma16816(accO[ncg * 2],     ph0, ph1, ph2, ph3, vh0, vh1);
                mma16816(accO[ncg * 2],     ph0, ph1, ph2, ph3, vl0, vl1);
                mma16816(accO[ncg * 2],     pl0, pl1, pl2, pl3, vh0, vh1);
                mma16816(accO[ncg * 2 + 1], ph0, ph1, ph2, ph3, vh2, vh3);
                mma16816(accO[ncg * 2 + 1], ph0, ph1, ph2, ph3, vl2, vl3);
                mma16816(accO[ncg * 2 + 1], pl0, pl1, pl2, pl3, vh2, vh3);
            }
        }
    }

    // ---- normalize + split-write bf16 hi/lo: out[t][h*128 + d] ----
    float i0 = 1.f / l_[0];
    float i1 = 1.f / l_[1];
#pragma unroll
    for (int nt = 0; nt < 16; nt++) {
        int col = h * DH + nt * 8 + 2 * tg;
        float v0 = accO[nt][0] * i0, v1 = accO[nt][1] * i0;
        float v2 = accO[nt][2] * i1, v3 = accO[nt][3] * i1;
        float h0 = __bfloat162float(__float2bfloat16(v0));
        float h1 = __bfloat162float(__float2bfloat16(v1));
        float h2 = __bfloat162float(__float2bfloat16(v2));
        float h3 = __bfloat162float(__float2bfloat16(v3));
        size_t o0 = (size_t)row0 * HID + col;
        size_t o1 = (size_t)(row0 + 8) * HID + col;
        *(uint32_t*)(oh + o0) = pack_bf16x2(h0, h1);
        *(uint32_t*)(oh + o1) = pack_bf16x2(h2, h3);
        *(uint32_t*)(ol + o0) = pack_bf16x2(v0 - h0, v1 - h1);
        *(uint32_t*)(ol + o1) = pack_bf16x2(v2 - h2, v3 - h3);
    }
}

// ---------------------------------------------------------------------------
// Launch
// ---------------------------------------------------------------------------
extern "C" void kernel_launch(void* const* d_in, const int* in_sizes, int n_in,
                              void* d_out, int out_size)
{
    const int*   positions = (const int*)d_in[0];
    const float* hidden    = (const float*)d_in[1];
    const float* w_qkv     = (const float*)d_in[2];
    const float* w_o       = (const float*)d_in[3];
    const float* q_norm_w  = (const float*)d_in[4];
    const float* k_norm_w  = (const float*)d_in[5];
    float*       out       = (float*)d_out;

    float* qkv_ptr = nullptr;
    __nv_bfloat16 *ah, *al, *bh, *bl;
    cudaGetSymbolAddress((void**)&qkv_ptr, g_qkv);
    cudaGetSymbolAddress((void**)&ah, g_ah);
    cudaGetSymbolAddress((void**)&al, g_al);
    cudaGetSymbolAddress((void**)&bh, g_bh);
    cudaGetSymbolAddress((void**)&bl, g_bl);

    // 1. Split hidden; transpose+split w_qkv.
    {
        int n = TT * HID;
        split_kernel<<<n / 4 / 256, 256>>>(hidden, ah, al, n);
        dim3 tg(QKVW / 32, HID / 32);
        transpose_split_kernel<<<tg, dim3(32, 8)>>>(w_qkv, bh, bl, HID, QKVW);
    }

    // 2. QKV projection via mma.sync bf16x3.
    {
        dim3 grid(QKVW / 128, TT / 128);
        gemm_mma_kernel<<<grid, 256>>>(TT, QKVW, HID, ah, al, bh, bl, qkv_ptr);
    }

    // 3. RMSNorm + RoPE on q,k (warp-per-head, in-place fp32)
    {
        norm_rope_kernel<<<TT * (NH + NKV) / 8, 256>>>(positions, q_norm_w, k_norm_w, qkv_ptr);
    }

    // 4. transpose+split w_o (bh/bl free after QKV GEMM)
    {
        dim3 tg(HID / 32, (NH * DH) / 32);
        transpose_split_kernel<<<tg, dim3(32, 8)>>>(w_o, bh, bl, NH * DH, HID);
    }

    // 5. Causal GQA flash attention (bf16x3, in-register softmax),
    //    writes split bf16 hi/lo directly into ah/al.
    {
        static_assert(sizeof(AttnSmem) <= 227 * 1024, "smem");
        cudaFuncSetAttribute(attn_kernel,
                             cudaFuncAttributeMaxDynamicSharedMemorySize,
                             (int)sizeof(AttnSmem));
        dim3 grid(NH, TT / AT_BM);
        attn_kernel<<<grid, 256, sizeof(AttnSmem)>>>(qkv_ptr, ah, al);
    }

    // 6. Output projection via mma.sync bf16x3.
    {
        dim3 grid(HID / 128, TT / 128);
        gemm_mma_kernel<<<grid, 256>>>(TT, HID, NH * DH, ah, al, bh, bl, out);
    }
}

// round 7
// speedup vs baseline: 2.4704x; 1.0683x over previous
#include <cuda_runtime.h>
#include <cuda_bf16.h>
#include <math.h>
#include <math_constants.h>
#include <stdint.h>

// Problem constants
#define TT   2048
#define HID  2048
#define NH   16
#define NKV  8
#define DH   128
#define QKVW ((NH + 2 * NKV) * DH)   // 4096
#define QW   (NH * DH)               // 2048
#define KVW  (NKV * DH)              // 1024
#define EPS  1e-6f

// Scratch (allocation-free rule: __device__ globals)
__device__ float g_qkv[(size_t)TT * QKVW];           // fp32 qkv (GEMM out)
__device__ __nv_bfloat16 g_ah[(size_t)TT * HID];     // GEMM A hi / attn-out hi
__device__ __nv_bfloat16 g_al[(size_t)TT * HID];     // GEMM A lo / attn-out lo
__device__ __nv_bfloat16 g_bh[(size_t)QKVW * HID];   // B^T hi ([N,K])
__device__ __nv_bfloat16 g_bl[(size_t)QKVW * HID];   // B^T lo
__device__ __nv_bfloat16 g_qsh[(size_t)TT * QW],  g_qsl[(size_t)TT * QW];   // split Q (scaled)
__device__ __nv_bfloat16 g_ksh[(size_t)TT * KVW], g_ksl[(size_t)TT * KVW];  // split K
__device__ __nv_bfloat16 g_vsh[(size_t)TT * KVW], g_vsl[(size_t)TT * KVW];  // split V

// ---------------------------------------------------------------------------
// PTX helpers (base sm_103 target — HMMA mma.sync + LDGSTS cp.async)
// ---------------------------------------------------------------------------
__device__ __forceinline__ void mma16816(float d[4],
                                         uint32_t a0, uint32_t a1, uint32_t a2, uint32_t a3,
                                         uint32_t b0, uint32_t b1)
{
    asm volatile(
        "mma.sync.aligned.m16n8k16.row.col.f32.bf16.bf16.f32 "
        "{%0,%1,%2,%3}, {%4,%5,%6,%7}, {%8,%9}, {%0,%1,%2,%3};\n"
        : "+f"(d[0]), "+f"(d[1]), "+f"(d[2]), "+f"(d[3])
        : "r"(a0), "r"(a1), "r"(a2), "r"(a3), "r"(b0), "r"(b1));
}

__device__ __forceinline__ void ldsm_x4_t(uint32_t& r0, uint32_t& r1,
                                          uint32_t& r2, uint32_t& r3, uint32_t addr)
{
    asm volatile("ldmatrix.sync.aligned.m8n8.x4.trans.shared.b16 {%0,%1,%2,%3}, [%4];"
                 : "=r"(r0), "=r"(r1), "=r"(r2), "=r"(r3) : "r"(addr));
}

__device__ __forceinline__ uint32_t su32(const void* p) {
    return (uint32_t)__cvta_generic_to_shared(p);
}

__device__ __forceinline__ uint32_t pack_bf16x2(float a, float b) {
    __nv_bfloat162 t = __floats2bfloat162_rn(a, b);
    return *(uint32_t*)&t;
}

__device__ __forceinline__ void cp_async16(uint32_t dst, const void* src) {
    asm volatile("cp.async.cg.shared.global [%0], [%1], 16;" :: "r"(dst), "l"(src));
}
__device__ __forceinline__ void cp_commit() {
    asm volatile("cp.async.commit_group;" ::: "memory");
}
template <int N>
__device__ __forceinline__ void cp_wait() {
    asm volatile("cp.async.wait_group %0;" :: "n"(N) : "memory");
}

// hi/lo split of a float4, stored as 2x bf162 each
__device__ __forceinline__ void split4_store(float4 v, __nv_bfloat16* hp, __nv_bfloat16* lp) {
    __nv_bfloat16 h0 = __float2bfloat16(v.x), h1 = __float2bfloat16(v.y);
    __nv_bfloat16 h2 = __float2bfloat16(v.z), h3 = __float2bfloat16(v.w);
    *(uint32_t*)(hp)     = pack_bf16x2(__bfloat162float(h0), __bfloat162float(h1));
    *(uint32_t*)(hp + 2) = pack_bf16x2(__bfloat162float(h2), __bfloat162float(h3));
    *(uint32_t*)(lp)     = pack_bf16x2(v.x - __bfloat162float(h0), v.y - __bfloat162float(h1));
    *(uint32_t*)(lp + 2) = pack_bf16x2(v.z - __bfloat162float(h2), v.w - __bfloat162float(h3));
}

// ---------------------------------------------------------------------------
// Split conversion: fp32 -> (hi, lo) bf16, same layout. n % 4 == 0.
// ---------------------------------------------------------------------------
__global__ __launch_bounds__(256) void split_kernel(
    const float* __restrict__ x,
    __nv_bfloat16* __restrict__ hi, __nv_bfloat16* __restrict__ lo, int n)
{
    int i = (blockIdx.x * blockDim.x + threadIdx.x) * 4;
    if (i >= n) return;
    float4 v = *(const float4*)(x + i);
    split4_store(v, hi + i, lo + i);
}

// ---------------------------------------------------------------------------
// Transpose + split: W[K,N] fp32 -> Th/Tl [N,K] bf16. K,N % 32 == 0.
// ---------------------------------------------------------------------------
__global__ __launch_bounds__(256) void transpose_split_kernel(
    const float* __restrict__ W,
    __nv_bfloat16* __restrict__ Th, __nv_bfloat16* __restrict__ Tl,
    int K, int N)
{
    __shared__ float tile[32][33];
    const int bn = blockIdx.x * 32;
    const int bk = blockIdx.y * 32;
    const int tx = threadIdx.x;
    const int ty = threadIdx.y;
#pragma unroll
    for (int j = 0; j < 32; j += 8)
        tile[ty + j][tx] = W[(size_t)(bk + ty + j) * N + bn + tx];
    __syncthreads();
#pragma unroll
    for (int j = 0; j < 32; j += 8) {
        float v = tile[tx][ty + j];
        __nv_bfloat16 h = __float2bfloat16(v);
        __nv_bfloat16 l = __float2bfloat16(v - __bfloat162float(h));
        size_t o = (size_t)(bn + ty + j) * K + bk + tx;
        Th[o] = h;
        Tl[o] = l;
    }
}

// ---------------------------------------------------------------------------
// mma.sync bf16x3 GEMM (unchanged): C[M,N] = A[M,K] @ B[K,N].
// ---------------------------------------------------------------------------
#define GPITCH 40

__global__ __launch_bounds__(256) void gemm_mma_kernel(
    int M, int N, int K,
    const __nv_bfloat16* __restrict__ Ah, const __nv_bfloat16* __restrict__ Al,
    const __nv_bfloat16* __restrict__ Bh, const __nv_bfloat16* __restrict__ Bl,
    float* __restrict__ C)
{
    __shared__ __nv_bfloat16 sAh[128 * GPITCH], sAl[128 * GPITCH];
    __shared__ __nv_bfloat16 sBh[128 * GPITCH], sBl[128 * GPITCH];

    const int tid  = threadIdx.x;
    const int lane = tid & 31;
    const int wid  = tid >> 5;
    const int wm   = wid >> 2;
    const int wn   = wid & 3;
    const int gq   = lane >> 2;
    const int tg   = lane & 3;
    const int bm = blockIdx.y * 128;
    const int bn = blockIdx.x * 128;

    const int r0g = tid >> 2, q0 = tid & 3;
    const int r1g = (tid + 256) >> 2, q1 = (tid + 256) & 3;

    float acc[4][4][4];
#pragma unroll
    for (int a = 0; a < 4; a++)
#pragma unroll
        for (int b = 0; b < 4; b++)
#pragma unroll
            for (int c = 0; c < 4; c++) acc[a][b][c] = 0.f;

    const int nch = K / 32;
    uint4 pA0, pA1, pAl0, pAl1, pB0, pB1, pBl0, pBl1;
    {
        pA0  = *(const uint4*)(Ah + (size_t)(bm + r0g) * K + q0 * 8);
        pA1  = *(const uint4*)(Ah + (size_t)(bm + r1g) * K + q1 * 8);
        pAl0 = *(const uint4*)(Al + (size_t)(bm + r0g) * K + q0 * 8);
        pAl1 = *(const uint4*)(Al + (size_t)(bm + r1g) * K + q1 * 8);
        pB0  = *(const uint4*)(Bh + (size_t)(bn + r0g) * K + q0 * 8);
        pB1  = *(const uint4*)(Bh + (size_t)(bn + r1g) * K + q1 * 8);
        pBl0 = *(const uint4*)(Bl + (size_t)(bn + r0g) * K + q0 * 8);
        pBl1 = *(const uint4*)(Bl + (size_t)(bn + r1g) * K + q1 * 8);
    }

    for (int c = 0; c < nch; c++) {
        __syncthreads();
        *(uint4*)&sAh[r0g * GPITCH + q0 * 8] = pA0;
        *(uint4*)&sAh[r1g * GPITCH + q1 * 8] = pA1;
        *(uint4*)&sAl[r0g * GPITCH + q0 * 8] = pAl0;
        *(uint4*)&sAl[r1g * GPITCH + q1 * 8] = pAl1;
        *(uint4*)&sBh[r0g * GPITCH + q0 * 8] = pB0;
        *(uint4*)&sBh[r1g * GPITCH + q1 * 8] = pB1;
        *(uint4*)&sBl[r0g * GPITCH + q0 * 8] = pBl0;
        *(uint4*)&sBl[r1g * GPITCH + q1 * 8] = pBl1;
        __syncthreads();

        if (c + 1 < nch) {
            const int k0 = (c + 1) * 32;
            pA0  = *(const uint4*)(Ah + (size_t)(bm + r0g) * K + k0 + q0 * 8);
            pA1  = *(const uint4*)(Ah + (size_t)(bm + r1g) * K + k0 + q1 * 8);
            pAl0 = *(const uint4*)(Al + (size_t)(bm + r0g) * K + k0 + q0 * 8);
            pAl1 = *(const uint4*)(Al + (size_t)(bm + r1g) * K + k0 + q1 * 8);
            pB0  = *(const uint4*)(Bh + (size_t)(bn + r0g) * K + k0 + q0 * 8);
            pB1  = *(const uint4*)(Bh + (size_t)(bn + r1g) * K + k0 + q1 * 8);
            pBl0 = *(const uint4*)(Bl + (size_t)(bn + r0g) * K + k0 + q0 * 8);
            pBl1 = *(const uint4*)(Bl + (size_t)(bn + r1g) * K + k0 + q1 * 8);
        }

#pragma unroll
        for (int ks = 0; ks < 2; ks++) {
            const int kk = ks * 16;
            uint32_t ah[4][4], al[4][4], bh[4][2], bl[4][2];
#pragma unroll
            for (int mt = 0; mt < 4; mt++) {
                int row = wm * 64 + mt * 16 + gq;
                ah[mt][0] = *(const uint32_t*)&sAh[row * GPITCH + kk + 2 * tg];
                ah[mt][1] = *(const uint32_t*)&sAh[(row + 8) * GPITCH + kk + 2 * tg];
                ah[mt][2] = *(const uint32_t*)&sAh[row * GPITCH + kk + 2 * tg + 8];
                ah[mt][3] = *(const uint32_t*)&sAh[(row + 8) * GPITCH + kk + 2 * tg + 8];
                al[mt][0] = *(const uint32_t*)&sAl[row * GPITCH + kk + 2 * tg];
                al[mt][1] = *(const uint32_t*)&sAl[(row + 8) * GPITCH + kk + 2 * tg];
                al[mt][2] = *(const uint32_t*)&sAl[row * GPITCH + kk + 2 * tg + 8];
                al[mt][3] = *(const uint32_t*)&sAl[(row + 8) * GPITCH + kk + 2 * tg + 8];
            }
#pragma unroll
            for (int nt = 0; nt < 4; nt++) {
                int n = wn * 32 + nt * 8 + gq;
                bh[nt][0] = *(const uint32_t*)&sBh[n * GPITCH + kk + 2 * tg];
                bh[nt][1] = *(const uint32_t*)&sBh[n * GPITCH + kk + 2 * tg + 8];
                bl[nt][0] = *(const uint32_t*)&sBl[n * GPITCH + kk + 2 * tg];
                bl[nt][1] = *(const uint32_t*)&sBl[n * GPITCH + kk + 2 * tg + 8];
            }
#pragma unroll
            for (int mt = 0; mt < 4; mt++)
#pragma unroll
                for (int nt = 0; nt < 4; nt++) {
                    mma16816(acc[mt][nt], ah[mt][0], ah[mt][1], ah[mt][2], ah[mt][3],
                             bh[nt][0], bh[nt][1]);
                    mma16816(acc[mt][nt], ah[mt][0], ah[mt][1], ah[mt][2], ah[mt][3],
                             bl[nt][0], bl[nt][1]);
                    mma16816(acc[mt][nt], al[mt][0], al[mt][1], al[mt][2], al[mt][3],
                             bh[nt][0], bh[nt][1]);
                }
        }
    }

#pragma unroll
    for (int mt = 0; mt < 4; mt++) {
        int row = bm + wm * 64 + mt * 16 + gq;
#pragma unroll
        for (int nt = 0; nt < 4; nt++) {
            int col = bn + wn * 32 + nt * 8 + 2 * tg;
            *(float2*)(C + (size_t)row * N + col) =
                make_float2(acc[mt][nt][0], acc[mt][nt][1]);
            *(float2*)(C + (size_t)(row + 8) * N + col) =
                make_float2(acc[mt][nt][2], acc[mt][nt][3]);
        }
    }
}

// ---------------------------------------------------------------------------
// RMSNorm + RoPE + hi/lo split. One warp per (t, slot), 32 slots:
// 0..15  q heads  -> norm(qw) + rope + scale -> g_qsh/g_qsl
// 16..23 k heads  -> norm(kw) + rope         -> g_ksh/g_ksl
// 24..31 v slots  -> plain split             -> g_vsh/g_vsl
// ---------------------------------------------------------------------------
__global__ __launch_bounds__(256) void norm_rope_split_kernel(
    const int* __restrict__ positions,
    const float* __restrict__ qw, const float* __restrict__ kw,
    const float* __restrict__ qkv,
    __nv_bfloat16* __restrict__ qsh, __nv_bfloat16* __restrict__ qsl,
    __nv_bfloat16* __restrict__ ksh, __nv_bfloat16* __restrict__ ksl,
    __nv_bfloat16* __restrict__ vsh, __nv_bfloat16* __restrict__ vsl)
{
    const int gw   = blockIdx.x * 8 + (threadIdx.x >> 5);
    const int lane = threadIdx.x & 31;
    const int t    = gw >> 5;
    const int slot = gw & 31;

    if (slot >= 24) {
        const int vh = slot - 24;
        float4 v = ((const float4*)(qkv + (size_t)t * QKVW + (NH + NKV) * DH + vh * DH))[lane];
        size_t o = (size_t)t * KVW + vh * DH + lane * 4;
        split4_store(v, vsh + o, vsl + o);
        return;
    }

    const bool isq = (slot < NH);
    const float* ptr = qkv + (size_t)t * QKVW + slot * DH;
    const float* w = isq ? qw : kw;

    float4 x = ((const float4*)ptr)[lane];
    float ss = x.x * x.x + x.y * x.y + x.z * x.z + x.w * x.w;
#pragma unroll
    for (int o = 16; o > 0; o >>= 1) ss += __shfl_xor_sync(0xffffffffu, ss, o);
    float rinv = rsqrtf(ss * (1.f / DH) + EPS);

    float4 wv = ((const float4*)w)[lane];
    float4 xn = make_float4(x.x * rinv * wv.x, x.y * rinv * wv.y,
                            x.z * rinv * wv.z, x.w * rinv * wv.w);

    float4 other;
    other.x = __shfl_xor_sync(0xffffffffu, xn.x, 16);
    other.y = __shfl_xor_sync(0xffffffffu, xn.y, 16);
    other.z = __shfl_xor_sync(0xffffffffu, xn.z, 16);
    other.w = __shfl_xor_sync(0xffffffffu, xn.w, 16);

    const float pos = (float)positions[t];
    const int j = (lane & 15) * 4;
    float4 outv;
    float* xo = (float*)&outv;
    const float* x1 = (lane < 16) ? (const float*)&xn : (const float*)&other;
    const float* x2 = (lane < 16) ? (const float*)&other : (const float*)&xn;
#pragma unroll
    for (int c = 0; c < 4; c++) {
        float inv_freq = powf(10000.f, -(float)(j + c) * (1.f / 64.f));
        float sv, cv;
        sincosf(pos * inv_freq, &sv, &cv);
        xo[c] = (lane < 16) ? (x1[c] * cv - x2[c] * sv)
                            : (x2[c] * cv + x1[c] * sv);
    }

    if (isq) {
        const float scale = 0.08838834764831845f;  // 1/sqrt(128)
        outv.x *= scale; outv.y *= scale; outv.z *= scale; outv.w *= scale;
        size_t o = (size_t)t * QW + slot * DH + lane * 4;
        split4_store(outv, qsh + o, qsl + o);
    } else {
        size_t o = (size_t)t * KVW + (slot - NH) * DH + lane * 4;
        split4_store(outv, ksh + o, ksl + o);
    }
}

// ---------------------------------------------------------------------------
// FA2-style causal GQA attention, bf16x3 mma, in-register softmax.
// Pre-split bf16 inputs; cp.async double-buffered K/V tiles.
// 256 threads = 8 warps; warp w owns rows w*16..+15 of the 128-row q-tile.
// ---------------------------------------------------------------------------
#define AT_BM 128
#define AT_BN 64
#define QP 136      // smem pitch (bf16): 272B rows, conflict-free frags

struct AttnSmem {
    __nv_bfloat16 Qh[AT_BM * QP], Ql[AT_BM * QP];        // 34816 B each
    __nv_bfloat16 Kh[2][AT_BN * QP], Kl[2][AT_BN * QP];  // 17408 B per buf
    __nv_bfloat16 Vh[2][AT_BN * QP], Vl[2][AT_BN * QP];
};

__global__ __launch_bounds__(256, 1) void attn_kernel(
    const __nv_bfloat16* __restrict__ qsh, const __nv_bfloat16* __restrict__ qsl,
    const __nv_bfloat16* __restrict__ ksh, const __nv_bfloat16* __restrict__ ksl,
    const __nv_bfloat16* __restrict__ vsh, const __nv_bfloat16* __restrict__ vsl,
    __nv_bfloat16* __restrict__ oh, __nv_bfloat16* __restrict__ ol)
{
    extern __shared__ char smem_raw[];
    AttnSmem& s = *(AttnSmem*)smem_raw;

    const int h   = blockIdx.x;
    const int m0  = (gridDim.y - 1 - blockIdx.y) * AT_BM;  // heavy blocks first
    const int kvh = h >> 1;
    const int tid = threadIdx.x;
    const int lane = tid & 31;
    const int w    = tid >> 5;
    const int gq   = lane >> 2;
    const int tg   = lane & 3;

    // Q tile: direct bf16 loads (once per CTA)
    for (int u = tid; u < AT_BM * 16; u += 256) {
        int row = u >> 4;
        int c   = u & 15;
        size_t go = (size_t)(m0 + row) * QW + h * DH + c * 8;
        *(uint4*)((char*)s.Qh + row * 272 + c * 16) = *(const uint4*)(qsh + go);
        *(uint4*)((char*)s.Ql + row * 272 + c * 16) = *(const uint4*)(qsl + go);
    }

    const uint32_t sKh0 = su32(s.Kh[0]), sKh1 = su32(s.Kh[1]);
    const uint32_t sKl0 = su32(s.Kl[0]), sKl1 = su32(s.Kl[1]);
    const uint32_t sVh0 = su32(s.Vh[0]), sVh1 = su32(s.Vh[1]);
    const uint32_t sVl0 = su32(s.Vl[0]), sVl1 = su32(s.Vl[1]);

    // cp.async prefetch of one 64-key tile into buffer b
    auto prefetch = [&](int n0, int b) {
        uint32_t kh = b ? sKh1 : sKh0;
        uint32_t kl = b ? sKl1 : sKl0;
        uint32_t vh = b ? sVh1 : sVh0;
        uint32_t vl = b ? sVl1 : sVl0;
#pragma unroll
        for (int i = 0; i < 4; i++) {
            int u = tid + i * 256;
            int row = u >> 4;
            int c   = u & 15;
            uint32_t so = (uint32_t)(row * 272 + c * 16);
            size_t go = (size_t)(n0 + row) * KVW + kvh * DH + c * 8;
            cp_async16(kh + so, ksh + go);
            cp_async16(kl + so, ksl + go);
            cp_async16(vh + so, vsh + go);
            cp_async16(vl + so, vsl + go);
        }
    };

    float m_[2] = { -CUDART_INF_F, -CUDART_INF_F };
    float l_[2] = { 0.f, 0.f };

    float accO[16][4];
#pragma unroll
    for (int a = 0; a < 16; a++)
#pragma unroll
        for (int c = 0; c < 4; c++) accO[a][c] = 0.f;

    const uint32_t vlane_off = (uint32_t)((lane & 15) * 272 + ((lane >> 4) << 4));

    const int row0 = m0 + w * 16 + gq;
    const int n_tiles = (m0 + AT_BM) / AT_BN;

    prefetch(0, 0);
    cp_commit();

    for (int tile = 0; tile < n_tiles; tile++) {
        const int n0 = tile * AT_BN;
        const int b  = tile & 1;

        if (tile + 1 < n_tiles) {
            prefetch(n0 + AT_BN, b ^ 1);
            cp_commit();
            cp_wait<1>();
        } else {
            cp_wait<0>();
        }
        __syncthreads();   // tile b data visible to all; Q visible on iter 0

        const __nv_bfloat16* Kh = s.Kh[b];
        const __nv_bfloat16* Kl = s.Kl[b];
        const uint32_t svh = b ? sVh1 : sVh0;
        const uint32_t svl = b ? sVl1 : sVl0;

        // ---- S = Q @ K^T (bf16x3), warp tile 16x64 ----
        float accS[8][4];
#pragma unroll
        for (int bb = 0; bb < 8; bb++)
#pragma unroll
            for (int c = 0; c < 4; c++) accS[bb][c] = 0.f;

#pragma unroll
        for (int ks = 0; ks < 8; ks++) {
            const int kk = ks * 16;
            const int row = w * 16 + gq;
            uint32_t qh0 = *(const uint32_t*)&s.Qh[row * QP + kk + 2 * tg];
            uint32_t qh1 = *(const uint32_t*)&s.Qh[(row + 8) * QP + kk + 2 * tg];
            uint32_t qh2 = *(const uint32_t*)&s.Qh[row * QP + kk + 2 * tg + 8];
            uint32_t qh3 = *(const uint32_t*)&s.Qh[(row + 8) * QP + kk + 2 * tg + 8];
            uint32_t ql0 = *(const uint32_t*)&s.Ql[row * QP + kk + 2 * tg];
            uint32_t ql1 = *(const uint32_t*)&s.Ql[(row + 8) * QP + kk + 2 * tg];
            uint32_t ql2 = *(const uint32_t*)&s.Ql[row * QP + kk + 2 * tg + 8];
            uint32_t ql3 = *(const uint32_t*)&s.Ql[(row + 8) * QP + kk + 2 * tg + 8];
#pragma unroll
            for (int nt = 0; nt < 8; nt++) {
                int n = nt * 8 + gq;
                uint32_t bh0 = *(const uint32_t*)&Kh[n * QP + kk + 2 * tg];
                uint32_t bh1 = *(const uint32_t*)&Kh[n * QP + kk + 2 * tg + 8];
                uint32_t bl0 = *(const uint32_t*)&Kl[n * QP + kk + 2 * tg];
                uint32_t bl1 = *(const uint32_t*)&Kl[n * QP + kk + 2 * tg + 8];
                mma16816(accS[nt], qh0, qh1, qh2, qh3, bh0, bh1);
                mma16816(accS[nt], qh0, qh1, qh2, qh3, bl0, bl1);
                mma16816(accS[nt], ql0, ql1, ql2, ql3, bh0, bh1);
            }
        }

        // ---- causal mask ----
        if (n0 + AT_BN - 1 > m0) {
#pragma unroll
            for (int nt = 0; nt < 8; nt++) {
                int c0 = n0 + nt * 8 + 2 * tg;
                if (c0     > row0)     accS[nt][0] = -CUDART_INF_F;
                if (c0 + 1 > row0)     accS[nt][1] = -CUDART_INF_F;
                if (c0     > row0 + 8) accS[nt][2] = -CUDART_INF_F;
                if (c0 + 1 > row0 + 8) accS[nt][3] = -CUDART_INF_F;
            }
        }

        // ---- in-register online softmax ----
        float mx0 = accS[0][0], mx1 = accS[0][2];
#pragma unroll
        for (int nt = 0; nt < 8; nt++) {
            mx0 = fmaxf(mx0, fmaxf(accS[nt][0], accS[nt][1]));
            mx1 = fmaxf(mx1, fmaxf(accS[nt][2], accS[nt][3]));
        }
        mx0 = fmaxf(mx0, __shfl_xor_sync(0xffffffffu, mx0, 1));
        mx0 = fmaxf(mx0, __shfl_xor_sync(0xffffffffu, mx0, 2));
        mx1 = fmaxf(mx1, __shfl_xor_sync(0xffffffffu, mx1, 1));
        mx1 = fmaxf(mx1, __shfl_xor_sync(0xffffffffu, mx1, 2));

        float mn0 = fmaxf(m_[0], mx0);
        float mn1 = fmaxf(m_[1], mx1);
        float corr0 = __expf(m_[0] - mn0);
        float corr1 = __expf(m_[1] - mn1);
        float sum0 = 0.f, sum1 = 0.f;
#pragma unroll
        for (int nt = 0; nt < 8; nt++) {
            accS[nt][0] = __expf(accS[nt][0] - mn0);
            accS[nt][1] = __expf(accS[nt][1] - mn0);
            accS[nt][2] = __expf(accS[nt][2] - mn1);
            accS[nt][3] = __expf(accS[nt][3] - mn1);
            sum0 += accS[nt][0] + accS[nt][1];
            sum1 += accS[nt][2] + accS[nt][3];
        }
        sum0 += __shfl_xor_sync(0xffffffffu, sum0, 1);
        sum0 += __shfl_xor_sync(0xffffffffu, sum0, 2);
        sum1 += __shfl_xor_sync(0xffffffffu, sum1, 1);
        sum1 += __shfl_xor_sync(0xffffffffu, sum1, 2);
        l_[0] = l_[0] * corr0 + sum0;
        l_[1] = l_[1] * corr1 + sum1;
        m_[0] = mn0; m_[1] = mn1;

#pragma unroll
        for (int nt = 0; nt < 16; nt++) {
            accO[nt][0] *= corr0; accO[nt][1] *= corr0;
            accO[nt][2] *= corr1; accO[nt][3] *= corr1;
        }

        // ---- O += P @ V (bf16x3), warp tile 16x128, k=64 ----
#pragma unroll
        for (int kc = 0; kc < 4; kc++) {
            float p00 = accS[2 * kc][0],     p01 = accS[2 * kc][1];
            float p10 = accS[2 * kc][2],     p11 = accS[2 * kc][3];
            float p20 = accS[2 * kc + 1][0], p21 = accS[2 * kc + 1][1];
            float p30 = accS[2 * kc + 1][2], p31 = accS[2 * kc + 1][3];
            float h00 = __bfloat162float(__float2bfloat16(p00));
            float h01 = __bfloat162float(__float2bfloat16(p01));
            float h10 = __bfloat162float(__float2bfloat16(p10));
            float h11 = __bfloat162float(__float2bfloat16(p11));
            float h20 = __bfloat162float(__float2bfloat16(p20));
            float h21 = __bfloat162float(__float2bfloat16(p21));
            float h30 = __bfloat162float(__float2bfloat16(p30));
            float h31 = __bfloat162float(__float2bfloat16(p31));
            uint32_t ph0 = pack_bf16x2(h00, h01);
            uint32_t ph1 = pack_bf16x2(h10, h11);
            uint32_t ph2 = pack_bf16x2(h20, h21);
            uint32_t ph3 = pack_bf16x2(h30, h31);
            uint32_t pl0 = pack_bf16x2(p00 - h00, p01 - h01);
            uint32_t pl1 = pack_bf16x2(p10 - h10, p11 - h11);
            uint32_t pl2 = pack_bf16x2(p20 - h20, p21 - h21);
            uint32_t pl3 = pack_bf16x2(p30 - h30, p31 - h31);

#pragma unroll
            for (int ncg = 0; ncg < 8; ncg++) {
                uint32_t base_off = (uint32_t)(kc * 16 * 272 + ncg * 32) + vlane_off;
                uint32_t vh0, vh1, vh2, vh3, vl0, vl1, vl2, vl3;
                ldsm_x4_t(vh0, vh1, vh2, vh3, svh + base_off);
                ldsm_x4_t(vl0, vl1, vl2, vl3, svl + base_off);
                mma16816(accO[ncg * 2],     ph0, ph1, ph2, ph3, vh0, vh1);
                mma16816(accO[ncg * 2],     ph0, ph1, ph2, ph3, vl0, vl1);
                mma16816(accO[ncg * 2],     pl0, pl1, pl2, pl3, vh0, vh1);
                mma16816(accO[ncg * 2 + 1], ph0, ph1, ph2, ph3, vh2, vh3);
                mma16816(accO[ncg * 2 + 1], ph0, ph1, ph2, ph3, vl2, vl3);
                mma16816(accO[ncg * 2 + 1], pl0, pl1, pl2, pl3, vh2, vh3);
            }
        }
        __syncthreads();   // compute done before next prefetch overwrites buf b^1's pair
    }

    // ---- normalize + split-write bf16 hi/lo ----
    float i0 = 1.f / l_[0];
    float i1 = 1.f / l_[1];
#pragma unroll
    for (int nt = 0; nt < 16; nt++) {
        int col = h * DH + nt * 8 + 2 * tg;
        float v0 = accO[nt][0] * i0, v1 = accO[nt][1] * i0;
        float v2 = accO[nt][2] * i1, v3 = accO[nt][3] * i1;
        float h0 = __bfloat162float(__float2bfloat16(v0));
        float h1 = __bfloat162float(__float2bfloat16(v1));
        float h2 = __bfloat162float(__float2bfloat16(v2));
        float h3 = __bfloat162float(__float2bfloat16(v3));
        size_t o0 = (size_t)row0 * HID + col;
        size_t o1 = (size_t)(row0 + 8) * HID + col;
        *(uint32_t*)(oh + o0) = pack_bf16x2(h0, h1);
        *(uint32_t*)(oh + o1) = pack_bf16x2(h2, h3);
        *(uint32_t*)(ol + o0) = pack_bf16x2(v0 - h0, v1 - h1);
        *(uint32_t*)(ol + o1) = pack_bf16x2(v2 - h2, v3 - h3);
    }
}

// ---------------------------------------------------------------------------
// Launch
// ---------------------------------------------------------------------------
extern "C" void kernel_launch(void* const* d_in, const int* in_sizes, int n_in,
                              void* d_out, int out_size)
{
    const int*   positions = (const int*)d_in[0];
    const float* hidden    = (const float*)d_in[1];
    const float* w_qkv     = (const float*)d_in[2];
    const float* w_o       = (const float*)d_in[3];
    const float* q_norm_w  = (const float*)d_in[4];
    const float* k_norm_w  = (const float*)d_in[5];
    float*       out       = (float*)d_out;

    float* qkv_ptr = nullptr;
    __nv_bfloat16 *ah, *al, *bh, *bl, *qsh, *qsl, *ksh, *ksl, *vsh, *vsl;
    cudaGetSymbolAddress((void**)&qkv_ptr, g_qkv);
    cudaGetSymbolAddress((void**)&ah, g_ah);
    cudaGetSymbolAddress((void**)&al, g_al);
    cudaGetSymbolAddress((void**)&bh, g_bh);
    cudaGetSymbolAddress((void**)&bl, g_bl);
    cudaGetSymbolAddress((void**)&qsh, g_qsh);
    cudaGetSymbolAddress((void**)&qsl, g_qsl);
    cudaGetSymbolAddress((void**)&ksh, g_ksh);
    cudaGetSymbolAddress((void**)&ksl, g_ksl);
    cudaGetSymbolAddress((void**)&vsh, g_vsh);
    cudaGetSymbolAddress((void**)&vsl, g_vsl);

    // 1. Split hidden; transpose+split w_qkv.
    {
        int n = TT * HID;
        split_kernel<<<n / 4 / 256, 256>>>(hidden, ah, al, n);
        dim3 tg(QKVW / 32, HID / 32);
        transpose_split_kernel<<<tg, dim3(32, 8)>>>(w_qkv, bh, bl, HID, QKVW);
    }

    // 2. QKV projection via mma.sync bf16x3.
    {
        dim3 grid(QKVW / 128, TT / 128);
        gemm_mma_kernel<<<grid, 256>>>(TT, QKVW, HID, ah, al, bh, bl, qkv_ptr);
    }

    // 3. RMSNorm + RoPE + split to bf16 hi/lo (q scaled; v plain split).
    {
        norm_rope_split_kernel<<<TT * 32 / 8, 256>>>(
            positions, q_norm_w, k_norm_w, qkv_ptr,
            qsh, qsl, ksh, ksl, vsh, vsl);
    }

    // 4. transpose+split w_o (bh/bl free after QKV GEMM)
    {
        dim3 tg(HID / 32, (NH * DH) / 32);
        transpose_split_kernel<<<tg, dim3(32, 8)>>>(w_o, bh, bl, NH * DH, HID);
    }

    // 5. Causal GQA flash attention (pre-split bf16, cp.async pipeline),
    //    writes split bf16 hi/lo into ah/al.
    {
        static_assert(sizeof(AttnSmem) <= 227 * 1024, "smem");
        cudaFuncSetAttribute(attn_kernel,
                             cudaFuncAttributeMaxDynamicSharedMemorySize,
                             (int)sizeof(AttnSmem));
        dim3 grid(NH, TT / AT_BM);
        attn_kernel<<<grid, 256, sizeof(AttnSmem)>>>(
            qsh, qsl, ksh, ksl, vsh, vsl, ah, al);
    }

    // 6. Output projection via mma.sync bf16x3.
    {
        dim3 grid(HID / 128, TT / 128);
        gemm_mma_kernel<<<grid, 256>>>(TT, HID, NH * DH, ah, al, bh, bl, out);
    }
}

// round 8
// speedup vs baseline: 2.7338x; 1.1066x over previous
#include <cuda_runtime.h>
#include <cuda_bf16.h>
#include <math.h>
#include <math_constants.h>
#include <stdint.h>

// Problem constants
#define TT   2048
#define HID  2048
#define NH   16
#define NKV  8
#define DH   128
#define QKVW ((NH + 2 * NKV) * DH)   // 4096
#define QW   (NH * DH)               // 2048
#define KVW  (NKV * DH)              // 1024
#define EPS  1e-6f

// Scratch (allocation-free rule: __device__ globals)
__device__ float g_qkv[(size_t)TT * QKVW];           // fp32 qkv (GEMM out)
__device__ __nv_bfloat16 g_ah[(size_t)TT * HID];     // GEMM A hi / attn-out hi
__device__ __nv_bfloat16 g_al[(size_t)TT * HID];     // GEMM A lo / attn-out lo
__device__ __nv_bfloat16 g_bh[(size_t)QKVW * HID];   // B^T hi ([N,K])
__device__ __nv_bfloat16 g_bl[(size_t)QKVW * HID];   // B^T lo
__device__ __nv_bfloat16 g_qsh[(size_t)TT * QW],  g_qsl[(size_t)TT * QW];   // split Q (scaled)
__device__ __nv_bfloat16 g_ksh[(size_t)TT * KVW], g_ksl[(size_t)TT * KVW];  // split K
__device__ __nv_bfloat16 g_vsh[(size_t)TT * KVW], g_vsl[(size_t)TT * KVW];  // split V

// ---------------------------------------------------------------------------
// PTX helpers (base sm_103 target — HMMA mma.sync + ldmatrix + cp.async)
// ---------------------------------------------------------------------------
__device__ __forceinline__ void mma16816(float d[4],
                                         uint32_t a0, uint32_t a1, uint32_t a2, uint32_t a3,
                                         uint32_t b0, uint32_t b1)
{
    asm volatile(
        "mma.sync.aligned.m16n8k16.row.col.f32.bf16.bf16.f32 "
        "{%0,%1,%2,%3}, {%4,%5,%6,%7}, {%8,%9}, {%0,%1,%2,%3};\n"
        : "+f"(d[0]), "+f"(d[1]), "+f"(d[2]), "+f"(d[3])
        : "r"(a0), "r"(a1), "r"(a2), "r"(a3), "r"(b0), "r"(b1));
}

__device__ __forceinline__ void ldsm_x4(uint32_t& r0, uint32_t& r1,
                                        uint32_t& r2, uint32_t& r3, uint32_t addr)
{
    asm volatile("ldmatrix.sync.aligned.m8n8.x4.shared.b16 {%0,%1,%2,%3}, [%4];"
                 : "=r"(r0), "=r"(r1), "=r"(r2), "=r"(r3) : "r"(addr));
}

__device__ __forceinline__ void ldsm_x4_t(uint32_t& r0, uint32_t& r1,
                                          uint32_t& r2, uint32_t& r3, uint32_t addr)
{
    asm volatile("ldmatrix.sync.aligned.m8n8.x4.trans.shared.b16 {%0,%1,%2,%3}, [%4];"
                 : "=r"(r0), "=r"(r1), "=r"(r2), "=r"(r3) : "r"(addr));
}

__device__ __forceinline__ uint32_t su32(const void* p) {
    return (uint32_t)__cvta_generic_to_shared(p);
}

__device__ __forceinline__ uint32_t pack_bf16x2(float a, float b) {
    __nv_bfloat162 t = __floats2bfloat162_rn(a, b);
    return *(uint32_t*)&t;
}

__device__ __forceinline__ void cp_async16(uint32_t dst, const void* src) {
    asm volatile("cp.async.cg.shared.global [%0], [%1], 16;" :: "r"(dst), "l"(src));
}
__device__ __forceinline__ void cp_commit() {
    asm volatile("cp.async.commit_group;" ::: "memory");
}
template <int N>
__device__ __forceinline__ void cp_wait() {
    asm volatile("cp.async.wait_group %0;" :: "n"(N) : "memory");
}

// hi/lo split of a float4, stored as 2x bf162 each
__device__ __forceinline__ void split4_store(float4 v, __nv_bfloat16* hp, __nv_bfloat16* lp) {
    __nv_bfloat16 h0 = __float2bfloat16(v.x), h1 = __float2bfloat16(v.y);
    __nv_bfloat16 h2 = __float2bfloat16(v.z), h3 = __float2bfloat16(v.w);
    *(uint32_t*)(hp)     = pack_bf16x2(__bfloat162float(h0), __bfloat162float(h1));
    *(uint32_t*)(hp + 2) = pack_bf16x2(__bfloat162float(h2), __bfloat162float(h3));
    *(uint32_t*)(lp)     = pack_bf16x2(v.x - __bfloat162float(h0), v.y - __bfloat162float(h1));
    *(uint32_t*)(lp + 2) = pack_bf16x2(v.z - __bfloat162float(h2), v.w - __bfloat162float(h3));
}

// ---------------------------------------------------------------------------
// Split conversion: fp32 -> (hi, lo) bf16, same layout. n % 4 == 0.
// ---------------------------------------------------------------------------
__global__ __launch_bounds__(256) void split_kernel(
    const float* __restrict__ x,
    __nv_bfloat16* __restrict__ hi, __nv_bfloat16* __restrict__ lo, int n)
{
    int i = (blockIdx.x * blockDim.x + threadIdx.x) * 4;
    if (i >= n) return;
    float4 v = *(const float4*)(x + i);
    split4_store(v, hi + i, lo + i);
}

// ---------------------------------------------------------------------------
// Transpose + split: W[K,N] fp32 -> Th/Tl [N,K] bf16. K,N % 32 == 0.
// ---------------------------------------------------------------------------
__global__ __launch_bounds__(256) void transpose_split_kernel(
    const float* __restrict__ W,
    __nv_bfloat16* __restrict__ Th, __nv_bfloat16* __restrict__ Tl,
    int K, int N)
{
    __shared__ float tile[32][33];
    const int bn = blockIdx.x * 32;
    const int bk = blockIdx.y * 32;
    const int tx = threadIdx.x;
    const int ty = threadIdx.y;
#pragma unroll
    for (int j = 0; j < 32; j += 8)
        tile[ty + j][tx] = W[(size_t)(bk + ty + j) * N + bn + tx];
    __syncthreads();
#pragma unroll
    for (int j = 0; j < 32; j += 8) {
        float v = tile[tx][ty + j];
        __nv_bfloat16 h = __float2bfloat16(v);
        __nv_bfloat16 l = __float2bfloat16(v - __bfloat162float(h));
        size_t o = (size_t)(bn + ty + j) * K + bk + tx;
        Th[o] = h;
        Tl[o] = l;
    }
}

// ---------------------------------------------------------------------------
// mma.sync bf16x3 GEMM: C[M,N] = A[M,K] @ B[K,N]; ldmatrix fragment loads.
// ---------------------------------------------------------------------------
#define GPITCH 40   // 80B rows

__global__ __launch_bounds__(256) void gemm_mma_kernel(
    int M, int N, int K,
    const __nv_bfloat16* __restrict__ Ah, const __nv_bfloat16* __restrict__ Al,
    const __nv_bfloat16* __restrict__ Bh, const __nv_bfloat16* __restrict__ Bl,
    float* __restrict__ C)
{
    __shared__ __nv_bfloat16 sAh[128 * GPITCH], sAl[128 * GPITCH];
    __shared__ __nv_bfloat16 sBh[128 * GPITCH], sBl[128 * GPITCH];

    const int tid  = threadIdx.x;
    const int lane = tid & 31;
    const int wid  = tid >> 5;
    const int wm   = wid >> 2;
    const int wn   = wid & 3;
    const int gq   = lane >> 2;
    const int tg   = lane & 3;
    const int bm = blockIdx.y * 128;
    const int bn = blockIdx.x * 128;

    const int r0g = tid >> 2, q0 = tid & 3;
    const int r1g = (tid + 256) >> 2, q1 = (tid + 256) & 3;

    // ldmatrix lane offsets (bytes), pitch 80B
    const uint32_t a_off = (uint32_t)((lane & 15) * 80 + (lane & 16));
    const uint32_t b_off = (uint32_t)(((lane & 7) + ((lane >> 4) << 3)) * 80 + (((lane >> 3) & 1) << 4));
    const uint32_t uAh = su32(sAh), uAl = su32(sAl);
    const uint32_t uBh = su32(sBh), uBl = su32(sBl);

    float acc[4][4][4];
#pragma unroll
    for (int a = 0; a < 4; a++)
#pragma unroll
        for (int b = 0; b < 4; b++)
#pragma unroll
            for (int c = 0; c < 4; c++) acc[a][b][c] = 0.f;

    const int nch = K / 32;
    uint4 pA0, pA1, pAl0, pAl1, pB0, pB1, pBl0, pBl1;
    {
        pA0  = *(const uint4*)(Ah + (size_t)(bm + r0g) * K + q0 * 8);
        pA1  = *(const uint4*)(Ah + (size_t)(bm + r1g) * K + q1 * 8);
        pAl0 = *(const uint4*)(Al + (size_t)(bm + r0g) * K + q0 * 8);
        pAl1 = *(const uint4*)(Al + (size_t)(bm + r1g) * K + q1 * 8);
        pB0  = *(const uint4*)(Bh + (size_t)(bn + r0g) * K + q0 * 8);
        pB1  = *(const uint4*)(Bh + (size_t)(bn + r1g) * K + q1 * 8);
        pBl0 = *(const uint4*)(Bl + (size_t)(bn + r0g) * K + q0 * 8);
        pBl1 = *(const uint4*)(Bl + (size_t)(bn + r1g) * K + q1 * 8);
    }

    for (int c = 0; c < nch; c++) {
        __syncthreads();
        *(uint4*)&sAh[r0g * GPITCH + q0 * 8] = pA0;
        *(uint4*)&sAh[r1g * GPITCH + q1 * 8] = pA1;
        *(uint4*)&sAl[r0g * GPITCH + q0 * 8] = pAl0;
        *(uint4*)&sAl[r1g * GPITCH + q1 * 8] = pAl1;
        *(uint4*)&sBh[r0g * GPITCH + q0 * 8] = pB0;
        *(uint4*)&sBh[r1g * GPITCH + q1 * 8] = pB1;
        *(uint4*)&sBl[r0g * GPITCH + q0 * 8] = pBl0;
        *(uint4*)&sBl[r1g * GPITCH + q1 * 8] = pBl1;
        __syncthreads();

        if (c + 1 < nch) {
            const int k0 = (c + 1) * 32;
            pA0  = *(const uint4*)(Ah + (size_t)(bm + r0g) * K + k0 + q0 * 8);
            pA1  = *(const uint4*)(Ah + (size_t)(bm + r1g) * K + k0 + q1 * 8);
            pAl0 = *(const uint4*)(Al + (size_t)(bm + r0g) * K + k0 + q0 * 8);
            pAl1 = *(const uint4*)(Al + (size_t)(bm + r1g) * K + k0 + q1 * 8);
            pB0  = *(const uint4*)(Bh + (size_t)(bn + r0g) * K + k0 + q0 * 8);
            pB1  = *(const uint4*)(Bh + (size_t)(bn + r1g) * K + k0 + q1 * 8);
            pBl0 = *(const uint4*)(Bl + (size_t)(bn + r0g) * K + k0 + q0 * 8);
            pBl1 = *(const uint4*)(Bl + (size_t)(bn + r1g) * K + k0 + q1 * 8);
        }

#pragma unroll
        for (int ks = 0; ks < 2; ks++) {
            const uint32_t kb = (uint32_t)(ks * 32);   // bytes
            uint32_t ah[4][4], al[4][4], bh[4][2], bl[4][2];
#pragma unroll
            for (int mt = 0; mt < 4; mt++) {
                uint32_t base = (uint32_t)((wm * 64 + mt * 16) * 80) + kb;
                ldsm_x4(ah[mt][0], ah[mt][1], ah[mt][2], ah[mt][3], uAh + base + a_off);
                ldsm_x4(al[mt][0], al[mt][1], al[mt][2], al[mt][3], uAl + base + a_off);
            }
#pragma unroll
            for (int ntp = 0; ntp < 2; ntp++) {
                uint32_t base = (uint32_t)((wn * 32 + ntp * 16) * 80) + kb;
                ldsm_x4(bh[2 * ntp][0], bh[2 * ntp][1], bh[2 * ntp + 1][0], bh[2 * ntp + 1][1],
                        uBh + base + b_off);
                ldsm_x4(bl[2 * ntp][0], bl[2 * ntp][1], bl[2 * ntp + 1][0], bl[2 * ntp + 1][1],
                        uBl + base + b_off);
            }
#pragma unroll
            for (int mt = 0; mt < 4; mt++)
#pragma unroll
                for (int nt = 0; nt < 4; nt++) {
                    mma16816(acc[mt][nt], ah[mt][0], ah[mt][1], ah[mt][2], ah[mt][3],
                             bh[nt][0], bh[nt][1]);
                    mma16816(acc[mt][nt], ah[mt][0], ah[mt][1], ah[mt][2], ah[mt][3],
                             bl[nt][0], bl[nt][1]);
                    mma16816(acc[mt][nt], al[mt][0], al[mt][1], al[mt][2], al[mt][3],
                             bh[nt][0], bh[nt][1]);
                }
        }
    }

#pragma unroll
    for (int mt = 0; mt < 4; mt++) {
        int row = bm + wm * 64 + mt * 16 + gq;
#pragma unroll
        for (int nt = 0; nt < 4; nt++) {
            int col = bn + wn * 32 + nt * 8 + 2 * tg;
            *(float2*)(C + (size_t)row * N + col) =
                make_float2(acc[mt][nt][0], acc[mt][nt][1]);
            *(float2*)(C + (size_t)(row + 8) * N + col) =
                make_float2(acc[mt][nt][2], acc[mt][nt][3]);
        }
    }
}

// ---------------------------------------------------------------------------
// RMSNorm + RoPE + hi/lo split. One warp per (t, slot), 32 slots.
// ---------------------------------------------------------------------------
__global__ __launch_bounds__(256) void norm_rope_split_kernel(
    const int* __restrict__ positions,
    const float* __restrict__ qw, const float* __restrict__ kw,
    const float* __restrict__ qkv,
    __nv_bfloat16* __restrict__ qsh, __nv_bfloat16* __restrict__ qsl,
    __nv_bfloat16* __restrict__ ksh, __nv_bfloat16* __restrict__ ksl,
    __nv_bfloat16* __restrict__ vsh, __nv_bfloat16* __restrict__ vsl)
{
    const int gw   = blockIdx.x * 8 + (threadIdx.x >> 5);
    const int lane = threadIdx.x & 31;
    const int t    = gw >> 5;
    const int slot = gw & 31;

    if (slot >= 24) {
        const int vh = slot - 24;
        float4 v = ((const float4*)(qkv + (size_t)t * QKVW + (NH + NKV) * DH + vh * DH))[lane];
        size_t o = (size_t)t * KVW + vh * DH + lane * 4;
        split4_store(v, vsh + o, vsl + o);
        return;
    }

    const bool isq = (slot < NH);
    const float* ptr = qkv + (size_t)t * QKVW + slot * DH;
    const float* w = isq ? qw : kw;

    float4 x = ((const float4*)ptr)[lane];
    float ss = x.x * x.x + x.y * x.y + x.z * x.z + x.w * x.w;
#pragma unroll
    for (int o = 16; o > 0; o >>= 1) ss += __shfl_xor_sync(0xffffffffu, ss, o);
    float rinv = rsqrtf(ss * (1.f / DH) + EPS);

    float4 wv = ((const float4*)w)[lane];
    float4 xn = make_float4(x.x * rinv * wv.x, x.y * rinv * wv.y,
                            x.z * rinv * wv.z, x.w * rinv * wv.w);

    float4 other;
    other.x = __shfl_xor_sync(0xffffffffu, xn.x, 16);
    other.y = __shfl_xor_sync(0xffffffffu, xn.y, 16);
    other.z = __shfl_xor_sync(0xffffffffu, xn.z, 16);
    other.w = __shfl_xor_sync(0xffffffffu, xn.w, 16);

    const float pos = (float)positions[t];
    const int j = (lane & 15) * 4;
    float4 outv;
    float* xo = (float*)&outv;
    const float* x1 = (lane < 16) ? (const float*)&xn : (const float*)&other;
    const float* x2 = (lane < 16) ? (const float*)&other : (const float*)&xn;
#pragma unroll
    for (int c = 0; c < 4; c++) {
        float inv_freq = powf(10000.f, -(float)(j + c) * (1.f / 64.f));
        float sv, cv;
        sincosf(pos * inv_freq, &sv, &cv);
        xo[c] = (lane < 16) ? (x1[c] * cv - x2[c] * sv)
                            : (x2[c] * cv + x1[c] * sv);
    }

    if (isq) {
        const float scale = 0.08838834764831845f;  // 1/sqrt(128)
        outv.x *= scale; outv.y *= scale; outv.z *= scale; outv.w *= scale;
        size_t o = (size_t)t * QW + slot * DH + lane * 4;
        split4_store(outv, qsh + o, qsl + o);
    } else {
        size_t o = (size_t)t * KVW + (slot - NH) * DH + lane * 4;
        split4_store(outv, ksh + o, ksl + o);
    }
}

// ---------------------------------------------------------------------------
// FA2-style causal GQA attention, bf16x3 mma, in-register softmax,
// cp.async double-buffered K/V, ldmatrix fragment loads everywhere.
// ---------------------------------------------------------------------------
#define AT_BM 128
#define AT_BN 64
#define QP 136      // smem pitch (bf16): 272B rows

struct AttnSmem {
    __nv_bfloat16 Qh[AT_BM * QP], Ql[AT_BM * QP];
    __nv_bfloat16 Kh[2][AT_BN * QP], Kl[2][AT_BN * QP];
    __nv_bfloat16 Vh[2][AT_BN * QP], Vl[2][AT_BN * QP];
};

__global__ __launch_bounds__(256, 1) void attn_kernel(
    const __nv_bfloat16* __restrict__ qsh, const __nv_bfloat16* __restrict__ qsl,
    const __nv_bfloat16* __restrict__ ksh, const __nv_bfloat16* __restrict__ ksl,
    const __nv_bfloat16* __restrict__ vsh, const __nv_bfloat16* __restrict__ vsl,
    __nv_bfloat16* __restrict__ oh, __nv_bfloat16* __restrict__ ol)
{
    extern __shared__ char smem_raw[];
    AttnSmem& s = *(AttnSmem*)smem_raw;

    const int h   = blockIdx.x;
    const int m0  = (gridDim.y - 1 - blockIdx.y) * AT_BM;  // heavy blocks first
    const int kvh = h >> 1;
    const int tid = threadIdx.x;
    const int lane = tid & 31;
    const int w    = tid >> 5;
    const int gq   = lane >> 2;
    const int tg   = lane & 3;

    // Q tile: direct bf16 loads (once per CTA)
    for (int u = tid; u < AT_BM * 16; u += 256) {
        int row = u >> 4;
        int c   = u & 15;
        size_t go = (size_t)(m0 + row) * QW + h * DH + c * 8;
        *(uint4*)((char*)s.Qh + row * 272 + c * 16) = *(const uint4*)(qsh + go);
        *(uint4*)((char*)s.Ql + row * 272 + c * 16) = *(const uint4*)(qsl + go);
    }

    const uint32_t uQh = su32(s.Qh), uQl = su32(s.Ql);
    const uint32_t uKh[2] = { su32(s.Kh[0]), su32(s.Kh[1]) };
    const uint32_t uKl[2] = { su32(s.Kl[0]), su32(s.Kl[1]) };
    const uint32_t uVh[2] = { su32(s.Vh[0]), su32(s.Vh[1]) };
    const uint32_t uVl[2] = { su32(s.Vl[0]), su32(s.Vl[1]) };

    // ldmatrix lane offsets (bytes), pitch 272B
    const uint32_t a_off = (uint32_t)((lane & 15) * 272 + (lane & 16));
    const uint32_t b_off = (uint32_t)(((lane & 7) + ((lane >> 4) << 3)) * 272 + (((lane >> 3) & 1) << 4));
    const uint32_t vlane_off = (uint32_t)((lane & 15) * 272 + ((lane >> 4) << 4));

    // cp.async prefetch of one 64-key tile into buffer b
    auto prefetch = [&](int n0, int b) {
#pragma unroll
        for (int i = 0; i < 4; i++) {
            int u = tid + i * 256;
            int row = u >> 4;
            int c   = u & 15;
            uint32_t so = (uint32_t)(row * 272 + c * 16);
            size_t go = (size_t)(n0 + row) * KVW + kvh * DH + c * 8;
            cp_async16(uKh[b] + so, ksh + go);
            cp_async16(uKl[b] + so, ksl + go);
            cp_async16(uVh[b] + so, vsh + go);
            cp_async16(uVl[b] + so, vsl + go);
        }
    };

    float m_[2] = { -CUDART_INF_F, -CUDART_INF_F };
    float l_[2] = { 0.f, 0.f };

    float accO[16][4];
#pragma unroll
    for (int a = 0; a < 16; a++)
#pragma unroll
        for (int c = 0; c < 4; c++) accO[a][c] = 0.f;

    const int row0 = m0 + w * 16 + gq;
    const int n_tiles = (m0 + AT_BM) / AT_BN;

    prefetch(0, 0);
    cp_commit();

    for (int tile = 0; tile < n_tiles; tile++) {
        const int n0 = tile * AT_BN;
        const int b  = tile & 1;

        if (tile + 1 < n_tiles) {
            prefetch(n0 + AT_BN, b ^ 1);
            cp_commit();
            cp_wait<1>();
        } else {
            cp_wait<0>();
        }
        __syncthreads();

        const uint32_t kh = uKh[b], kl = uKl[b];
        const uint32_t svh = uVh[b], svl = uVl[b];

        // ---- S = Q @ K^T (bf16x3), warp tile 16x64, ldmatrix frags ----
        float accS[8][4];
#pragma unroll
        for (int bb = 0; bb < 8; bb++)
#pragma unroll
            for (int c = 0; c < 4; c++) accS[bb][c] = 0.f;

#pragma unroll
        for (int ks = 0; ks < 8; ks++) {
            const uint32_t kb = (uint32_t)(ks * 32);   // bytes
            const uint32_t qbase = (uint32_t)(w * 16 * 272) + kb;
            uint32_t qh0, qh1, qh2, qh3, ql0, ql1, ql2, ql3;
            ldsm_x4(qh0, qh1, qh2, qh3, uQh + qbase + a_off);
            ldsm_x4(ql0, ql1, ql2, ql3, uQl + qbase + a_off);
#pragma unroll
            for (int ntp = 0; ntp < 4; ntp++) {
                uint32_t base = (uint32_t)(ntp * 16 * 272) + kb + b_off;
                uint32_t bh0, bh1, bh2, bh3, bl0, bl1, bl2, bl3;
                ldsm_x4(bh0, bh1, bh2, bh3, kh + base);
                ldsm_x4(bl0, bl1, bl2, bl3, kl + base);
                mma16816(accS[2 * ntp],     qh0, qh1, qh2, qh3, bh0, bh1);
                mma16816(accS[2 * ntp],     qh0, qh1, qh2, qh3, bl0, bl1);
                mma16816(accS[2 * ntp],     ql0, ql1, ql2, ql3, bh0, bh1);
                mma16816(accS[2 * ntp + 1], qh0, qh1, qh2, qh3, bh2, bh3);
                mma16816(accS[2 * ntp + 1], qh0, qh1, qh2, qh3, bl2, bl3);
                mma16816(accS[2 * ntp + 1], ql0, ql1, ql2, ql3, bh2, bh3);
            }
        }

        // ---- causal mask ----
        if (n0 + AT_BN - 1 > m0) {
#pragma unroll
            for (int nt = 0; nt < 8; nt++) {
                int c0 = n0 + nt * 8 + 2 * tg;
                if (c0     > row0)     accS[nt][0] = -CUDART_INF_F;
                if (c0 + 1 > row0)     accS[nt][1] = -CUDART_INF_F;
                if (c0     > row0 + 8) accS[nt][2] = -CUDART_INF_F;
                if (c0 + 1 > row0 + 8) accS[nt][3] = -CUDART_INF_F;
            }
        }

        // ---- in-register online softmax ----
        float mx0 = accS[0][0], mx1 = accS[0][2];
#pragma unroll
        for (int nt = 0; nt < 8; nt++) {
            mx0 = fmaxf(mx0, fmaxf(accS[nt][0], accS[nt][1]));
            mx1 = fmaxf(mx1, fmaxf(accS[nt][2], accS[nt][3]));
        }
        mx0 = fmaxf(mx0, __shfl_xor_sync(0xffffffffu, mx0, 1));
        mx0 = fmaxf(mx0, __shfl_xor_sync(0xffffffffu, mx0, 2));
        mx1 = fmaxf(mx1, __shfl_xor_sync(0xffffffffu, mx1, 1));
        mx1 = fmaxf(mx1, __shfl_xor_sync(0xffffffffu, mx1, 2));

        float mn0 = fmaxf(m_[0], mx0);
        float mn1 = fmaxf(m_[1], mx1);
        float corr0 = __expf(m_[0] - mn0);
        float corr1 = __expf(m_[1] - mn1);
        float sum0 = 0.f, sum1 = 0.f;
#pragma unroll
        for (int nt = 0; nt < 8; nt++) {
            accS[nt][0] = __expf(accS[nt][0] - mn0);
            accS[nt][1] = __expf(accS[nt][1] - mn0);
            accS[nt][2] = __expf(accS[nt][2] - mn1);
            accS[nt][3] = __expf(accS[nt][3] - mn1);
            sum0 += accS[nt][0] + accS[nt][1];
            sum1 += accS[nt][2] + accS[nt][3];
        }
        sum0 += __shfl_xor_sync(0xffffffffu, sum0, 1);
        sum0 += __shfl_xor_sync(0xffffffffu, sum0, 2);
        sum1 += __shfl_xor_sync(0xffffffffu, sum1, 1);
        sum1 += __shfl_xor_sync(0xffffffffu, sum1, 2);
        l_[0] = l_[0] * corr0 + sum0;
        l_[1] = l_[1] * corr1 + sum1;
        m_[0] = mn0; m_[1] = mn1;

#pragma unroll
        for (int nt = 0; nt < 16; nt++) {
            accO[nt][0] *= corr0; accO[nt][1] *= corr0;
            accO[nt][2] *= corr1; accO[nt][3] *= corr1;
        }

        // ---- O += P @ V (bf16x3), warp tile 16x128, k=64 ----
#pragma unroll
        for (int kc = 0; kc < 4; kc++) {
            float p00 = accS[2 * kc][0],     p01 = accS[2 * kc][1];
            float p10 = accS[2 * kc][2],     p11 = accS[2 * kc][3];
            float p20 = accS[2 * kc + 1][0], p21 = accS[2 * kc + 1][1];
            float p30 = accS[2 * kc + 1][2], p31 = accS[2 * kc + 1][3];
            float h00 = __bfloat162float(__float2bfloat16(p00));
            float h01 = __bfloat162float(__float2bfloat16(p01));
            float h10 = __bfloat162float(__float2bfloat16(p10));
            float h11 = __bfloat162float(__float2bfloat16(p11));
            float h20 = __bfloat162float(__float2bfloat16(p20));
            float h21 = __bfloat162float(__float2bfloat16(p21));
            float h30 = __bfloat162float(__float2bfloat16(p30));
            float h31 = __bfloat162float(__float2bfloat16(p31));
            uint32_t ph0 = pack_bf16x2(h00, h01);
            uint32_t ph1 = pack_bf16x2(h10, h11);
            uint32_t ph2 = pack_bf16x2(h20, h21);
            uint32_t ph3 = pack_bf16x2(h30, h31);
            uint32_t pl0 = pack_bf16x2(p00 - h00, p01 - h01);
            uint32_t pl1 = pack_bf16x2(p10 - h10, p11 - h11);
            uint32_t pl2 = pack_bf16x2(p20 - h20, p21 - h21);
            uint32_t pl3 = pack_bf16x2(p30 - h30, p31 - h31);

#pragma unroll
            for (int ncg = 0; ncg < 8; ncg++) {
                uint32_t base_off = (uint32_t)(kc * 16 * 272 + ncg * 32) + vlane_off;
                uint32_t vh0, vh1, vh2, vh3, vl0, vl1, vl2, vl3;
                ldsm_x4_t(vh0, vh1, vh2, vh3, svh + base_off);
                ldsm_x4_t(vl0, vl1, vl2, vl3, svl + base_off);
                mma16816(accO[ncg * 2],     ph0, ph1, ph2, ph3, vh0, vh1);
                mma16816(accO[ncg * 2],     ph0, ph1, ph2, ph3, vl0, vl1);
                mma16816(accO[ncg * 2],     pl0, pl1, pl2, pl3, vh0, vh1);
                mma16816(accO[ncg * 2 + 1], ph0, ph1, ph2, ph3, vh2, vh3);
                mma16816(accO[ncg * 2 + 1], ph0, ph1, ph2, ph3, vl2, vl3);
                mma16816(accO[ncg * 2 + 1], pl0, pl1, pl2, pl3, vh2, vh3);
            }
        }
        __syncthreads();
    }

    // ---- normalize + split-write bf16 hi/lo ----
    float i0 = 1.f / l_[0];
    float i1 = 1.f / l_[1];
#pragma unroll
    for (int nt = 0; nt < 16; nt++) {
        int col = h * DH + nt * 8 + 2 * tg;
        float v0 = accO[nt][0] * i0, v1 = accO[nt][1] * i0;
        float v2 = accO[nt][2] * i1, v3 = accO[nt][3] * i1;
        float h0 = __bfloat162float(__float2bfloat16(v0));
        float h1 = __bfloat162float(__float2bfloat16(v1));
        float h2 = __bfloat162float(__float2bfloat16(v2));
        float h3 = __bfloat162float(__float2bfloat16(v3));
        size_t o0 = (size_t)row0 * HID + col;
        size_t o1 = (size_t)(row0 + 8) * HID + col;
        *(uint32_t*)(oh + o0) = pack_bf16x2(h0, h1);
        *(uint32_t*)(oh + o1) = pack_bf16x2(h2, h3);
        *(uint32_t*)(ol + o0) = pack_bf16x2(v0 - h0, v1 - h1);
        *(uint32_t*)(ol + o1) = pack_bf16x2(v2 - h2, v3 - h3);
    }
}

// ---------------------------------------------------------------------------
// Launch
// ---------------------------------------------------------------------------
extern "C" void kernel_launch(void* const* d_in, const int* in_sizes, int n_in,
                              void* d_out, int out_size)
{
    const int*   positions = (const int*)d_in[0];
    const float* hidden    = (const float*)d_in[1];
    const float* w_qkv     = (const float*)d_in[2];
    const float* w_o       = (const float*)d_in[3];
    const float* q_norm_w  = (const float*)d_in[4];
    const float* k_norm_w  = (const float*)d_in[5];
    float*       out       = (float*)d_out;

    float* qkv_ptr = nullptr;
    __nv_bfloat16 *ah, *al, *bh, *bl, *qsh, *qsl, *ksh, *ksl, *vsh, *vsl;
    cudaGetSymbolAddress((void**)&qkv_ptr, g_qkv);
    cudaGetSymbolAddress((void**)&ah, g_ah);
    cudaGetSymbolAddress((void**)&al, g_al);
    cudaGetSymbolAddress((void**)&bh, g_bh);
    cudaGetSymbolAddress((void**)&bl, g_bl);
    cudaGetSymbolAddress((void**)&qsh, g_qsh);
    cudaGetSymbolAddress((void**)&qsl, g_qsl);
    cudaGetSymbolAddress((void**)&ksh, g_ksh);
    cudaGetSymbolAddress((void**)&ksl, g_ksl);
    cudaGetSymbolAddress((void**)&vsh, g_vsh);
    cudaGetSymbolAddress((void**)&vsl, g_vsl);

    // 1. Split hidden; transpose+split w_qkv.
    {
        int n = TT * HID;
        split_kernel<<<n / 4 / 256, 256>>>(hidden, ah, al, n);
        dim3 tg(QKVW / 32, HID / 32);
        transpose_split_kernel<<<tg, dim3(32, 8)>>>(w_qkv, bh, bl, HID, QKVW);
    }

    // 2. QKV projection via mma.sync bf16x3.
    {
        dim3 grid(QKVW / 128, TT / 128);
        gemm_mma_kernel<<<grid, 256>>>(TT, QKVW, HID, ah, al, bh, bl, qkv_ptr);
    }

    // 3. RMSNorm + RoPE + split to bf16 hi/lo (q scaled; v plain split).
    {
        norm_rope_split_kernel<<<TT * 32 / 8, 256>>>(
            positions, q_norm_w, k_norm_w, qkv_ptr,
            qsh, qsl, ksh, ksl, vsh, vsl);
    }

    // 4. transpose+split w_o (bh/bl free after QKV GEMM)
    {
        dim3 tg(HID / 32, (NH * DH) / 32);
        transpose_split_kernel<<<tg, dim3(32, 8)>>>(w_o, bh, bl, NH * DH, HID);
    }

    // 5. Causal GQA flash attention (pre-split bf16, cp.async + ldmatrix),
    //    writes split bf16 hi/lo into ah/al.
    {
        static_assert(sizeof(AttnSmem) <= 227 * 1024, "smem");
        cudaFuncSetAttribute(attn_kernel,
                             cudaFuncAttributeMaxDynamicSharedMemorySize,
                             (int)sizeof(AttnSmem));
        dim3 grid(NH, TT / AT_BM);
        attn_kernel<<<grid, 256, sizeof(AttnSmem)>>>(
            qsh, qsl, ksh, ksl, vsh, vsl, ah, al);
    }

    // 6. Output projection via mma.sync bf16x3.
    {
        dim3 grid(HID / 128, TT / 128);
        gemm_mma_kernel<<<grid, 256>>>(TT, HID, NH * DH, ah, al, bh, bl, out);
    }
}

// round 9
// speedup vs baseline: 2.8294x; 1.0350x over previous
#include <cuda_runtime.h>
#include <cuda_bf16.h>
#include <math.h>
#include <math_constants.h>
#include <stdint.h>

// Problem constants
#define TT   2048
#define HID  2048
#define NH   16
#define NKV  8
#define DH   128
#define QKVW ((NH + 2 * NKV) * DH)   // 4096
#define QW   (NH * DH)               // 2048
#define KVW  (NKV * DH)              // 1024
#define EPS  1e-6f

// Scratch (allocation-free rule: __device__ globals)
__device__ float g_qkv[(size_t)TT * QKVW];           // fp32 qkv (GEMM out)
__device__ __nv_bfloat16 g_ah[(size_t)TT * HID];     // GEMM A hi / attn-out hi
__device__ __nv_bfloat16 g_al[(size_t)TT * HID];     // GEMM A lo / attn-out lo
__device__ __nv_bfloat16 g_bh[(size_t)QKVW * HID];   // B^T hi ([N,K])
__device__ __nv_bfloat16 g_bl[(size_t)QKVW * HID];   // B^T lo
__device__ __nv_bfloat16 g_qsh[(size_t)TT * QW],  g_qsl[(size_t)TT * QW];   // split Q (scaled)
__device__ __nv_bfloat16 g_ksh[(size_t)TT * KVW], g_ksl[(size_t)TT * KVW];  // split K
__device__ __nv_bfloat16 g_vsh[(size_t)TT * KVW], g_vsl[(size_t)TT * KVW];  // split V

// ---------------------------------------------------------------------------
// PTX helpers (base sm_103 target — HMMA mma.sync + ldmatrix + cp.async)
// ---------------------------------------------------------------------------
__device__ __forceinline__ void mma16816(float d[4],
                                         uint32_t a0, uint32_t a1, uint32_t a2, uint32_t a3,
                                         uint32_t b0, uint32_t b1)
{
    asm volatile(
        "mma.sync.aligned.m16n8k16.row.col.f32.bf16.bf16.f32 "
        "{%0,%1,%2,%3}, {%4,%5,%6,%7}, {%8,%9}, {%0,%1,%2,%3};\n"
        : "+f"(d[0]), "+f"(d[1]), "+f"(d[2]), "+f"(d[3])
        : "r"(a0), "r"(a1), "r"(a2), "r"(a3), "r"(b0), "r"(b1));
}

__device__ __forceinline__ void ldsm_x4(uint32_t& r0, uint32_t& r1,
                                        uint32_t& r2, uint32_t& r3, uint32_t addr)
{
    asm volatile("ldmatrix.sync.aligned.m8n8.x4.shared.b16 {%0,%1,%2,%3}, [%4];"
                 : "=r"(r0), "=r"(r1), "=r"(r2), "=r"(r3) : "r"(addr));
}

__device__ __forceinline__ void ldsm_x4_t(uint32_t& r0, uint32_t& r1,
                                          uint32_t& r2, uint32_t& r3, uint32_t addr)
{
    asm volatile("ldmatrix.sync.aligned.m8n8.x4.trans.shared.b16 {%0,%1,%2,%3}, [%4];"
                 : "=r"(r0), "=r"(r1), "=r"(r2), "=r"(r3) : "r"(addr));
}

__device__ __forceinline__ uint32_t su32(const void* p) {
    return (uint32_t)__cvta_generic_to_shared(p);
}

__device__ __forceinline__ uint32_t pack_bf16x2(float a, float b) {
    __nv_bfloat162 t = __floats2bfloat162_rn(a, b);
    return *(uint32_t*)&t;
}

__device__ __forceinline__ void cp_async16(uint32_t dst, const void* src) {
    asm volatile("cp.async.cg.shared.global [%0], [%1], 16;" :: "r"(dst), "l"(src));
}
__device__ __forceinline__ void cp_commit() {
    asm volatile("cp.async.commit_group;" ::: "memory");
}
template <int N>
__device__ __forceinline__ void cp_wait() {
    asm volatile("cp.async.wait_group %0;" :: "n"(N) : "memory");
}

// hi/lo split of a float4, stored as 2x bf162 each
__device__ __forceinline__ void split4_store(float4 v, __nv_bfloat16* hp, __nv_bfloat16* lp) {
    __nv_bfloat16 h0 = __float2bfloat16(v.x), h1 = __float2bfloat16(v.y);
    __nv_bfloat16 h2 = __float2bfloat16(v.z), h3 = __float2bfloat16(v.w);
    *(uint32_t*)(hp)     = pack_bf16x2(__bfloat162float(h0), __bfloat162float(h1));
    *(uint32_t*)(hp + 2) = pack_bf16x2(__bfloat162float(h2), __bfloat162float(h3));
    *(uint32_t*)(lp)     = pack_bf16x2(v.x - __bfloat162float(h0), v.y - __bfloat162float(h1));
    *(uint32_t*)(lp + 2) = pack_bf16x2(v.z - __bfloat162float(h2), v.w - __bfloat162float(h3));
}

// ---------------------------------------------------------------------------
// Split conversion: fp32 -> (hi, lo) bf16, same layout. n % 4 == 0.
// ---------------------------------------------------------------------------
__global__ __launch_bounds__(256) void split_kernel(
    const float* __restrict__ x,
    __nv_bfloat16* __restrict__ hi, __nv_bfloat16* __restrict__ lo, int n)
{
    int i = (blockIdx.x * blockDim.x + threadIdx.x) * 4;
    if (i >= n) return;
    float4 v = *(const float4*)(x + i);
    split4_store(v, hi + i, lo + i);
}

// ---------------------------------------------------------------------------
// Transpose + split: W[K,N] fp32 -> Th/Tl [N,K] bf16. K,N % 32 == 0.
// ---------------------------------------------------------------------------
__global__ __launch_bounds__(256) void transpose_split_kernel(
    const float* __restrict__ W,
    __nv_bfloat16* __restrict__ Th, __nv_bfloat16* __restrict__ Tl,
    int K, int N)
{
    __shared__ float tile[32][33];
    const int bn = blockIdx.x * 32;
    const int bk = blockIdx.y * 32;
    const int tx = threadIdx.x;
    const int ty = threadIdx.y;
#pragma unroll
    for (int j = 0; j < 32; j += 8)
        tile[ty + j][tx] = W[(size_t)(bk + ty + j) * N + bn + tx];
    __syncthreads();
#pragma unroll
    for (int j = 0; j < 32; j += 8) {
        float v = tile[tx][ty + j];
        __nv_bfloat16 h = __float2bfloat16(v);
        __nv_bfloat16 l = __float2bfloat16(v - __bfloat162float(h));
        size_t o = (size_t)(bn + ty + j) * K + bk + tx;
        Th[o] = h;
        Tl[o] = l;
    }
}

// ---------------------------------------------------------------------------
// mma.sync bf16x3 GEMM: cp.async double-buffered, ldmatrix frags.
// C[M,N] = A[M,K] @ B[K,N]; A [M,K] hi/lo, B transposed [N,K] hi/lo.
// CTA 128x128, 256 threads, warp tile 64x32, BK=32, 2 smem stages.
// ---------------------------------------------------------------------------
#define GPITCH 40   // 80B rows

__global__ __launch_bounds__(256) void gemm_mma_kernel(
    int M, int N, int K,
    const __nv_bfloat16* __restrict__ Ah, const __nv_bfloat16* __restrict__ Al,
    const __nv_bfloat16* __restrict__ Bh, const __nv_bfloat16* __restrict__ Bl,
    float* __restrict__ C)
{
    __shared__ __nv_bfloat16 sAh[2][128 * GPITCH], sAl[2][128 * GPITCH];
    __shared__ __nv_bfloat16 sBh[2][128 * GPITCH], sBl[2][128 * GPITCH];

    const int tid  = threadIdx.x;
    const int lane = tid & 31;
    const int wid  = tid >> 5;
    const int wm   = wid >> 2;
    const int wn   = wid & 3;
    const int gq   = lane >> 2;
    const int tg   = lane & 3;
    const int bm = blockIdx.y * 128;
    const int bn = blockIdx.x * 128;

    // ldmatrix lane offsets (bytes), pitch 80B
    const uint32_t a_off = (uint32_t)((lane & 15) * 80 + (lane & 16));
    const uint32_t b_off = (uint32_t)(((lane & 7) + ((lane >> 4) << 3)) * 80 + (((lane >> 3) & 1) << 4));
    const uint32_t uAh[2] = { su32(sAh[0]), su32(sAh[1]) };
    const uint32_t uAl[2] = { su32(sAl[0]), su32(sAl[1]) };
    const uint32_t uBh[2] = { su32(sBh[0]), su32(sBh[1]) };
    const uint32_t uBl[2] = { su32(sBl[0]), su32(sBl[1]) };

    float acc[4][4][4];
#pragma unroll
    for (int a = 0; a < 4; a++)
#pragma unroll
        for (int b = 0; b < 4; b++)
#pragma unroll
            for (int c = 0; c < 4; c++) acc[a][b][c] = 0.f;

    const int nch = K / 32;

    // cp.async one 32-K chunk into stage st (4 arrays x 128 rows x 64B)
    auto load_chunk = [&](int c, int st) {
        const int k0 = c * 32;
#pragma unroll
        for (int i = 0; i < 2; i++) {
            int u = tid + i * 256;
            int row = u >> 2;
            int q   = u & 3;
            uint32_t so = (uint32_t)(row * 80 + q * 16);
            size_t goA = (size_t)(bm + row) * K + k0 + q * 8;
            size_t goB = (size_t)(bn + row) * K + k0 + q * 8;
            cp_async16(uAh[st] + so, Ah + goA);
            cp_async16(uAl[st] + so, Al + goA);
            cp_async16(uBh[st] + so, Bh + goB);
            cp_async16(uBl[st] + so, Bl + goB);
        }
    };

    load_chunk(0, 0);
    cp_commit();

    for (int c = 0; c < nch; c++) {
        const int st = c & 1;
        if (c + 1 < nch) {
            load_chunk(c + 1, st ^ 1);
            cp_commit();
            cp_wait<1>();
        } else {
            cp_wait<0>();
        }
        __syncthreads();

#pragma unroll
        for (int ks = 0; ks < 2; ks++) {
            const uint32_t kb = (uint32_t)(ks * 32);   // bytes
            uint32_t ah[4][4], al[4][4], bh[4][2], bl[4][2];
#pragma unroll
            for (int mt = 0; mt < 4; mt++) {
                uint32_t base = (uint32_t)((wm * 64 + mt * 16) * 80) + kb;
                ldsm_x4(ah[mt][0], ah[mt][1], ah[mt][2], ah[mt][3], uAh[st] + base + a_off);
                ldsm_x4(al[mt][0], al[mt][1], al[mt][2], al[mt][3], uAl[st] + base + a_off);
            }
#pragma unroll
            for (int ntp = 0; ntp < 2; ntp++) {
                uint32_t base = (uint32_t)((wn * 32 + ntp * 16) * 80) + kb;
                ldsm_x4(bh[2 * ntp][0], bh[2 * ntp][1], bh[2 * ntp + 1][0], bh[2 * ntp + 1][1],
                        uBh[st] + base + b_off);
                ldsm_x4(bl[2 * ntp][0], bl[2 * ntp][1], bl[2 * ntp + 1][0], bl[2 * ntp + 1][1],
                        uBl[st] + base + b_off);
            }
#pragma unroll
            for (int mt = 0; mt < 4; mt++)
#pragma unroll
                for (int nt = 0; nt < 4; nt++) {
                    mma16816(acc[mt][nt], ah[mt][0], ah[mt][1], ah[mt][2], ah[mt][3],
                             bh[nt][0], bh[nt][1]);
                    mma16816(acc[mt][nt], ah[mt][0], ah[mt][1], ah[mt][2], ah[mt][3],
                             bl[nt][0], bl[nt][1]);
                    mma16816(acc[mt][nt], al[mt][0], al[mt][1], al[mt][2], al[mt][3],
                             bh[nt][0], bh[nt][1]);
                }
        }
        __syncthreads();   // all reads of stage st done before it's refilled
    }

#pragma unroll
    for (int mt = 0; mt < 4; mt++) {
        int row = bm + wm * 64 + mt * 16 + gq;
#pragma unroll
        for (int nt = 0; nt < 4; nt++) {
            int col = bn + wn * 32 + nt * 8 + 2 * tg;
            *(float2*)(C + (size_t)row * N + col) =
                make_float2(acc[mt][nt][0], acc[mt][nt][1]);
            *(float2*)(C + (size_t)(row + 8) * N + col) =
                make_float2(acc[mt][nt][2], acc[mt][nt][3]);
        }
    }
}

// ---------------------------------------------------------------------------
// RMSNorm + RoPE + hi/lo split. One warp per (t, slot), 32 slots.
// ---------------------------------------------------------------------------
__global__ __launch_bounds__(256) void norm_rope_split_kernel(
    const int* __restrict__ positions,
    const float* __restrict__ qw, const float* __restrict__ kw,
    const float* __restrict__ qkv,
    __nv_bfloat16* __restrict__ qsh, __nv_bfloat16* __restrict__ qsl,
    __nv_bfloat16* __restrict__ ksh, __nv_bfloat16* __restrict__ ksl,
    __nv_bfloat16* __restrict__ vsh, __nv_bfloat16* __restrict__ vsl)
{
    const int gw   = blockIdx.x * 8 + (threadIdx.x >> 5);
    const int lane = threadIdx.x & 31;
    const int t    = gw >> 5;
    const int slot = gw & 31;

    if (slot >= 24) {
        const int vh = slot - 24;
        float4 v = ((const float4*)(qkv + (size_t)t * QKVW + (NH + NKV) * DH + vh * DH))[lane];
        size_t o = (size_t)t * KVW + vh * DH + lane * 4;
        split4_store(v, vsh + o, vsl + o);
        return;
    }

    const bool isq = (slot < NH);
    const float* ptr = qkv + (size_t)t * QKVW + slot * DH;
    const float* w = isq ? qw : kw;

    float4 x = ((const float4*)ptr)[lane];
    float ss = x.x * x.x + x.y * x.y + x.z * x.z + x.w * x.w;
#pragma unroll
    for (int o = 16; o > 0; o >>= 1) ss += __shfl_xor_sync(0xffffffffu, ss, o);
    float rinv = rsqrtf(ss * (1.f / DH) + EPS);

    float4 wv = ((const float4*)w)[lane];
    float4 xn = make_float4(x.x * rinv * wv.x, x.y * rinv * wv.y,
                            x.z * rinv * wv.z, x.w * rinv * wv.w);

    float4 other;
    other.x = __shfl_xor_sync(0xffffffffu, xn.x, 16);
    other.y = __shfl_xor_sync(0xffffffffu, xn.y, 16);
    other.z = __shfl_xor_sync(0xffffffffu, xn.z, 16);
    other.w = __shfl_xor_sync(0xffffffffu, xn.w, 16);

    const float pos = (float)positions[t];
    const int j = (lane & 15) * 4;
    float4 outv;
    float* xo = (float*)&outv;
    const float* x1 = (lane < 16) ? (const float*)&xn : (const float*)&other;
    const float* x2 = (lane < 16) ? (const float*)&other : (const float*)&xn;
#pragma unroll
    for (int c = 0; c < 4; c++) {
        float inv_freq = powf(10000.f, -(float)(j + c) * (1.f / 64.f));
        float sv, cv;
        sincosf(pos * inv_freq, &sv, &cv);
        xo[c] = (lane < 16) ? (x1[c] * cv - x2[c] * sv)
                            : (x2[c] * cv + x1[c] * sv);
    }

    if (isq) {
        const float scale = 0.08838834764831845f;  // 1/sqrt(128)
        outv.x *= scale; outv.y *= scale; outv.z *= scale; outv.w *= scale;
        size_t o = (size_t)t * QW + slot * DH + lane * 4;
        split4_store(outv, qsh + o, qsl + o);
    } else {
        size_t o = (size_t)t * KVW + (slot - NH) * DH + lane * 4;
        split4_store(outv, ksh + o, ksl + o);
    }
}

// ---------------------------------------------------------------------------
// FA2-style causal GQA attention, bf16x3 mma, in-register softmax,
// cp.async double-buffered K/V; Q fragments resident in registers.
// ---------------------------------------------------------------------------
#define AT_BM 128
#define AT_BN 64
#define QP 136      // smem pitch (bf16): 272B rows

struct AttnSmem {
    __nv_bfloat16 Qh[AT_BM * QP], Ql[AT_BM * QP];
    __nv_bfloat16 Kh[2][AT_BN * QP], Kl[2][AT_BN * QP];
    __nv_bfloat16 Vh[2][AT_BN * QP], Vl[2][AT_BN * QP];
};

__global__ __launch_bounds__(256, 1) void attn_kernel(
    const __nv_bfloat16* __restrict__ qsh, const __nv_bfloat16* __restrict__ qsl,
    const __nv_bfloat16* __restrict__ ksh, const __nv_bfloat16* __restrict__ ksl,
    const __nv_bfloat16* __restrict__ vsh, const __nv_bfloat16* __restrict__ vsl,
    __nv_bfloat16* __restrict__ oh, __nv_bfloat16* __restrict__ ol)
{
    extern __shared__ char smem_raw[];
    AttnSmem& s = *(AttnSmem*)smem_raw;

    const int h   = blockIdx.x;
    const int m0  = (gridDim.y - 1 - blockIdx.y) * AT_BM;  // heavy blocks first
    const int kvh = h >> 1;
    const int tid = threadIdx.x;
    const int lane = tid & 31;
    const int w    = tid >> 5;
    const int gq   = lane >> 2;
    const int tg   = lane & 3;

    const uint32_t uQh = su32(s.Qh), uQl = su32(s.Ql);
    const uint32_t uKh[2] = { su32(s.Kh[0]), su32(s.Kh[1]) };
    const uint32_t uKl[2] = { su32(s.Kl[0]), su32(s.Kl[1]) };
    const uint32_t uVh[2] = { su32(s.Vh[0]), su32(s.Vh[1]) };
    const uint32_t uVl[2] = { su32(s.Vl[0]), su32(s.Vl[1]) };

    // ldmatrix lane offsets (bytes), pitch 272B
    const uint32_t a_off = (uint32_t)((lane & 15) * 272 + (lane & 16));
    const uint32_t b_off = (uint32_t)(((lane & 7) + ((lane >> 4) << 3)) * 272 + (((lane >> 3) & 1) << 4));
    const uint32_t vlane_off = (uint32_t)((lane & 15) * 272 + ((lane >> 4) << 4));

    // cp.async prefetch of one 64-key tile into buffer b
    auto prefetch = [&](int n0, int b) {
#pragma unroll
        for (int i = 0; i < 4; i++) {
            int u = tid + i * 256;
            int row = u >> 4;
            int c   = u & 15;
            uint32_t so = (uint32_t)(row * 272 + c * 16);
            size_t go = (size_t)(n0 + row) * KVW + kvh * DH + c * 8;
            cp_async16(uKh[b] + so, ksh + go);
            cp_async16(uKl[b] + so, ksl + go);
            cp_async16(uVh[b] + so, vsh + go);
            cp_async16(uVl[b] + so, vsl + go);
        }
    };

    // Q tile: direct bf16 loads into smem (once per CTA)
    for (int u = tid; u < AT_BM * 16; u += 256) {
        int row = u >> 4;
        int c   = u & 15;
        size_t go = (size_t)(m0 + row) * QW + h * DH + c * 8;
        *(uint4*)((char*)s.Qh + row * 272 + c * 16) = *(const uint4*)(qsh + go);
        *(uint4*)((char*)s.Ql + row * 272 + c * 16) = *(const uint4*)(qsl + go);
    }

    prefetch(0, 0);
    cp_commit();
    __syncthreads();   // Q stores visible for ldmatrix

    // Hoist Q fragments into registers (this warp's 16 rows, all 128 K)
    uint32_t qfh[8][4], qfl[8][4];
#pragma unroll
    for (int ks = 0; ks < 8; ks++) {
        uint32_t qbase = (uint32_t)(w * 16 * 272 + ks * 32) + a_off;
        ldsm_x4(qfh[ks][0], qfh[ks][1], qfh[ks][2], qfh[ks][3], uQh + qbase);
        ldsm_x4(qfl[ks][0], qfl[ks][1], qfl[ks][2], qfl[ks][3], uQl + qbase);
    }

    float m_[2] = { -CUDART_INF_F, -CUDART_INF_F };
    float l_[2] = { 0.f, 0.f };

    float accO[16][4];
#pragma unroll
    for (int a = 0; a < 16; a++)
#pragma unroll
        for (int c = 0; c < 4; c++) accO[a][c] = 0.f;

    const int row0 = m0 + w * 16 + gq;
    const int n_tiles = (m0 + AT_BM) / AT_BN;

    for (int tile = 0; tile < n_tiles; tile++) {
        const int n0 = tile * AT_BN;
        const int b  = tile & 1;

        if (tile + 1 < n_tiles) {
            prefetch(n0 + AT_BN, b ^ 1);
            cp_commit();
            cp_wait<1>();
        } else {
            cp_wait<0>();
        }
        __syncthreads();

        const uint32_t kh = uKh[b], kl = uKl[b];
        const uint32_t svh = uVh[b], svl = uVl[b];

        // ---- S = Q @ K^T (bf16x3), warp tile 16x64, Q frags in regs ----
        float accS[8][4];
#pragma unroll
        for (int bb = 0; bb < 8; bb++)
#pragma unroll
            for (int c = 0; c < 4; c++) accS[bb][c] = 0.f;

#pragma unroll
        for (int ks = 0; ks < 8; ks++) {
            const uint32_t kb = (uint32_t)(ks * 32);   // bytes
#pragma unroll
            for (int ntp = 0; ntp < 4; ntp++) {
                uint32_t base = (uint32_t)(ntp * 16 * 272) + kb + b_off;
                uint32_t bh0, bh1, bh2, bh3, bl0, bl1, bl2, bl3;
                ldsm_x4(bh0, bh1, bh2, bh3, kh + base);
                ldsm_x4(bl0, bl1, bl2, bl3, kl + base);
                mma16816(accS[2 * ntp],     qfh[ks][0], qfh[ks][1], qfh[ks][2], qfh[ks][3], bh0, bh1);
                mma16816(accS[2 * ntp],     qfh[ks][0], qfh[ks][1], qfh[ks][2], qfh[ks][3], bl0, bl1);
                mma16816(accS[2 * ntp],     qfl[ks][0], qfl[ks][1], qfl[ks][2], qfl[ks][3], bh0, bh1);
                mma16816(accS[2 * ntp + 1], qfh[ks][0], qfh[ks][1], qfh[ks][2], qfh[ks][3], bh2, bh3);
                mma16816(accS[2 * ntp + 1], qfh[ks][0], qfh[ks][1], qfh[ks][2], qfh[ks][3], bl2, bl3);
                mma16816(accS[2 * ntp + 1], qfl[ks][0], qfl[ks][1], qfl[ks][2], qfl[ks][3], bh2, bh3);
            }
        }

        // ---- causal mask ----
        if (n0 + AT_BN - 1 > m0) {
#pragma unroll
            for (int nt = 0; nt < 8; nt++) {
                int c0 = n0 + nt * 8 + 2 * tg;
                if (c0     > row0)     accS[nt][0] = -CUDART_INF_F;
                if (c0 + 1 > row0)     accS[nt][1] = -CUDART_INF_F;
                if (c0     > row0 + 8) accS[nt][2] = -CUDART_INF_F;
                if (c0 + 1 > row0 + 8) accS[nt][3] = -CUDART_INF_F;
            }
        }

        // ---- in-register online softmax ----
        float mx0 = accS[0][0], mx1 = accS[0][2];
#pragma unroll
        for (int nt = 0; nt < 8; nt++) {
            mx0 = fmaxf(mx0, fmaxf(accS[nt][0], accS[nt][1]));
            mx1 = fmaxf(mx1, fmaxf(accS[nt][2], accS[nt][3]));
        }
        mx0 = fmaxf(mx0, __shfl_xor_sync(0xffffffffu, mx0, 1));
        mx0 = fmaxf(mx0, __shfl_xor_sync(0xffffffffu, mx0, 2));
        mx1 = fmaxf(mx1, __shfl_xor_sync(0xffffffffu, mx1, 1));
        mx1 = fmaxf(mx1, __shfl_xor_sync(0xffffffffu, mx1, 2));

        float mn0 = fmaxf(m_[0], mx0);
        float mn1 = fmaxf(m_[1], mx1);
        float corr0 = __expf(m_[0] - mn0);
        float corr1 = __expf(m_[1] - mn1);
        float sum0 = 0.f, sum1 = 0.f;
#pragma unroll
        for (int nt = 0; nt < 8; nt++) {
            accS[nt][0] = __expf(accS[nt][0] - mn0);
            accS[nt][1] = __expf(accS[nt][1] - mn0);
            accS[nt][2] = __expf(accS[nt][2] - mn1);
            accS[nt][3] = __expf(accS[nt][3] - mn1);
            sum0 += accS[nt][0] + accS[nt][1];
            sum1 += accS[nt][2] + accS[nt][3];
        }
        sum0 += __shfl_xor_sync(0xffffffffu, sum0, 1);
        sum0 += __shfl_xor_sync(0xffffffffu, sum0, 2);
        sum1 += __shfl_xor_sync(0xffffffffu, sum1, 1);
        sum1 += __shfl_xor_sync(0xffffffffu, sum1, 2);
        l_[0] = l_[0] * corr0 + sum0;
        l_[1] = l_[1] * corr1 + sum1;
        m_[0] = mn0; m_[1] = mn1;

#pragma unroll
        for (int nt = 0; nt < 16; nt++) {
            accO[nt][0] *= corr0; accO[nt][1] *= corr0;
            accO[nt][2] *= corr1; accO[nt][3] *= corr1;
        }

        // ---- O += P @ V (bf16x3), warp tile 16x128, k=64 ----
#pragma unroll
        for (int kc = 0; kc < 4; kc++) {
            float p00 = accS[2 * kc][0],     p01 = accS[2 * kc][1];
            float p10 = accS[2 * kc][2],     p11 = accS[2 * kc][3];
            float p20 = accS[2 * kc + 1][0], p21 = accS[2 * kc + 1][1];
            float p30 = accS[2 * kc + 1][2], p31 = accS[2 * kc + 1][3];
            float h00 = __bfloat162float(__float2bfloat16(p00));
            float h01 = __bfloat162float(__float2bfloat16(p01));
            float h10 = __bfloat162float(__float2bfloat16(p10));
            float h11 = __bfloat162float(__float2bfloat16(p11));
            float h20 = __bfloat162float(__float2bfloat16(p20));
            float h21 = __bfloat162float(__float2bfloat16(p21));
            float h30 = __bfloat162float(__float2bfloat16(p30));
            float h31 = __bfloat162float(__float2bfloat16(p31));
            uint32_t ph0 = pack_bf16x2(h00, h01);
            uint32_t ph1 = pack_bf16x2(h10, h11);
            uint32_t ph2 = pack_bf16x2(h20, h21);
            uint32_t ph3 = pack_bf16x2(h30, h31);
            uint32_t pl0 = pack_bf16x2(p00 - h00, p01 - h01);
            uint32_t pl1 = pack_bf16x2(p10 - h10, p11 - h11);
            uint32_t pl2 = pack_bf16x2(p20 - h20, p21 - h21);
            uint32_t pl3 = pack_bf16x2(p30 - h30, p31 - h31);

#pragma unroll
            for (int ncg = 0; ncg < 8; ncg++) {
                uint32_t base_off = (uint32_t)(kc * 16 * 272 + ncg * 32) + vlane_off;
                uint32_t vh0, vh1, vh2, vh3, vl0, vl1, vl2, vl3;
                ldsm_x4_t(vh0, vh1, vh2, vh3, svh + base_off);
                ldsm_x4_t(vl0, vl1, vl2, vl3, svl + base_off);
                mma16816(accO[ncg * 2],     ph0, ph1, ph2, ph3, vh0, vh1);
                mma16816(accO[ncg * 2],     ph0, ph1, ph2, ph3, vl0, vl1);
                mma16816(accO[ncg * 2],     pl0, pl1, pl2, pl3, vh0, vh1);
                mma16816(accO[ncg * 2 + 1], ph0, ph1, ph2, ph3, vh2, vh3);
                mma16816(accO[ncg * 2 + 1], ph0, ph1, ph2, ph3, vl2, vl3);
                mma16816(accO[ncg * 2 + 1], pl0, pl1, pl2, pl3, vh2, vh3);
            }
        }
        __syncthreads();
    }

    // ---- normalize + split-write bf16 hi/lo ----
    float i0 = 1.f / l_[0];
    float i1 = 1.f / l_[1];
#pragma unroll
    for (int nt = 0; nt < 16; nt++) {
        int col = h * DH + nt * 8 + 2 * tg;
        float v0 = accO[nt][0] * i0, v1 = accO[nt][1] * i0;
        float v2 = accO[nt][2] * i1, v3 = accO[nt][3] * i1;
        float h0 = __bfloat162float(__float2bfloat16(v0));
        float h1 = __bfloat162float(__float2bfloat16(v1));
        float h2 = __bfloat162float(__float2bfloat16(v2));
        float h3 = __bfloat162float(__float2bfloat16(v3));
        size_t o0 = (size_t)row0 * HID + col;
        size_t o1 = (size_t)(row0 + 8) * HID + col;
        *(uint32_t*)(oh + o0) = pack_bf16x2(h0, h1);
        *(uint32_t*)(oh + o1) = pack_bf16x2(h2, h3);
        *(uint32_t*)(ol + o0) = pack_bf16x2(v0 - h0, v1 - h1);
        *(uint32_t*)(ol + o1) = pack_bf16x2(v2 - h2, v3 - h3);
    }
}

// ---------------------------------------------------------------------------
// Launch
// ---------------------------------------------------------------------------
extern "C" void kernel_launch(void* const* d_in, const int* in_sizes, int n_in,
                              void* d_out, int out_size)
{
    const int*   positions = (const int*)d_in[0];
    const float* hidden    = (const float*)d_in[1];
    const float* w_qkv     = (const float*)d_in[2];
    const float* w_o       = (const float*)d_in[3];
    const float* q_norm_w  = (const float*)d_in[4];
    const float* k_norm_w  = (const float*)d_in[5];
    float*       out       = (float*)d_out;

    float* qkv_ptr = nullptr;
    __nv_bfloat16 *ah, *al, *bh, *bl, *qsh, *qsl, *ksh, *ksl, *vsh, *vsl;
    cudaGetSymbolAddress((void**)&qkv_ptr, g_qkv);
    cudaGetSymbolAddress((void**)&ah, g_ah);
    cudaGetSymbolAddress((void**)&al, g_al);
    cudaGetSymbolAddress((void**)&bh, g_bh);
    cudaGetSymbolAddress((void**)&bl, g_bl);
    cudaGetSymbolAddress((void**)&qsh, g_qsh);
    cudaGetSymbolAddress((void**)&qsl, g_qsl);
    cudaGetSymbolAddress((void**)&ksh, g_ksh);
    cudaGetSymbolAddress((void**)&ksl, g_ksl);
    cudaGetSymbolAddress((void**)&vsh, g_vsh);
    cudaGetSymbolAddress((void**)&vsl, g_vsl);

    // 1. Split hidden; transpose+split w_qkv.
    {
        int n = TT * HID;
        split_kernel<<<n / 4 / 256, 256>>>(hidden, ah, al, n);
        dim3 tg(QKVW / 32, HID / 32);
        transpose_split_kernel<<<tg, dim3(32, 8)>>>(w_qkv, bh, bl, HID, QKVW);
    }

    // 2. QKV projection via mma.sync bf16x3 (cp.async pipelined).
    {
        dim3 grid(QKVW / 128, TT / 128);
        gemm_mma_kernel<<<grid, 256>>>(TT, QKVW, HID, ah, al, bh, bl, qkv_ptr);
    }

    // 3. RMSNorm + RoPE + split to bf16 hi/lo (q scaled; v plain split).
    {
        norm_rope_split_kernel<<<TT * 32 / 8, 256>>>(
            positions, q_norm_w, k_norm_w, qkv_ptr,
            qsh, qsl, ksh, ksl, vsh, vsl);
    }

    // 4. transpose+split w_o (bh/bl free after QKV GEMM)
    {
        dim3 tg(HID / 32, (NH * DH) / 32);
        transpose_split_kernel<<<tg, dim3(32, 8)>>>(w_o, bh, bl, NH * DH, HID);
    }

    // 5. Causal GQA flash attention (pre-split bf16, cp.async + ldmatrix,
    //    Q fragments in registers), writes split bf16 hi/lo into ah/al.
    {
        static_assert(sizeof(AttnSmem) <= 227 * 1024, "smem");
        cudaFuncSetAttribute(attn_kernel,
                             cudaFuncAttributeMaxDynamicSharedMemorySize,
                             (int)sizeof(AttnSmem));
        dim3 grid(NH, TT / AT_BM);
        attn_kernel<<<grid, 256, sizeof(AttnSmem)>>>(
            qsh, qsl, ksh, ksl, vsh, vsl, ah, al);
    }

    // 6. Output projection via mma.sync bf16x3.
    {
        dim3 grid(HID / 128, TT / 128);
        gemm_mma_kernel<<<grid, 256>>>(TT, HID, NH * DH, ah, al, bh, bl, out);
    }
}

// round 10
// speedup vs baseline: 2.8560x; 1.0094x over previous
#include <cuda_runtime.h>
#include <cuda_bf16.h>
#include <math.h>
#include <math_constants.h>
#include <stdint.h>

// Problem constants
#define TT   2048
#define HID  2048
#define NH   16
#define NKV  8
#define DH   128
#define QKVW ((NH + 2 * NKV) * DH)   // 4096
#define QW   (NH * DH)               // 2048
#define KVW  (NKV * DH)              // 1024
#define EPS  1e-6f

// Scratch (allocation-free rule: __device__ globals)
__device__ __nv_bfloat16 g_ah[(size_t)TT * HID];     // GEMM A hi / attn-out hi
__device__ __nv_bfloat16 g_al[(size_t)TT * HID];     // GEMM A lo / attn-out lo
__device__ __nv_bfloat16 g_bh[(size_t)QKVW * HID];   // B^T hi ([N,K])
__device__ __nv_bfloat16 g_bl[(size_t)QKVW * HID];   // B^T lo
__device__ __nv_bfloat16 g_qsh[(size_t)TT * QW],  g_qsl[(size_t)TT * QW];   // split Q (scaled)
__device__ __nv_bfloat16 g_ksh[(size_t)TT * KVW], g_ksl[(size_t)TT * KVW];  // split K
__device__ __nv_bfloat16 g_vsh[(size_t)TT * KVW], g_vsl[(size_t)TT * KVW];  // split V

// ---------------------------------------------------------------------------
// PTX helpers (base sm_103 target — HMMA mma.sync + ldmatrix + cp.async)
// ---------------------------------------------------------------------------
__device__ __forceinline__ void mma16816(float d[4],
                                         uint32_t a0, uint32_t a1, uint32_t a2, uint32_t a3,
                                         uint32_t b0, uint32_t b1)
{
    asm volatile(
        "mma.sync.aligned.m16n8k16.row.col.f32.bf16.bf16.f32 "
        "{%0,%1,%2,%3}, {%4,%5,%6,%7}, {%8,%9}, {%0,%1,%2,%3};\n"
        : "+f"(d[0]), "+f"(d[1]), "+f"(d[2]), "+f"(d[3])
        : "r"(a0), "r"(a1), "r"(a2), "r"(a3), "r"(b0), "r"(b1));
}

__device__ __forceinline__ void ldsm_x4(uint32_t& r0, uint32_t& r1,
                                        uint32_t& r2, uint32_t& r3, uint32_t addr)
{
    asm volatile("ldmatrix.sync.aligned.m8n8.x4.shared.b16 {%0,%1,%2,%3}, [%4];"
                 : "=r"(r0), "=r"(r1), "=r"(r2), "=r"(r3) : "r"(addr));
}

__device__ __forceinline__ void ldsm_x4_t(uint32_t& r0, uint32_t& r1,
                                          uint32_t& r2, uint32_t& r3, uint32_t addr)
{
    asm volatile("ldmatrix.sync.aligned.m8n8.x4.trans.shared.b16 {%0,%1,%2,%3}, [%4];"
                 : "=r"(r0), "=r"(r1), "=r"(r2), "=r"(r3) : "r"(addr));
}

__device__ __forceinline__ uint32_t su32(const void* p) {
    return (uint32_t)__cvta_generic_to_shared(p);
}

__device__ __forceinline__ uint32_t pack_bf16x2(float a, float b) {
    __nv_bfloat162 t = __floats2bfloat162_rn(a, b);
    return *(uint32_t*)&t;
}

__device__ __forceinline__ void cp_async16(uint32_t dst, const void* src) {
    asm volatile("cp.async.cg.shared.global [%0], [%1], 16;" :: "r"(dst), "l"(src));
}
__device__ __forceinline__ void cp_commit() {
    asm volatile("cp.async.commit_group;" ::: "memory");
}
template <int N>
__device__ __forceinline__ void cp_wait() {
    asm volatile("cp.async.wait_group %0;" :: "n"(N) : "memory");
}

// hi/lo split of a float4, stored as 2x bf162 each
__device__ __forceinline__ void split4_store(float4 v, __nv_bfloat16* hp, __nv_bfloat16* lp) {
    __nv_bfloat16 h0 = __float2bfloat16(v.x), h1 = __float2bfloat16(v.y);
    __nv_bfloat16 h2 = __float2bfloat16(v.z), h3 = __float2bfloat16(v.w);
    *(uint32_t*)(hp)     = pack_bf16x2(__bfloat162float(h0), __bfloat162float(h1));
    *(uint32_t*)(hp + 2) = pack_bf16x2(__bfloat162float(h2), __bfloat162float(h3));
    *(uint32_t*)(lp)     = pack_bf16x2(v.x - __bfloat162float(h0), v.y - __bfloat162float(h1));
    *(uint32_t*)(lp + 2) = pack_bf16x2(v.z - __bfloat162float(h2), v.w - __bfloat162float(h3));
}

// hi/lo split of 2 floats -> two u32 stores
__device__ __forceinline__ void split2_store(float a, float b,
                                             __nv_bfloat16* hp, __nv_bfloat16* lp) {
    float ha = __bfloat162float(__float2bfloat16(a));
    float hb = __bfloat162float(__float2bfloat16(b));
    *(uint32_t*)hp = pack_bf16x2(ha, hb);
    *(uint32_t*)lp = pack_bf16x2(a - ha, b - hb);
}

// ---------------------------------------------------------------------------
// Split conversion: fp32 -> (hi, lo) bf16, same layout. n % 4 == 0.
// ---------------------------------------------------------------------------
__global__ __launch_bounds__(256) void split_kernel(
    const float* __restrict__ x,
    __nv_bfloat16* __restrict__ hi, __nv_bfloat16* __restrict__ lo, int n)
{
    int i = (blockIdx.x * blockDim.x + threadIdx.x) * 4;
    if (i >= n) return;
    float4 v = *(const float4*)(x + i);
    split4_store(v, hi + i, lo + i);
}

// ---------------------------------------------------------------------------
// Transpose + split: W[K,N] fp32 -> Th/Tl [N,K] bf16. K,N % 32 == 0.
// ---------------------------------------------------------------------------
__global__ __launch_bounds__(256) void transpose_split_kernel(
    const float* __restrict__ W,
    __nv_bfloat16* __restrict__ Th, __nv_bfloat16* __restrict__ Tl,
    int K, int N)
{
    __shared__ float tile[32][33];
    const int bn = blockIdx.x * 32;
    const int bk = blockIdx.y * 32;
    const int tx = threadIdx.x;
    const int ty = threadIdx.y;
#pragma unroll
    for (int j = 0; j < 32; j += 8)
        tile[ty + j][tx] = W[(size_t)(bk + ty + j) * N + bn + tx];
    __syncthreads();
#pragma unroll
    for (int j = 0; j < 32; j += 8) {
        float v = tile[tx][ty + j];
        __nv_bfloat16 h = __float2bfloat16(v);
        __nv_bfloat16 l = __float2bfloat16(v - __bfloat162float(h));
        size_t o = (size_t)(bn + ty + j) * K + bk + tx;
        Th[o] = h;
        Tl[o] = l;
    }
}

// ---------------------------------------------------------------------------
// mma.sync bf16x3 GEMM: cp.async double-buffered, ldmatrix frags.
// FUSED=true: QKV projection — epilogue does per-head RMSNorm + RoPE +
//   hi/lo bf16 split, writing qs/ks/vs directly (N tile == head slot).
// FUSED=false: plain fp32 C output (O-projection).
// CTA 128x128, 256 threads, warp tile 64x32, BK=32, 2 smem stages.
// ---------------------------------------------------------------------------
#define GST   10240   // bytes per stage per array (128 rows x 80B)
#define GARR  20480   // bytes per array (2 stages)

template<bool FUSED>
__global__ __launch_bounds__(256) void gemm_mma_kernel_t(
    int M, int N, int K,
    const __nv_bfloat16* __restrict__ Ah, const __nv_bfloat16* __restrict__ Al,
    const __nv_bfloat16* __restrict__ Bh, const __nv_bfloat16* __restrict__ Bl,
    float* __restrict__ C,
    const int* __restrict__ positions,
    const float* __restrict__ qw, const float* __restrict__ kw,
    __nv_bfloat16* __restrict__ qsh, __nv_bfloat16* __restrict__ qsl,
    __nv_bfloat16* __restrict__ ksh, __nv_bfloat16* __restrict__ ksl,
    __nv_bfloat16* __restrict__ vsh, __nv_bfloat16* __restrict__ vsl)
{
    __shared__ __align__(16) char blob[81920];

    const int tid  = threadIdx.x;
    const int lane = tid & 31;
    const int wid  = tid >> 5;
    const int wm   = wid >> 2;
    const int wn   = wid & 3;
    const int gq   = lane >> 2;
    const int tg   = lane & 3;
    const int bm = blockIdx.y * 128;
    const int bn = blockIdx.x * 128;

    const uint32_t ub = su32(blob);
    // array bases: Ah 0, Al 20480, Bh 40960, Bl 61440; + stage*GST
    const uint32_t a_off = (uint32_t)((lane & 15) * 80 + (lane & 16));
    const uint32_t b_off = (uint32_t)(((lane & 7) + ((lane >> 4) << 3)) * 80 + (((lane >> 3) & 1) << 4));

    float acc[4][4][4];
#pragma unroll
    for (int a = 0; a < 4; a++)
#pragma unroll
        for (int b = 0; b < 4; b++)
#pragma unroll
            for (int c = 0; c < 4; c++) acc[a][b][c] = 0.f;

    const int nch = K / 32;

    auto load_chunk = [&](int c, int st) {
        const int k0 = c * 32;
        const uint32_t sb = ub + (uint32_t)st * GST;
#pragma unroll
        for (int i = 0; i < 2; i++) {
            int u = tid + i * 256;
            int row = u >> 2;
            int q   = u & 3;
            uint32_t so = (uint32_t)(row * 80 + q * 16);
            size_t goA = (size_t)(bm + row) * K + k0 + q * 8;
            size_t goB = (size_t)(bn + row) * K + k0 + q * 8;
            cp_async16(sb + so,             Ah + goA);
            cp_async16(sb + GARR + so,      Al + goA);
            cp_async16(sb + 2 * GARR + so,  Bh + goB);
            cp_async16(sb + 3 * GARR + so,  Bl + goB);
        }
    };

    load_chunk(0, 0);
    cp_commit();

    for (int c = 0; c < nch; c++) {
        const int st = c & 1;
        if (c + 1 < nch) {
            load_chunk(c + 1, st ^ 1);
            cp_commit();
            cp_wait<1>();
        } else {
            cp_wait<0>();
        }
        __syncthreads();

        const uint32_t sb = ub + (uint32_t)st * GST;
#pragma unroll
        for (int ks = 0; ks < 2; ks++) {
            const uint32_t kb = (uint32_t)(ks * 32);
            uint32_t ah[4][4], al[4][4], bh[4][2], bl[4][2];
#pragma unroll
            for (int mt = 0; mt < 4; mt++) {
                uint32_t base = (uint32_t)((wm * 64 + mt * 16) * 80) + kb + a_off;
                ldsm_x4(ah[mt][0], ah[mt][1], ah[mt][2], ah[mt][3], sb + base);
                ldsm_x4(al[mt][0], al[mt][1], al[mt][2], al[mt][3], sb + GARR + base);
            }
#pragma unroll
            for (int ntp = 0; ntp < 2; ntp++) {
                uint32_t base = (uint32_t)((wn * 32 + ntp * 16) * 80) + kb + b_off;
                ldsm_x4(bh[2 * ntp][0], bh[2 * ntp][1], bh[2 * ntp + 1][0], bh[2 * ntp + 1][1],
                        sb + 2 * GARR + base);
                ldsm_x4(bl[2 * ntp][0], bl[2 * ntp][1], bl[2 * ntp + 1][0], bl[2 * ntp + 1][1],
                        sb + 3 * GARR + base);
            }
#pragma unroll
            for (int mt = 0; mt < 4; mt++)
#pragma unroll
                for (int nt = 0; nt < 4; nt++) {
                    mma16816(acc[mt][nt], ah[mt][0], ah[mt][1], ah[mt][2], ah[mt][3],
                             bh[nt][0], bh[nt][1]);
                    mma16816(acc[mt][nt], ah[mt][0], ah[mt][1], ah[mt][2], ah[mt][3],
                             bl[nt][0], bl[nt][1]);
                    mma16816(acc[mt][nt], al[mt][0], al[mt][1], al[mt][2], al[mt][3],
                             bh[nt][0], bh[nt][1]);
                }
        }
        __syncthreads();
    }

    if constexpr (!FUSED) {
        // plain fp32 epilogue
#pragma unroll
        for (int mt = 0; mt < 4; mt++) {
            int row = bm + wm * 64 + mt * 16 + gq;
#pragma unroll
            for (int nt = 0; nt < 4; nt++) {
                int col = bn + wn * 32 + nt * 8 + 2 * tg;
                *(float2*)(C + (size_t)row * N + col) =
                    make_float2(acc[mt][nt][0], acc[mt][nt][1]);
                *(float2*)(C + (size_t)(row + 8) * N + col) =
                    make_float2(acc[mt][nt][2], acc[mt][nt][3]);
            }
        }
        return;
    } else {
        const int slot = bn >> 7;   // head slot 0..31 (0-15 q, 16-23 k, 24-31 v)

        if (slot >= 24) {
            // V: plain hi/lo split, no norm/rope
            const int vh = slot - 24;
#pragma unroll
            for (int mt = 0; mt < 4; mt++) {
#pragma unroll
                for (int hhalf = 0; hhalf < 2; hhalf++) {
                    int r = wm * 64 + mt * 16 + gq + 8 * hhalf;
                    int t = bm + r;
#pragma unroll
                    for (int nt = 0; nt < 4; nt++) {
                        int cn = wn * 32 + nt * 8 + 2 * tg;
                        size_t o = (size_t)t * KVW + vh * DH + cn;
                        split2_store(acc[mt][nt][2 * hhalf], acc[mt][nt][2 * hhalf + 1],
                                     vsh + o, vsl + o);
                    }
                }
            }
            return;
        }

        // Q/K: RMSNorm + RoPE + split
        float* xs   = (float*)blob;              // [128][132] fp32 (67584 B)
        float* sums = (float*)(blob + 67584);    // [128][4]

        // 1. per-row sum of squares: intra-thread + shuffle over tg + smem per warp-col
#pragma unroll
        for (int mt = 0; mt < 4; mt++) {
#pragma unroll
            for (int hhalf = 0; hhalf < 2; hhalf++) {
                float p = 0.f;
#pragma unroll
                for (int nt = 0; nt < 4; nt++) {
                    float v0 = acc[mt][nt][2 * hhalf];
                    float v1 = acc[mt][nt][2 * hhalf + 1];
                    p += v0 * v0 + v1 * v1;
                }
                p += __shfl_xor_sync(0xffffffffu, p, 1);
                p += __shfl_xor_sync(0xffffffffu, p, 2);
                if (tg == 0) {
                    int r = wm * 64 + mt * 16 + gq + 8 * hhalf;
                    sums[r * 4 + wn] = p;
                }
            }
        }
        __syncthreads();

        // 2. normalize (x * rinv * w[col]) into xs
        const float* wvec = (slot < NH) ? qw : kw;
        float wcol[8];
#pragma unroll
        for (int nt = 0; nt < 4; nt++) {
            int cn = wn * 32 + nt * 8 + 2 * tg;
            wcol[2 * nt]     = wvec[cn];
            wcol[2 * nt + 1] = wvec[cn + 1];
        }
#pragma unroll
        for (int mt = 0; mt < 4; mt++) {
#pragma unroll
            for (int hhalf = 0; hhalf < 2; hhalf++) {
                int r = wm * 64 + mt * 16 + gq + 8 * hhalf;
                float ssum = sums[r * 4 + 0] + sums[r * 4 + 1] + sums[r * 4 + 2] + sums[r * 4 + 3];
                float rinv = rsqrtf(ssum * (1.f / DH) + EPS);
#pragma unroll
                for (int nt = 0; nt < 4; nt++) {
                    int cn = wn * 32 + nt * 8 + 2 * tg;
                    xs[r * 132 + cn]     = acc[mt][nt][2 * hhalf] * rinv * wcol[2 * nt];
                    xs[r * 132 + cn + 1] = acc[mt][nt][2 * hhalf + 1] * rinv * wcol[2 * nt + 1];
                }
            }
        }
        __syncthreads();

        // 3. RoPE (+ scale for q) + split write
        const bool isq = (slot < NH);
        const float qscale = 0.08838834764831845f;   // 1/sqrt(128)
#pragma unroll
        for (int mt = 0; mt < 4; mt++) {
#pragma unroll
            for (int hhalf = 0; hhalf < 2; hhalf++) {
                int r = wm * 64 + mt * 16 + gq + 8 * hhalf;
                int t = bm + r;
                float pos = (float)positions[t];
#pragma unroll
                for (int nt = 0; nt < 4; nt++) {
                    int cn = wn * 32 + nt * 8 + 2 * tg;
                    int d  = cn & 63;
                    float x0 = xs[r * 132 + cn];
                    float x1 = xs[r * 132 + cn + 1];
                    float p0 = xs[r * 132 + (cn ^ 64)];
                    float p1 = xs[r * 132 + (cn ^ 64) + 1];
                    float if0 = powf(10000.f, -(float)d * (1.f / 64.f));
                    float if1 = powf(10000.f, -(float)(d + 1) * (1.f / 64.f));
                    float s0, c0, s1, c1;
                    sincosf(pos * if0, &s0, &c0);
                    sincosf(pos * if1, &s1, &c1);
                    float o0, o1;
                    if (cn < 64) {
                        o0 = x0 * c0 - p0 * s0;
                        o1 = x1 * c1 - p1 * s1;
                    } else {
                        o0 = x0 * c0 + p0 * s0;
                        o1 = x1 * c1 + p1 * s1;
                    }
                    if (isq) { o0 *= qscale; o1 *= qscale; }
                    if (isq) {
                        size_t o = (size_t)t * QW + slot * DH + cn;
                        split2_store(o0, o1, qsh + o, qsl + o);
                    } else {
                        size_t o = (size_t)t * KVW + (slot - NH) * DH + cn;
                        split2_store(o0, o1, ksh + o, ksl + o);
                    }
                }
            }
        }
    }
}

// ---------------------------------------------------------------------------
// FA2-style causal GQA attention, bf16x3 mma, in-register softmax,
// cp.async double-buffered K/V; Q fragments resident in registers.
// ---------------------------------------------------------------------------
#define AT_BM 128
#define AT_BN 64
#define QP 136      // smem pitch (bf16): 272B rows

struct AttnSmem {
    __nv_bfloat16 Qh[AT_BM * QP], Ql[AT_BM * QP];
    __nv_bfloat16 Kh[2][AT_BN * QP], Kl[2][AT_BN * QP];
    __nv_bfloat16 Vh[2][AT_BN * QP], Vl[2][AT_BN * QP];
};

__global__ __launch_bounds__(256, 1) void attn_kernel(
    const __nv_bfloat16* __restrict__ qsh, const __nv_bfloat16* __restrict__ qsl,
    const __nv_bfloat16* __restrict__ ksh, const __nv_bfloat16* __restrict__ ksl,
    const __nv_bfloat16* __restrict__ vsh, const __nv_bfloat16* __restrict__ vsl,
    __nv_bfloat16* __restrict__ oh, __nv_bfloat16* __restrict__ ol)
{
    extern __shared__ char smem_raw[];
    AttnSmem& s = *(AttnSmem*)smem_raw;

    const int h   = blockIdx.x;
    const int m0  = (gridDim.y - 1 - blockIdx.y) * AT_BM;  // heavy blocks first
    const int kvh = h >> 1;
    const int tid = threadIdx.x;
    const int lane = tid & 31;
    const int w    = tid >> 5;
    const int gq   = lane >> 2;
    const int tg   = lane & 3;

    const uint32_t uQh = su32(s.Qh), uQl = su32(s.Ql);
    const uint32_t uKh[2] = { su32(s.Kh[0]), su32(s.Kh[1]) };
    const uint32_t uKl[2] = { su32(s.Kl[0]), su32(s.Kl[1]) };
    const uint32_t uVh[2] = { su32(s.Vh[0]), su32(s.Vh[1]) };
    const uint32_t uVl[2] = { su32(s.Vl[0]), su32(s.Vl[1]) };

    const uint32_t a_off = (uint32_t)((lane & 15) * 272 + (lane & 16));
    const uint32_t b_off = (uint32_t)(((lane & 7) + ((lane >> 4) << 3)) * 272 + (((lane >> 3) & 1) << 4));
    const uint32_t vlane_off = (uint32_t)((lane & 15) * 272 + ((lane >> 4) << 4));

    auto prefetch = [&](int n0, int b) {
#pragma unroll
        for (int i = 0; i < 4; i++) {
            int u = tid + i * 256;
            int row = u >> 4;
            int c   = u & 15;
            uint32_t so = (uint32_t)(row * 272 + c * 16);
            size_t go = (size_t)(n0 + row) * KVW + kvh * DH + c * 8;
            cp_async16(uKh[b] + so, ksh + go);
            cp_async16(uKl[b] + so, ksl + go);
            cp_async16(uVh[b] + so, vsh + go);
            cp_async16(uVl[b] + so, vsl + go);
        }
    };

    // Q tile: direct bf16 loads into smem (once per CTA)
    for (int u = tid; u < AT_BM * 16; u += 256) {
        int row = u >> 4;
        int c   = u & 15;
        size_t go = (size_t)(m0 + row) * QW + h * DH + c * 8;
        *(uint4*)((char*)s.Qh + row * 272 + c * 16) = *(const uint4*)(qsh + go);
        *(uint4*)((char*)s.Ql + row * 272 + c * 16) = *(const uint4*)(qsl + go);
    }

    prefetch(0, 0);
    cp_commit();
    __syncthreads();

    // Hoist Q fragments into registers
    uint32_t qfh[8][4], qfl[8][4];
#pragma unroll
    for (int ks = 0; ks < 8; ks++) {
        uint32_t qbase = (uint32_t)(w * 16 * 272 + ks * 32) + a_off;
        ldsm_x4(qfh[ks][0], qfh[ks][1], qfh[ks][2], qfh[ks][3], uQh + qbase);
        ldsm_x4(qfl[ks][0], qfl[ks][1], qfl[ks][2], qfl[ks][3], uQl + qbase);
    }

    float m_[2] = { -CUDART_INF_F, -CUDART_INF_F };
    float l_[2] = { 0.f, 0.f };

    float accO[16][4];
#pragma unroll
    for (int a = 0; a < 16; a++)
#pragma unroll
        for (int c = 0; c < 4; c++) accO[a][c] = 0.f;

    const int row0 = m0 + w * 16 + gq;
    const int n_tiles = (m0 + AT_BM) / AT_BN;

    for (int tile = 0; tile < n_tiles; tile++) {
        const int n0 = tile * AT_BN;
        const int b  = tile & 1;

        if (tile + 1 < n_tiles) {
            prefetch(n0 + AT_BN, b ^ 1);
            cp_commit();
            cp_wait<1>();
        } else {
            cp_wait<0>();
        }
        __syncthreads();

        const uint32_t kh = uKh[b], kl = uKl[b];
        const uint32_t svh = uVh[b], svl = uVl[b];

        // ---- S = Q @ K^T (bf16x3), warp tile 16x64 ----
        float accS[8][4];
#pragma unroll
        for (int bb = 0; bb < 8; bb++)
#pragma unroll
            for (int c = 0; c < 4; c++) accS[bb][c] = 0.f;

#pragma unroll
        for (int ks = 0; ks < 8; ks++) {
            const uint32_t kb = (uint32_t)(ks * 32);
#pragma unroll
            for (int ntp = 0; ntp < 4; ntp++) {
                uint32_t base = (uint32_t)(ntp * 16 * 272) + kb + b_off;
                uint32_t bh0, bh1, bh2, bh3, bl0, bl1, bl2, bl3;
                ldsm_x4(bh0, bh1, bh2, bh3, kh + base);
                ldsm_x4(bl0, bl1, bl2, bl3, kl + base);
                mma16816(accS[2 * ntp],     qfh[ks][0], qfh[ks][1], qfh[ks][2], qfh[ks][3], bh0, bh1);
                mma16816(accS[2 * ntp],     qfh[ks][0], qfh[ks][1], qfh[ks][2], qfh[ks][3], bl0, bl1);
                mma16816(accS[2 * ntp],     qfl[ks][0], qfl[ks][1], qfl[ks][2], qfl[ks][3], bh0, bh1);
                mma16816(accS[2 * ntp + 1], qfh[ks][0], qfh[ks][1], qfh[ks][2], qfh[ks][3], bh2, bh3);
                mma16816(accS[2 * ntp + 1], qfh[ks][0], qfh[ks][1], qfh[ks][2], qfh[ks][3], bl2, bl3);
                mma16816(accS[2 * ntp + 1], qfl[ks][0], qfl[ks][1], qfl[ks][2], qfl[ks][3], bh2, bh3);
            }
        }

        // ---- causal mask ----
        if (n0 + AT_BN - 1 > m0) {
#pragma unroll
            for (int nt = 0; nt < 8; nt++) {
                int c0 = n0 + nt * 8 + 2 * tg;
                if (c0     > row0)     accS[nt][0] = -CUDART_INF_F;
                if (c0 + 1 > row0)     accS[nt][1] = -CUDART_INF_F;
                if (c0     > row0 + 8) accS[nt][2] = -CUDART_INF_F;
                if (c0 + 1 > row0 + 8) accS[nt][3] = -CUDART_INF_F;
            }
        }

        // ---- in-register online softmax ----
        float mx0 = accS[0][0], mx1 = accS[0][2];
#pragma unroll
        for (int nt = 0; nt < 8; nt++) {
            mx0 = fmaxf(mx0, fmaxf(accS[nt][0], accS[nt][1]));
            mx1 = fmaxf(mx1, fmaxf(accS[nt][2], accS[nt][3]));
        }
        mx0 = fmaxf(mx0, __shfl_xor_sync(0xffffffffu, mx0, 1));
        mx0 = fmaxf(mx0, __shfl_xor_sync(0xffffffffu, mx0, 2));
        mx1 = fmaxf(mx1, __shfl_xor_sync(0xffffffffu, mx1, 1));
        mx1 = fmaxf(mx1, __shfl_xor_sync(0xffffffffu, mx1, 2));

        float mn0 = fmaxf(m_[0], mx0);
        float mn1 = fmaxf(m_[1], mx1);
        float corr0 = __expf(m_[0] - mn0);
        float corr1 = __expf(m_[1] - mn1);
        float sum0 = 0.f, sum1 = 0.f;
#pragma unroll
        for (int nt = 0; nt < 8; nt++) {
            accS[nt][0] = __expf(accS[nt][0] - mn0);
            accS[nt][1] = __expf(accS[nt][1] - mn0);
            accS[nt][2] = __expf(accS[nt][2] - mn1);
            accS[nt][3] = __expf(accS[nt][3] - mn1);
            sum0 += accS[nt][0] + accS[nt][1];
            sum1 += accS[nt][2] + accS[nt][3];
        }
        sum0 += __shfl_xor_sync(0xffffffffu, sum0, 1);
        sum0 += __shfl_xor_sync(0xffffffffu, sum0, 2);
        sum1 += __shfl_xor_sync(0xffffffffu, sum1, 1);
        sum1 += __shfl_xor_sync(0xffffffffu, sum1, 2);
        l_[0] = l_[0] * corr0 + sum0;
        l_[1] = l_[1] * corr1 + sum1;
        m_[0] = mn0; m_[1] = mn1;

#pragma unroll
        for (int nt = 0; nt < 16; nt++) {
            accO[nt][0] *= corr0; accO[nt][1] *= corr0;
            accO[nt][2] *= corr1; accO[nt][3] *= corr1;
        }

        // ---- O += P @ V (bf16x3), warp tile 16x128, k=64 ----
#pragma unroll
        for (int kc = 0; kc < 4; kc++) {
            float p00 = accS[2 * kc][0],     p01 = accS[2 * kc][1];
            float p10 = accS[2 * kc][2],     p11 = accS[2 * kc][3];
            float p20 = accS[2 * kc + 1][0], p21 = accS[2 * kc + 1][1];
            float p30 = accS[2 * kc + 1][2], p31 = accS[2 * kc + 1][3];
            float h00 = __bfloat162float(__float2bfloat16(p00));
            float h01 = __bfloat162float(__float2bfloat16(p01));
            float h10 = __bfloat162float(__float2bfloat16(p10));
            float h11 = __bfloat162float(__float2bfloat16(p11));
            float h20 = __bfloat162float(__float2bfloat16(p20));
            float h21 = __bfloat162float(__float2bfloat16(p21));
            float h30 = __bfloat162float(__float2bfloat16(p30));
            float h31 = __bfloat162float(__float2bfloat16(p31));
            uint32_t ph0 = pack_bf16x2(h00, h01);
            uint32_t ph1 = pack_bf16x2(h10, h11);
            uint32_t ph2 = pack_bf16x2(h20, h21);
            uint32_t ph3 = pack_bf16x2(h30, h31);
            uint32_t pl0 = pack_bf16x2(p00 - h00, p01 - h01);
            uint32_t pl1 = pack_bf16x2(p10 - h10, p11 - h11);
            uint32_t pl2 = pack_bf16x2(p20 - h20, p21 - h21);
            uint32_t pl3 = pack_bf16x2(p30 - h30, p31 - h31);

#pragma unroll
            for (int ncg = 0; ncg < 8; ncg++) {
                uint32_t base_off = (uint32_t)(kc * 16 * 272 + ncg * 32) + vlane_off;
                uint32_t vh0, vh1, vh2, vh3, vl0, vl1, vl2, vl3;
                ldsm_x4_t(vh0, vh1, vh2, vh3, svh + base_off);
                ldsm_x4_t(vl0, vl1, vl2, vl3, svl + base_off);
                mma16816(accO[ncg * 2],     ph0, ph1, ph2, ph3, vh0, vh1);
                mma16816(accO[ncg * 2],     ph0, ph1, ph2, ph3, vl0, vl1);
                mma16816(accO[ncg * 2],     pl0, pl1, pl2, pl3, vh0, vh1);
                mma16816(accO[ncg * 2 + 1], ph0, ph1, ph2, ph3, vh2, vh3);
                mma16816(accO[ncg * 2 + 1], ph0, ph1, ph2, ph3, vl2, vl3);
                mma16816(accO[ncg * 2 + 1], pl0, pl1, pl2, pl3, vh2, vh3);
            }
        }
        __syncthreads();
    }

    // ---- normalize + split-write bf16 hi/lo ----
    float i0 = 1.f / l_[0];
    float i1 = 1.f / l_[1];
#pragma unroll
    for (int nt = 0; nt < 16; nt++) {
        int col = h * DH + nt * 8 + 2 * tg;
        float v0 = accO[nt][0] * i0, v1 = accO[nt][1] * i0;
        float v2 = accO[nt][2] * i1, v3 = accO[nt][3] * i1;
        size_t o0 = (size_t)row0 * HID + col;
        size_t o1 = (size_t)(row0 + 8) * HID + col;
        split2_store(v0, v1, oh + o0, ol + o0);
        split2_store(v2, v3, oh + o1, ol + o1);
    }
}

// ---------------------------------------------------------------------------
// Launch
// ---------------------------------------------------------------------------
extern "C" void kernel_launch(void* const* d_in, const int* in_sizes, int n_in,
                              void* d_out, int out_size)
{
    const int*   positions = (const int*)d_in[0];
    const float* hidden    = (const float*)d_in[1];
    const float* w_qkv     = (const float*)d_in[2];
    const float* w_o       = (const float*)d_in[3];
    const float* q_norm_w  = (const float*)d_in[4];
    const float* k_norm_w  = (const float*)d_in[5];
    float*       out       = (float*)d_out;

    __nv_bfloat16 *ah, *al, *bh, *bl, *qsh, *qsl, *ksh, *ksl, *vsh, *vsl;
    cudaGetSymbolAddress((void**)&ah, g_ah);
    cudaGetSymbolAddress((void**)&al, g_al);
    cudaGetSymbolAddress((void**)&bh, g_bh);
    cudaGetSymbolAddress((void**)&bl, g_bl);
    cudaGetSymbolAddress((void**)&qsh, g_qsh);
    cudaGetSymbolAddress((void**)&qsl, g_qsl);
    cudaGetSymbolAddress((void**)&ksh, g_ksh);
    cudaGetSymbolAddress((void**)&ksl, g_ksl);
    cudaGetSymbolAddress((void**)&vsh, g_vsh);
    cudaGetSymbolAddress((void**)&vsl, g_vsl);

    // 1. Split hidden; transpose+split w_qkv.
    {
        int n = TT * HID;
        split_kernel<<<n / 4 / 256, 256>>>(hidden, ah, al, n);
        dim3 tg(QKVW / 32, HID / 32);
        transpose_split_kernel<<<tg, dim3(32, 8)>>>(w_qkv, bh, bl, HID, QKVW);
    }

    // 2. QKV projection with FUSED norm/rope/split epilogue.
    {
        dim3 grid(QKVW / 128, TT / 128);
        gemm_mma_kernel_t<true><<<grid, 256>>>(
            TT, QKVW, HID, ah, al, bh, bl,
            nullptr, positions, q_norm_w, k_norm_w,
            qsh, qsl, ksh, ksl, vsh, vsl);
    }

    // 3. transpose+split w_o (bh/bl free after QKV GEMM)
    {
        dim3 tg(HID / 32, (NH * DH) / 32);
        transpose_split_kernel<<<tg, dim3(32, 8)>>>(w_o, bh, bl, NH * DH, HID);
    }

    // 4. Causal GQA flash attention; writes split bf16 hi/lo into ah/al.
    {
        static_assert(sizeof(AttnSmem) <= 227 * 1024, "smem");
        cudaFuncSetAttribute(attn_kernel,
                             cudaFuncAttributeMaxDynamicSharedMemorySize,
                             (int)sizeof(AttnSmem));
        dim3 grid(NH, TT / AT_BM);
        attn_kernel<<<grid, 256, sizeof(AttnSmem)>>>(
            qsh, qsl, ksh, ksl, vsh, vsl, ah, al);
    }

    // 5. Output projection (plain fp32 epilogue).
    {
        dim3 grid(HID / 128, TT / 128);
        gemm_mma_kernel_t<false><<<grid, 256>>>(
            TT, HID, NH * DH, ah, al, bh, bl,
            out, nullptr, nullptr, nullptr,
            nullptr, nullptr, nullptr, nullptr, nullptr, nullptr);
    }
}

// round 11
// speedup vs baseline: 2.9932x; 1.0480x over previous
#include <cuda_runtime.h>
#include <cuda_bf16.h>
#include <math.h>
#include <math_constants.h>
#include <stdint.h>

// Problem constants
#define TT   2048
#define HID  2048
#define NH   16
#define NKV  8
#define DH   128
#define QKVW ((NH + 2 * NKV) * DH)   // 4096
#define QW   (NH * DH)               // 2048
#define KVW  (NKV * DH)              // 1024
#define EPS  1e-6f

// Scratch (allocation-free rule: __device__ globals)
__device__ __nv_bfloat16 g_ah[(size_t)TT * HID];     // GEMM A hi / attn-out hi
__device__ __nv_bfloat16 g_al[(size_t)TT * HID];     // GEMM A lo / attn-out lo
__device__ __nv_bfloat16 g_bh[(size_t)QKVW * HID];   // B^T hi ([N,K])
__device__ __nv_bfloat16 g_bl[(size_t)QKVW * HID];   // B^T lo
__device__ __nv_bfloat16 g_qsh[(size_t)TT * QW],  g_qsl[(size_t)TT * QW];   // split Q (scaled)
__device__ __nv_bfloat16 g_ksh[(size_t)TT * KVW], g_ksl[(size_t)TT * KVW];  // split K
__device__ __nv_bfloat16 g_vsh[(size_t)TT * KVW], g_vsl[(size_t)TT * KVW];  // split V
__device__ float2 g_rope[(size_t)TT * 64];           // (cos, sin) per (t, d)

// ---------------------------------------------------------------------------
// PTX helpers (base sm_103 target — HMMA mma.sync + ldmatrix + cp.async)
// ---------------------------------------------------------------------------
__device__ __forceinline__ void mma16816(float d[4],
                                         uint32_t a0, uint32_t a1, uint32_t a2, uint32_t a3,
                                         uint32_t b0, uint32_t b1)
{
    asm volatile(
        "mma.sync.aligned.m16n8k16.row.col.f32.bf16.bf16.f32 "
        "{%0,%1,%2,%3}, {%4,%5,%6,%7}, {%8,%9}, {%0,%1,%2,%3};\n"
        : "+f"(d[0]), "+f"(d[1]), "+f"(d[2]), "+f"(d[3])
        : "r"(a0), "r"(a1), "r"(a2), "r"(a3), "r"(b0), "r"(b1));
}

__device__ __forceinline__ void ldsm_x4(uint32_t& r0, uint32_t& r1,
                                        uint32_t& r2, uint32_t& r3, uint32_t addr)
{
    asm volatile("ldmatrix.sync.aligned.m8n8.x4.shared.b16 {%0,%1,%2,%3}, [%4];"
                 : "=r"(r0), "=r"(r1), "=r"(r2), "=r"(r3) : "r"(addr));
}

__device__ __forceinline__ void ldsm_x4_t(uint32_t& r0, uint32_t& r1,
                                          uint32_t& r2, uint32_t& r3, uint32_t addr)
{
    asm volatile("ldmatrix.sync.aligned.m8n8.x4.trans.shared.b16 {%0,%1,%2,%3}, [%4];"
                 : "=r"(r0), "=r"(r1), "=r"(r2), "=r"(r3) : "r"(addr));
}

__device__ __forceinline__ uint32_t su32(const void* p) {
    return (uint32_t)__cvta_generic_to_shared(p);
}

__device__ __forceinline__ uint32_t pack_bf16x2(float a, float b) {
    __nv_bfloat162 t = __floats2bfloat162_rn(a, b);
    return *(uint32_t*)&t;
}

__device__ __forceinline__ void cp_async16(uint32_t dst, const void* src) {
    asm volatile("cp.async.cg.shared.global [%0], [%1], 16;" :: "r"(dst), "l"(src));
}
__device__ __forceinline__ void cp_commit() {
    asm volatile("cp.async.commit_group;" ::: "memory");
}
template <int N>
__device__ __forceinline__ void cp_wait() {
    asm volatile("cp.async.wait_group %0;" :: "n"(N) : "memory");
}

// hi/lo split of a float4, stored as 2x bf162 each
__device__ __forceinline__ void split4_store(float4 v, __nv_bfloat16* hp, __nv_bfloat16* lp) {
    __nv_bfloat16 h0 = __float2bfloat16(v.x), h1 = __float2bfloat16(v.y);
    __nv_bfloat16 h2 = __float2bfloat16(v.z), h3 = __float2bfloat16(v.w);
    *(uint32_t*)(hp)     = pack_bf16x2(__bfloat162float(h0), __bfloat162float(h1));
    *(uint32_t*)(hp + 2) = pack_bf16x2(__bfloat162float(h2), __bfloat162float(h3));
    *(uint32_t*)(lp)     = pack_bf16x2(v.x - __bfloat162float(h0), v.y - __bfloat162float(h1));
    *(uint32_t*)(lp + 2) = pack_bf16x2(v.z - __bfloat162float(h2), v.w - __bfloat162float(h3));
}

// hi/lo split of 2 floats -> two u32 stores
__device__ __forceinline__ void split2_store(float a, float b,
                                             __nv_bfloat16* hp, __nv_bfloat16* lp) {
    float ha = __bfloat162float(__float2bfloat16(a));
    float hb = __bfloat162float(__float2bfloat16(b));
    *(uint32_t*)hp = pack_bf16x2(ha, hb);
    *(uint32_t*)lp = pack_bf16x2(a - ha, b - hb);
}

// ---------------------------------------------------------------------------
// Split conversion (+ RoPE table build by the first TT*64 threads).
// ---------------------------------------------------------------------------
__global__ __launch_bounds__(256) void split_kernel(
    const float* __restrict__ x,
    __nv_bfloat16* __restrict__ hi, __nv_bfloat16* __restrict__ lo, int n,
    const int* __restrict__ positions, float2* __restrict__ rope)
{
    int j = blockIdx.x * blockDim.x + threadIdx.x;
    if (rope && j < TT * 64) {
        int t = j >> 6;
        int d = j & 63;
        float pos = (float)positions[t];
        float inv_freq = powf(10000.f, -(float)d * (1.f / 64.f));
        float sv, cv;
        sincosf(pos * inv_freq, &sv, &cv);
        rope[j] = make_float2(cv, sv);
    }
    int i = j * 4;
    if (i >= n) return;
    float4 v = *(const float4*)(x + i);
    split4_store(v, hi + i, lo + i);
}

// ---------------------------------------------------------------------------
// Transpose + split: W[K,N] fp32 -> Th/Tl [N,K] bf16. K,N % 32 == 0.
// ---------------------------------------------------------------------------
__global__ __launch_bounds__(256) void transpose_split_kernel(
    const float* __restrict__ W,
    __nv_bfloat16* __restrict__ Th, __nv_bfloat16* __restrict__ Tl,
    int K, int N)
{
    __shared__ float tile[32][33];
    const int bn = blockIdx.x * 32;
    const int bk = blockIdx.y * 32;
    const int tx = threadIdx.x;
    const int ty = threadIdx.y;
#pragma unroll
    for (int j = 0; j < 32; j += 8)
        tile[ty + j][tx] = W[(size_t)(bk + ty + j) * N + bn + tx];
    __syncthreads();
#pragma unroll
    for (int j = 0; j < 32; j += 8) {
        float v = tile[tx][ty + j];
        __nv_bfloat16 h = __float2bfloat16(v);
        __nv_bfloat16 l = __float2bfloat16(v - __bfloat162float(h));
        size_t o = (size_t)(bn + ty + j) * K + bk + tx;
        Th[o] = h;
        Tl[o] = l;
    }
}

// ---------------------------------------------------------------------------
// mma.sync bf16x3 GEMM: cp.async double-buffered, ldmatrix frags.
// Dynamic smem (80 KB) + launch_bounds(256,2) -> 2 CTAs/SM.
// FUSED=true: QKV projection with RMSNorm+RoPE(table)+split epilogue.
// ---------------------------------------------------------------------------
#define GST   10240   // bytes per stage per array (128 rows x 80B)
#define GARR  20480   // bytes per array (2 stages)
#define GEMM_SMEM 81920

template<bool FUSED>
__global__ __launch_bounds__(256, 2) void gemm_mma_kernel_t(
    int M, int N, int K,
    const __nv_bfloat16* __restrict__ Ah, const __nv_bfloat16* __restrict__ Al,
    const __nv_bfloat16* __restrict__ Bh, const __nv_bfloat16* __restrict__ Bl,
    float* __restrict__ C,
    const float2* __restrict__ rope,
    const float* __restrict__ qw, const float* __restrict__ kw,
    __nv_bfloat16* __restrict__ qsh, __nv_bfloat16* __restrict__ qsl,
    __nv_bfloat16* __restrict__ ksh, __nv_bfloat16* __restrict__ ksl,
    __nv_bfloat16* __restrict__ vsh, __nv_bfloat16* __restrict__ vsl)
{
    extern __shared__ __align__(16) char blob[];

    const int tid  = threadIdx.x;
    const int lane = tid & 31;
    const int wid  = tid >> 5;
    const int wm   = wid >> 2;
    const int wn   = wid & 3;
    const int gq   = lane >> 2;
    const int tg   = lane & 3;
    const int bm = blockIdx.y * 128;
    const int bn = blockIdx.x * 128;

    const uint32_t ub = su32(blob);
    const uint32_t a_off = (uint32_t)((lane & 15) * 80 + (lane & 16));
    const uint32_t b_off = (uint32_t)(((lane & 7) + ((lane >> 4) << 3)) * 80 + (((lane >> 3) & 1) << 4));

    float acc[4][4][4];
#pragma unroll
    for (int a = 0; a < 4; a++)
#pragma unroll
        for (int b = 0; b < 4; b++)
#pragma unroll
            for (int c = 0; c < 4; c++) acc[a][b][c] = 0.f;

    const int nch = K / 32;

    auto load_chunk = [&](int c, int st) {
        const int k0 = c * 32;
        const uint32_t sb = ub + (uint32_t)st * GST;
#pragma unroll
        for (int i = 0; i < 2; i++) {
            int u = tid + i * 256;
            int row = u >> 2;
            int q   = u & 3;
            uint32_t so = (uint32_t)(row * 80 + q * 16);
            size_t goA = (size_t)(bm + row) * K + k0 + q * 8;
            size_t goB = (size_t)(bn + row) * K + k0 + q * 8;
            cp_async16(sb + so,             Ah + goA);
            cp_async16(sb + GARR + so,      Al + goA);
            cp_async16(sb + 2 * GARR + so,  Bh + goB);
            cp_async16(sb + 3 * GARR + so,  Bl + goB);
        }
    };

    load_chunk(0, 0);
    cp_commit();

    for (int c = 0; c < nch; c++) {
        const int st = c & 1;
        if (c + 1 < nch) {
            load_chunk(c + 1, st ^ 1);
            cp_commit();
            cp_wait<1>();
        } else {
            cp_wait<0>();
        }
        __syncthreads();

        const uint32_t sb = ub + (uint32_t)st * GST;
#pragma unroll
        for (int ks = 0; ks < 2; ks++) {
            const uint32_t kb = (uint32_t)(ks * 32);
            uint32_t ah[4][4], al[4][4], bh[4][2], bl[4][2];
#pragma unroll
            for (int mt = 0; mt < 4; mt++) {
                uint32_t base = (uint32_t)((wm * 64 + mt * 16) * 80) + kb + a_off;
                ldsm_x4(ah[mt][0], ah[mt][1], ah[mt][2], ah[mt][3], sb + base);
                ldsm_x4(al[mt][0], al[mt][1], al[mt][2], al[mt][3], sb + GARR + base);
            }
#pragma unroll
            for (int ntp = 0; ntp < 2; ntp++) {
                uint32_t base = (uint32_t)((wn * 32 + ntp * 16) * 80) + kb + b_off;
                ldsm_x4(bh[2 * ntp][0], bh[2 * ntp][1], bh[2 * ntp + 1][0], bh[2 * ntp + 1][1],
                        sb + 2 * GARR + base);
                ldsm_x4(bl[2 * ntp][0], bl[2 * ntp][1], bl[2 * ntp + 1][0], bl[2 * ntp + 1][1],
                        sb + 3 * GARR + base);
            }
#pragma unroll
            for (int mt = 0; mt < 4; mt++)
#pragma unroll
                for (int nt = 0; nt < 4; nt++) {
                    mma16816(acc[mt][nt], ah[mt][0], ah[mt][1], ah[mt][2], ah[mt][3],
                             bh[nt][0], bh[nt][1]);
                    mma16816(acc[mt][nt], ah[mt][0], ah[mt][1], ah[mt][2], ah[mt][3],
                             bl[nt][0], bl[nt][1]);
                    mma16816(acc[mt][nt], al[mt][0], al[mt][1], al[mt][2], al[mt][3],
                             bh[nt][0], bh[nt][1]);
                }
        }
        __syncthreads();
    }

    if constexpr (!FUSED) {
#pragma unroll
        for (int mt = 0; mt < 4; mt++) {
            int row = bm + wm * 64 + mt * 16 + gq;
#pragma unroll
            for (int nt = 0; nt < 4; nt++) {
                int col = bn + wn * 32 + nt * 8 + 2 * tg;
                *(float2*)(C + (size_t)row * N + col) =
                    make_float2(acc[mt][nt][0], acc[mt][nt][1]);
                *(float2*)(C + (size_t)(row + 8) * N + col) =
                    make_float2(acc[mt][nt][2], acc[mt][nt][3]);
            }
        }
        return;
    } else {
        const int slot = bn >> 7;   // head slot 0..31 (0-15 q, 16-23 k, 24-31 v)

        if (slot >= 24) {
            const int vh = slot - 24;
#pragma unroll
            for (int mt = 0; mt < 4; mt++) {
#pragma unroll
                for (int hhalf = 0; hhalf < 2; hhalf++) {
                    int r = wm * 64 + mt * 16 + gq + 8 * hhalf;
                    int t = bm + r;
#pragma unroll
                    for (int nt = 0; nt < 4; nt++) {
                        int cn = wn * 32 + nt * 8 + 2 * tg;
                        size_t o = (size_t)t * KVW + vh * DH + cn;
                        split2_store(acc[mt][nt][2 * hhalf], acc[mt][nt][2 * hhalf + 1],
                                     vsh + o, vsl + o);
                    }
                }
            }
            return;
        }

        // Q/K: RMSNorm + RoPE(table) + split
        float* xs   = (float*)blob;              // [128][132] fp32 (67584 B)
        float* sums = (float*)(blob + 67584);    // [128][4]

#pragma unroll
        for (int mt = 0; mt < 4; mt++) {
#pragma unroll
            for (int hhalf = 0; hhalf < 2; hhalf++) {
                float p = 0.f;
#pragma unroll
                for (int nt = 0; nt < 4; nt++) {
                    float v0 = acc[mt][nt][2 * hhalf];
                    float v1 = acc[mt][nt][2 * hhalf + 1];
                    p += v0 * v0 + v1 * v1;
                }
                p += __shfl_xor_sync(0xffffffffu, p, 1);
                p += __shfl_xor_sync(0xffffffffu, p, 2);
                if (tg == 0) {
                    int r = wm * 64 + mt * 16 + gq + 8 * hhalf;
                    sums[r * 4 + wn] = p;
                }
            }
        }
        __syncthreads();

        const float* wvec = (slot < NH) ? qw : kw;
        float wcol[8];
#pragma unroll
        for (int nt = 0; nt < 4; nt++) {
            int cn = wn * 32 + nt * 8 + 2 * tg;
            wcol[2 * nt]     = wvec[cn];
            wcol[2 * nt + 1] = wvec[cn + 1];
        }
#pragma unroll
        for (int mt = 0; mt < 4; mt++) {
#pragma unroll
            for (int hhalf = 0; hhalf < 2; hhalf++) {
                int r = wm * 64 + mt * 16 + gq + 8 * hhalf;
                float ssum = sums[r * 4 + 0] + sums[r * 4 + 1] + sums[r * 4 + 2] + sums[r * 4 + 3];
                float rinv = rsqrtf(ssum * (1.f / DH) + EPS);
#pragma unroll
                for (int nt = 0; nt < 4; nt++) {
                    int cn = wn * 32 + nt * 8 + 2 * tg;
                    xs[r * 132 + cn]     = acc[mt][nt][2 * hhalf] * rinv * wcol[2 * nt];
                    xs[r * 132 + cn + 1] = acc[mt][nt][2 * hhalf + 1] * rinv * wcol[2 * nt + 1];
                }
            }
        }
        __syncthreads();

        const bool isq = (slot < NH);
        const float qscale = 0.08838834764831845f;   // 1/sqrt(128)
#pragma unroll
        for (int mt = 0; mt < 4; mt++) {
#pragma unroll
            for (int hhalf = 0; hhalf < 2; hhalf++) {
                int r = wm * 64 + mt * 16 + gq + 8 * hhalf;
                int t = bm + r;
#pragma unroll
                for (int nt = 0; nt < 4; nt++) {
                    int cn = wn * 32 + nt * 8 + 2 * tg;
                    int d  = cn & 63;
                    float x0 = xs[r * 132 + cn];
                    float x1 = xs[r * 132 + cn + 1];
                    float p0 = xs[r * 132 + (cn ^ 64)];
                    float p1 = xs[r * 132 + (cn ^ 64) + 1];
                    float2 cs0 = rope[t * 64 + d];
                    float2 cs1 = rope[t * 64 + d + 1];
                    float o0, o1;
                    if (cn < 64) {
                        o0 = x0 * cs0.x - p0 * cs0.y;
                        o1 = x1 * cs1.x - p1 * cs1.y;
                    } else {
                        o0 = x0 * cs0.x + p0 * cs0.y;
                        o1 = x1 * cs1.x + p1 * cs1.y;
                    }
                    if (isq) { o0 *= qscale; o1 *= qscale; }
                    if (isq) {
                        size_t o = (size_t)t * QW + slot * DH + cn;
                        split2_store(o0, o1, qsh + o, qsl + o);
                    } else {
                        size_t o = (size_t)t * KVW + (slot - NH) * DH + cn;
                        split2_store(o0, o1, ksh + o, ksl + o);
                    }
                }
            }
        }
    }
}

// ---------------------------------------------------------------------------
// FA2-style causal GQA attention, bf16x3 mma, in-register softmax,
// cp.async double-buffered K/V; Q fragments resident in registers.
// ---------------------------------------------------------------------------
#define AT_BM 128
#define AT_BN 64
#define QP 136      // smem pitch (bf16): 272B rows

struct AttnSmem {
    __nv_bfloat16 Qh[AT_BM * QP], Ql[AT_BM * QP];
    __nv_bfloat16 Kh[2][AT_BN * QP], Kl[2][AT_BN * QP];
    __nv_bfloat16 Vh[2][AT_BN * QP], Vl[2][AT_BN * QP];
};

__global__ __launch_bounds__(256, 1) void attn_kernel(
    const __nv_bfloat16* __restrict__ qsh, const __nv_bfloat16* __restrict__ qsl,
    const __nv_bfloat16* __restrict__ ksh, const __nv_bfloat16* __restrict__ ksl,
    const __nv_bfloat16* __restrict__ vsh, const __nv_bfloat16* __restrict__ vsl,
    __nv_bfloat16* __restrict__ oh, __nv_bfloat16* __restrict__ ol)
{
    extern __shared__ char smem_raw[];
    AttnSmem& s = *(AttnSmem*)smem_raw;

    const int h   = blockIdx.x;
    const int m0  = (gridDim.y - 1 - blockIdx.y) * AT_BM;  // heavy blocks first
    const int kvh = h >> 1;
    const int tid = threadIdx.x;
    const int lane = tid & 31;
    const int w    = tid >> 5;
    const int gq   = lane >> 2;
    const int tg   = lane & 3;

    const uint32_t uQh = su32(s.Qh), uQl = su32(s.Ql);
    const uint32_t uKh[2] = { su32(s.Kh[0]), su32(s.Kh[1]) };
    const uint32_t uKl[2] = { su32(s.Kl[0]), su32(s.Kl[1]) };
    const uint32_t uVh[2] = { su32(s.Vh[0]), su32(s.Vh[1]) };
    const uint32_t uVl[2] = { su32(s.Vl[0]), su32(s.Vl[1]) };

    const uint32_t a_off = (uint32_t)((lane & 15) * 272 + (lane & 16));
    const uint32_t b_off = (uint32_t)(((lane & 7) + ((lane >> 4) << 3)) * 272 + (((lane >> 3) & 1) << 4));
    const uint32_t vlane_off = (uint32_t)((lane & 15) * 272 + ((lane >> 4) << 4));

    auto prefetch = [&](int n0, int b) {
#pragma unroll
        for (int i = 0; i < 4; i++) {
            int u = tid + i * 256;
            int row = u >> 4;
            int c   = u & 15;
            uint32_t so = (uint32_t)(row * 272 + c * 16);
            size_t go = (size_t)(n0 + row) * KVW + kvh * DH + c * 8;
            cp_async16(uKh[b] + so, ksh + go);
            cp_async16(uKl[b] + so, ksl + go);
            cp_async16(uVh[b] + so, vsh + go);
            cp_async16(uVl[b] + so, vsl + go);
        }
    };

    for (int u = tid; u < AT_BM * 16; u += 256) {
        int row = u >> 4;
        int c   = u & 15;
        size_t go = (size_t)(m0 + row) * QW + h * DH + c * 8;
        *(uint4*)((char*)s.Qh + row * 272 + c * 16) = *(const uint4*)(qsh + go);
        *(uint4*)((char*)s.Ql + row * 272 + c * 16) = *(const uint4*)(qsl + go);
    }

    prefetch(0, 0);
    cp_commit();
    __syncthreads();

    uint32_t qfh[8][4], qfl[8][4];
#pragma unroll
    for (int ks = 0; ks < 8; ks++) {
        uint32_t qbase = (uint32_t)(w * 16 * 272 + ks * 32) + a_off;
        ldsm_x4(qfh[ks][0], qfh[ks][1], qfh[ks][2], qfh[ks][3], uQh + qbase);
        ldsm_x4(qfl[ks][0], qfl[ks][1], qfl[ks][2], qfl[ks][3], uQl + qbase);
    }

    float m_[2] = { -CUDART_INF_F, -CUDART_INF_F };
    float l_[2] = { 0.f, 0.f };

    float accO[16][4];
#pragma unroll
    for (int a = 0; a < 16; a++)
#pragma unroll
        for (int c = 0; c < 4; c++) accO[a][c] = 0.f;

    const int row0 = m0 + w * 16 + gq;
    const int n_tiles = (m0 + AT_BM) / AT_BN;

    for (int tile = 0; tile < n_tiles; tile++) {
        const int n0 = tile * AT_BN;
        const int b  = tile & 1;

        if (tile + 1 < n_tiles) {
            prefetch(n0 + AT_BN, b ^ 1);
            cp_commit();
            cp_wait<1>();
        } else {
            cp_wait<0>();
        }
        __syncthreads();

        const uint32_t kh = uKh[b], kl = uKl[b];
        const uint32_t svh = uVh[b], svl = uVl[b];

        float accS[8][4];
#pragma unroll
        for (int bb = 0; bb < 8; bb++)
#pragma unroll
            for (int c = 0; c < 4; c++) accS[bb][c] = 0.f;

#pragma unroll
        for (int ks = 0; ks < 8; ks++) {
            const uint32_t kb = (uint32_t)(ks * 32);
#pragma unroll
            for (int ntp = 0; ntp < 4; ntp++) {
                uint32_t base = (uint32_t)(ntp * 16 * 272) + kb + b_off;
                uint32_t bh0, bh1, bh2, bh3, bl0, bl1, bl2, bl3;
                ldsm_x4(bh0, bh1, bh2, bh3, kh + base);
                ldsm_x4(bl0, bl1, bl2, bl3, kl + base);
                mma16816(accS[2 * ntp],     qfh[ks][0], qfh[ks][1], qfh[ks][2], qfh[ks][3], bh0, bh1);
                mma16816(accS[2 * ntp],     qfh[ks][0], qfh[ks][1], qfh[ks][2], qfh[ks][3], bl0, bl1);
                mma16816(accS[2 * ntp],     qfl[ks][0], qfl[ks][1], qfl[ks][2], qfl[ks][3], bh0, bh1);
                mma16816(accS[2 * ntp + 1], qfh[ks][0], qfh[ks][1], qfh[ks][2], qfh[ks][3], bh2, bh3);
                mma16816(accS[2 * ntp + 1], qfh[ks][0], qfh[ks][1], qfh[ks][2], qfh[ks][3], bl2, bl3);
                mma16816(accS[2 * ntp + 1], qfl[ks][0], qfl[ks][1], qfl[ks][2], qfl[ks][3], bh2, bh3);
            }
        }

        if (n0 + AT_BN - 1 > m0) {
#pragma unroll
            for (int nt = 0; nt < 8; nt++) {
                int c0 = n0 + nt * 8 + 2 * tg;
                if (c0     > row0)     accS[nt][0] = -CUDART_INF_F;
                if (c0 + 1 > row0)     accS[nt][1] = -CUDART_INF_F;
                if (c0     > row0 + 8) accS[nt][2] = -CUDART_INF_F;
                if (c0 + 1 > row0 + 8) accS[nt][3] = -CUDART_INF_F;
            }
        }

        float mx0 = accS[0][0], mx1 = accS[0][2];
#pragma unroll
        for (int nt = 0; nt < 8; nt++) {
            mx0 = fmaxf(mx0, fmaxf(accS[nt][0], accS[nt][1]));
            mx1 = fmaxf(mx1, fmaxf(accS[nt][2], accS[nt][3]));
        }
        mx0 = fmaxf(mx0, __shfl_xor_sync(0xffffffffu, mx0, 1));
        mx0 = fmaxf(mx0, __shfl_xor_sync(0xffffffffu, mx0, 2));
        mx1 = fmaxf(mx1, __shfl_xor_sync(0xffffffffu, mx1, 1));
        mx1 = fmaxf(mx1, __shfl_xor_sync(0xffffffffu, mx1, 2));

        float mn0 = fmaxf(m_[0], mx0);
        float mn1 = fmaxf(m_[1], mx1);
        float corr0 = __expf(m_[0] - mn0);
        float corr1 = __expf(m_[1] - mn1);
        float sum0 = 0.f, sum1 = 0.f;
#pragma unroll
        for (int nt = 0; nt < 8; nt++) {
            accS[nt][0] = __expf(accS[nt][0] - mn0);
            accS[nt][1] = __expf(accS[nt][1] - mn0);
            accS[nt][2] = __expf(accS[nt][2] - mn1);
            accS[nt][3] = __expf(accS[nt][3] - mn1);
            sum0 += accS[nt][0] + accS[nt][1];
            sum1 += accS[nt][2] + accS[nt][3];
        }
        sum0 += __shfl_xor_sync(0xffffffffu, sum0, 1);
        sum0 += __shfl_xor_sync(0xffffffffu, sum0, 2);
        sum1 += __shfl_xor_sync(0xffffffffu, sum1, 1);
        sum1 += __shfl_xor_sync(0xffffffffu, sum1, 2);
        l_[0] = l_[0] * corr0 + sum0;
        l_[1] = l_[1] * corr1 + sum1;
        m_[0] = mn0; m_[1] = mn1;

#pragma unroll
        for (int nt = 0; nt < 16; nt++) {
            accO[nt][0] *= corr0; accO[nt][1] *= corr0;
            accO[nt][2] *= corr1; accO[nt][3] *= corr1;
        }

#pragma unroll
        for (int kc = 0; kc < 4; kc++) {
            float p00 = accS[2 * kc][0],     p01 = accS[2 * kc][1];
            float p10 = accS[2 * kc][2],     p11 = accS[2 * kc][3];
            float p20 = accS[2 * kc + 1][0], p21 = accS[2 * kc + 1][1];
            float p30 = accS[2 * kc + 1][2], p31 = accS[2 * kc + 1][3];
            float h00 = __bfloat162float(__float2bfloat16(p00));
            float h01 = __bfloat162float(__float2bfloat16(p01));
            float h10 = __bfloat162float(__float2bfloat16(p10));
            float h11 = __bfloat162float(__float2bfloat16(p11));
            float h20 = __bfloat162float(__float2bfloat16(p20));
            float h21 = __bfloat162float(__float2bfloat16(p21));
            float h30 = __bfloat162float(__float2bfloat16(p30));
            float h31 = __bfloat162float(__float2bfloat16(p31));
            uint32_t ph0 = pack_bf16x2(h00, h01);
            uint32_t ph1 = pack_bf16x2(h10, h11);
            uint32_t ph2 = pack_bf16x2(h20, h21);
            uint32_t ph3 = pack_bf16x2(h30, h31);
            uint32_t pl0 = pack_bf16x2(p00 - h00, p01 - h01);
            uint32_t pl1 = pack_bf16x2(p10 - h10, p11 - h11);
            uint32_t pl2 = pack_bf16x2(p20 - h20, p21 - h21);
            uint32_t pl3 = pack_bf16x2(p30 - h30, p31 - h31);

#pragma unroll
            for (int ncg = 0; ncg < 8; ncg++) {
                uint32_t base_off = (uint32_t)(kc * 16 * 272 + ncg * 32) + vlane_off;
                uint32_t vh0, vh1, vh2, vh3, vl0, vl1, vl2, vl3;
                ldsm_x4_t(vh0, vh1, vh2, vh3, svh + base_off);
                ldsm_x4_t(vl0, vl1, vl2, vl3, svl + base_off);
                mma16816(accO[ncg * 2],     ph0, ph1, ph2, ph3, vh0, vh1);
                mma16816(accO[ncg * 2],     ph0, ph1, ph2, ph3, vl0, vl1);
                mma16816(accO[ncg * 2],     pl0, pl1, pl2, pl3, vh0, vh1);
                mma16816(accO[ncg * 2 + 1], ph0, ph1, ph2, ph3, vh2, vh3);
                mma16816(accO[ncg * 2 + 1], ph0, ph1, ph2, ph3, vl2, vl3);
                mma16816(accO[ncg * 2 + 1], pl0, pl1, pl2, pl3, vh2, vh3);
            }
        }
        __syncthreads();
    }

    float i0 = 1.f / l_[0];
    float i1 = 1.f / l_[1];
#pragma unroll
    for (int nt = 0; nt < 16; nt++) {
        int col = h * DH + nt * 8 + 2 * tg;
        float v0 = accO[nt][0] * i0, v1 = accO[nt][1] * i0;
        float v2 = accO[nt][2] * i1, v3 = accO[nt][3] * i1;
        size_t o0 = (size_t)row0 * HID + col;
        size_t o1 = (size_t)(row0 + 8) * HID + col;
        split2_store(v0, v1, oh + o0, ol + o0);
        split2_store(v2, v3, oh + o1, ol + o1);
    }
}

// ---------------------------------------------------------------------------
// Launch
// ---------------------------------------------------------------------------
extern "C" void kernel_launch(void* const* d_in, const int* in_sizes, int n_in,
                              void* d_out, int out_size)
{
    const int*   positions = (const int*)d_in[0];
    const float* hidden    = (const float*)d_in[1];
    const float* w_qkv     = (const float*)d_in[2];
    const float* w_o       = (const float*)d_in[3];
    const float* q_norm_w  = (const float*)d_in[4];
    const float* k_norm_w  = (const float*)d_in[5];
    float*       out       = (float*)d_out;

    __nv_bfloat16 *ah, *al, *bh, *bl, *qsh, *qsl, *ksh, *ksl, *vsh, *vsl;
    float2* rope;
    cudaGetSymbolAddress((void**)&ah, g_ah);
    cudaGetSymbolAddress((void**)&al, g_al);
    cudaGetSymbolAddress((void**)&bh, g_bh);
    cudaGetSymbolAddress((void**)&bl, g_bl);
    cudaGetSymbolAddress((void**)&qsh, g_qsh);
    cudaGetSymbolAddress((void**)&qsl, g_qsl);
    cudaGetSymbolAddress((void**)&ksh, g_ksh);
    cudaGetSymbolAddress((void**)&ksl, g_ksl);
    cudaGetSymbolAddress((void**)&vsh, g_vsh);
    cudaGetSymbolAddress((void**)&vsl, g_vsl);
    cudaGetSymbolAddress((void**)&rope, g_rope);

    cudaFuncSetAttribute(gemm_mma_kernel_t<true>,
                         cudaFuncAttributeMaxDynamicSharedMemorySize, GEMM_SMEM);
    cudaFuncSetAttribute(gemm_mma_kernel_t<false>,
                         cudaFuncAttributeMaxDynamicSharedMemorySize, GEMM_SMEM);

    // 1. Split hidden (+ build RoPE table); transpose+split w_qkv.
    {
        int n = TT * HID;
        split_kernel<<<n / 4 / 256, 256>>>(hidden, ah, al, n, positions, rope);
        dim3 tg(QKVW / 32, HID / 32);
        transpose_split_kernel<<<tg, dim3(32, 8)>>>(w_qkv, bh, bl, HID, QKVW);
    }

    // 2. QKV projection with FUSED norm/rope/split epilogue (2 CTAs/SM).
    {
        dim3 grid(QKVW / 128, TT / 128);
        gemm_mma_kernel_t<true><<<grid, 256, GEMM_SMEM>>>(
            TT, QKVW, HID, ah, al, bh, bl,
            nullptr, rope, q_norm_w, k_norm_w,
            qsh, qsl, ksh, ksl, vsh, vsl);
    }

    // 3. Causal GQA flash attention (moved up for ncu visibility);
    //    writes split bf16 hi/lo into ah/al.
    {
        static_assert(sizeof(AttnSmem) <= 227 * 1024, "smem");
        cudaFuncSetAttribute(attn_kernel,
                             cudaFuncAttributeMaxDynamicSharedMemorySize,
                             (int)sizeof(AttnSmem));
        dim3 grid(NH, TT / AT_BM);
        attn_kernel<<<grid, 256, sizeof(AttnSmem)>>>(
            qsh, qsl, ksh, ksl, vsh, vsl, ah, al);
    }

    // 4. transpose+split w_o (only needed before O-proj; bh/bl free now).
    {
        dim3 tg(HID / 32, (NH * DH) / 32);
        transpose_split_kernel<<<tg, dim3(32, 8)>>>(w_o, bh, bl, NH * DH, HID);
    }

    // 5. Output projection (plain fp32 epilogue, 2 CTAs/SM).
    {
        dim3 grid(HID / 128, TT / 128);
        gemm_mma_kernel_t<false><<<grid, 256, GEMM_SMEM>>>(
            TT, HID, NH * DH, ah, al, bh, bl,
            out, nullptr, nullptr, nullptr,
            nullptr, nullptr, nullptr, nullptr, nullptr, nullptr);
    }
}